// round 9
// baseline (speedup 1.0000x reference)
#include <cuda_runtime.h>
#include <cuda_bf16.h>
#include <cstdint>

#define EPS_BN 1e-5f
#define EPS_RENORM 1e-9f

#define BATCH 8
#define CH    1024
#define NPTS  2048
#define CQK   128

typedef __nv_bfloat16 bf16;

// ---------------- scratch (no allocations allowed) ----------------
__device__ float g_x1[BATCH * CH * NPTS];
__device__ float g_S [(size_t)BATCH * NPTS * NPTS];
__device__ float g_rd[BATCH * NPTS];
__device__ bf16 g_xh [BATCH * CH * NPTS], g_xl [BATCH * CH * NPTS];
__device__ bf16 g_x1h[BATCH * CH * NPTS], g_x1l[BATCH * CH * NPTS];
__device__ bf16 g_vh [BATCH * CH * NPTS], g_vl [BATCH * CH * NPTS];
__device__ bf16 g_th [BATCH * CH * NPTS], g_tl [BATCH * CH * NPTS];
__device__ bf16 g_qh [BATCH * NPTS * CQK], g_ql[BATCH * NPTS * CQK];
__device__ bf16 g_kh [BATCH * CQK * NPTS], g_kl[BATCH * CQK * NPTS];
__device__ bf16 g_Sh [(size_t)BATCH * NPTS * NPTS], g_Sl[(size_t)BATCH * NPTS * NPTS];
__device__ bf16 g_W1h[CH * CH],  g_W1l[CH * CH];
__device__ bf16 g_W2h[CH * CH],  g_W2l[CH * CH];
__device__ bf16 g_W5h[CH * CH],  g_W5l[CH * CH];
__device__ bf16 g_W3h[CQK * CH], g_W3l[CQK * CH];
__device__ bf16 g_W4h[CQK * CH], g_W4l[CQK * CH];

// ---------------- PTX helpers ----------------
__device__ __forceinline__ uint32_t s2u(const void* p) {
    uint32_t a;
    asm("{ .reg .u64 t; cvta.to.shared.u64 t, %1; cvt.u32.u64 %0, t; }"
        : "=r"(a) : "l"(p));
    return a;
}
__device__ __forceinline__ void cp16(uint32_t saddr, const void* g) {
    asm volatile("cp.async.cg.shared.global [%0], [%1], 16;"
                 :: "r"(saddr), "l"(g) : "memory");
}
#define CP_COMMIT() asm volatile("cp.async.commit_group;" ::: "memory")
#define CP_WAIT(n)  asm volatile("cp.async.wait_group %0;" :: "n"(n) : "memory")

__device__ __forceinline__ void ldsm4(uint32_t* r, uint32_t a) {
    asm volatile("ldmatrix.sync.aligned.m8n8.x4.shared.b16 {%0,%1,%2,%3}, [%4];"
                 : "=r"(r[0]), "=r"(r[1]), "=r"(r[2]), "=r"(r[3]) : "r"(a));
}
__device__ __forceinline__ void ldsm4t(uint32_t* r, uint32_t a) {
    asm volatile("ldmatrix.sync.aligned.m8n8.x4.trans.shared.b16 {%0,%1,%2,%3}, [%4];"
                 : "=r"(r[0]), "=r"(r[1]), "=r"(r[2]), "=r"(r[3]) : "r"(a));
}
__device__ __forceinline__ void mma16816(float* d, const uint32_t* a, const uint32_t* b) {
    asm volatile("mma.sync.aligned.m16n8k16.row.col.f32.bf16.bf16.f32 "
                 "{%0,%1,%2,%3}, {%4,%5,%6,%7}, {%8,%9}, {%0,%1,%2,%3};"
                 : "+f"(d[0]), "+f"(d[1]), "+f"(d[2]), "+f"(d[3])
                 : "r"(a[0]), "r"(a[1]), "r"(a[2]), "r"(a[3]), "r"(b[0]), "r"(b[1]));
}

// ---------------- split-bf16 MMA GEMM ----------------
// C[b] (BMxBN tile of M x N) = (Ah+Al)[b] @ (Bh+Bl)[b] ; 3-term split.
// A row-major [M][K], B row-major [K][N], N == NPTS.
// 8 warps, warp tile 64x64: (BM/64)x(BN/64) warp grid. BK=32, 4-stage cp.async.
#define NSTG   4

enum { EP_X1 = 0, EP_BNR = 1, EP_BNR_T = 2, EP_S = 3, EP_SUBDIV = 4, EP_FINAL = 5 };

template<int EPI, bool ABATCH, int BM, int BN>
__global__ void __launch_bounds__(256)
mma_gemm(const bf16* __restrict__ Ahp, const bf16* __restrict__ Alp, size_t sA,
         const bf16* __restrict__ Bhp, const bf16* __restrict__ Blp, size_t sB,
         int M, int K,
         float* __restrict__ C32, bf16* __restrict__ Ch, bf16* __restrict__ Cl,
         const float* __restrict__ gg, const float* __restrict__ bb,
         const float* __restrict__ mm, const float* __restrict__ vv,
         const float* __restrict__ add, const float* __restrict__ rdiv)
{
    constexpr int WM   = BM / 64;               // warps along M
    constexpr int ABYT = BM * 64;               // A term bytes (BM rows x 64B)
    constexpr int BOFF = 2 * ABYT;              // Bh offset
    constexpr int BLO  = BOFF + 64 * BN;        // Bl offset
    constexpr int STG  = 2 * ABYT + 128 * BN;   // stage bytes (= 49152)
    constexpr int CPB  = BN / 8;                // B chunks per k-row

    extern __shared__ __align__(256) char smraw[];
    const uint32_t smb = s2u(smraw);
    const int tid  = threadIdx.x;
    const int lane = tid & 31;
    const int wid  = tid >> 5;
    const int m_w  = (wid % WM) * 64;
    const int n_w  = (wid / WM) * 64;
    const int bz   = blockIdx.z;
    const int rowStart = blockIdx.y * BM;
    const int colStart = blockIdx.x * BN;
    const int N = NPTS;

    const bf16* Ah_ = Ahp + (ABATCH ? (size_t)bz * sA : 0);
    const bf16* Al_ = Alp + (ABATCH ? (size_t)bz * sA : 0);
    const bf16* Bh_ = Bhp + (size_t)bz * sB;
    const bf16* Bl_ = Blp + (size_t)bz * sB;

    float acc[4][8][4];
#pragma unroll
    for (int i = 0; i < 4; i++)
#pragma unroll
        for (int j = 0; j < 8; j++)
#pragma unroll
            for (int r = 0; r < 4; r++) acc[i][j][r] = 0.f;

    auto loadStage = [&](int t) {
        const int s = t & (NSTG - 1);
        const uint32_t base = smb + (uint32_t)s * STG;
        const int k0 = t * 32;
#pragma unroll
        for (int i = 0; i < BM / 64; i++) {      // A: BM rows x 4 chunks
            int idx = tid + i * 256;
            int row = idx >> 2, c = idx & 3;
            uint32_t off = (uint32_t)(row * 64 + ((c ^ ((row >> 1) & 3)) << 4));
            size_t go = (size_t)(rowStart + row) * K + k0 + c * 8;
            cp16(base + off,        Ah_ + go);
            cp16(base + ABYT + off, Al_ + go);
        }
#pragma unroll
        for (int i = 0; i < BN / 64; i++) {      // B: 32 rows x CPB chunks
            int idx = tid + i * 256;
            int k = idx / CPB, cn = idx % CPB;
            uint32_t off = (uint32_t)(k * (BN * 2) + ((cn ^ (k & 7)) << 4));
            size_t go = (size_t)(k0 + k) * N + colStart + cn * 8;
            cp16(base + BOFF + off, Bh_ + go);
            cp16(base + BLO  + off, Bl_ + go);
        }
        CP_COMMIT();
    };

    const int T = K / 32;
    const int P = (T < 3) ? T : 3;
    for (int t = 0; t < P; t++) loadStage(t);

    for (int t = 0; t < T; t++) {
        const int rem = T - t;
        if (rem >= 3) { CP_WAIT(2); } else if (rem == 2) { CP_WAIT(1); } else { CP_WAIT(0); }
        __syncthreads();
        if (t + 3 < T) loadStage(t + 3);

        const uint32_t Ab = smb + (uint32_t)(t & (NSTG - 1)) * STG;
#pragma unroll
        for (int ks = 0; ks < 2; ks++) {
            uint32_t ah[4][4], al[4][4];
#pragma unroll
            for (int i = 0; i < 4; i++) {
                int row = m_w + i * 16 + (lane & 15);
                int c = ks * 2 + (lane >> 4);
                uint32_t off = (uint32_t)(row * 64 + ((c ^ ((row >> 1) & 3)) << 4));
                ldsm4(ah[i], Ab + off);
                ldsm4(al[i], Ab + ABYT + off);
            }
#pragma unroll
            for (int p = 0; p < 4; p++) {
                int g = lane >> 3, j8 = lane & 7;
                int k = ks * 16 + (g & 1) * 8 + j8;
                int cn = (n_w >> 3) + p * 2 + (g >> 1);
                uint32_t off = (uint32_t)(k * (BN * 2) + ((cn ^ (k & 7)) << 4));
                uint32_t bh[4], bl[4];
                ldsm4t(bh, Ab + BOFF + off);
                ldsm4t(bl, Ab + BLO  + off);
#pragma unroll
                for (int i = 0; i < 4; i++) {
                    mma16816(acc[i][2 * p],     ah[i], bh);
                    mma16816(acc[i][2 * p],     ah[i], bl);
                    mma16816(acc[i][2 * p],     al[i], bh);
                    mma16816(acc[i][2 * p + 1], ah[i], bh + 2);
                    mma16816(acc[i][2 * p + 1], ah[i], bl + 2);
                    mma16816(acc[i][2 * p + 1], al[i], bh + 2);
                }
            }
        }
    }

    // ---------------- epilogue ----------------
    __shared__ float s_scl[BM], s_off[BM];
    if (EPI == EP_X1 || EPI == EP_BNR || EPI == EP_BNR_T || EPI == EP_FINAL) {
#pragma unroll
        for (int i = tid; i < BM; i += 256) {
            int rg = rowStart + i;
            float inv = rsqrtf(vv[rg] + EPS_BN);
            float sc = gg[rg] * inv;
            s_scl[i] = sc;
            s_off[i] = bb[rg] - mm[rg] * sc;
        }
        __syncthreads();
    }

    const size_t sC = (size_t)M * N;
#pragma unroll
    for (int i = 0; i < 4; i++) {
#pragma unroll
        for (int j = 0; j < 8; j++) {
#pragma unroll
            for (int hseg = 0; hseg < 2; hseg++) {
                const int rl = m_w + i * 16 + (lane >> 2) + hseg * 8;
                const int cl = n_w + j * 8 + (lane & 3) * 2;
                const float y0 = acc[i][j][hseg * 2];
                const float y1 = acc[i][j][hseg * 2 + 1];
                const int rg = rowStart + rl;
                const int cg = colStart + cl;
                const size_t o = (size_t)bz * sC + (size_t)rg * N + cg;

                if (EPI == EP_S) {
                    float2 v2; v2.x = y0; v2.y = y1;
                    *(float2*)(C32 + o) = v2;
                } else if (EPI == EP_SUBDIV) {
                    float2 ad  = *(const float2*)(add + o);
                    float2 rdv = *(const float2*)(rdiv + (size_t)bz * N + cg);
                    float z0 = ad.x - y0 * rdv.x;
                    float z1 = ad.y - y1 * rdv.y;
                    bf16 h0 = __float2bfloat16(z0), h1 = __float2bfloat16(z1);
                    __nv_bfloat162 hh; hh.x = h0; hh.y = h1;
                    __nv_bfloat162 ll;
                    ll.x = __float2bfloat16(z0 - __bfloat162float(h0));
                    ll.y = __float2bfloat16(z1 - __bfloat162float(h1));
                    *(__nv_bfloat162*)(Ch + o) = hh;
                    *(__nv_bfloat162*)(Cl + o) = ll;
                } else {
                    const float sc = s_scl[rl], of = s_off[rl];
                    float z0 = fmaxf(y0 * sc + of, 0.f);
                    float z1 = fmaxf(y1 * sc + of, 0.f);
                    if (EPI == EP_BNR_T) {
                        size_t ot = (size_t)bz * ((size_t)NPTS * CQK);
                        size_t o0 = ot + (size_t)cg * CQK + rg;
                        size_t o1 = o0 + CQK;
                        bf16 h0 = __float2bfloat16(z0), h1 = __float2bfloat16(z1);
                        Ch[o0] = h0; Cl[o0] = __float2bfloat16(z0 - __bfloat162float(h0));
                        Ch[o1] = h1; Cl[o1] = __float2bfloat16(z1 - __bfloat162float(h1));
                    } else if (EPI == EP_FINAL) {
                        float2 ad = *(const float2*)(add + o);
                        float2 v2; v2.x = ad.x + z0; v2.y = ad.y + z1;
                        *(float2*)(C32 + o) = v2;
                    } else {
                        if (EPI == EP_X1) {
                            float2 v2; v2.x = z0; v2.y = z1;
                            *(float2*)(C32 + o) = v2;
                        }
                        bf16 h0 = __float2bfloat16(z0), h1 = __float2bfloat16(z1);
                        __nv_bfloat162 hh; hh.x = h0; hh.y = h1;
                        __nv_bfloat162 ll;
                        ll.x = __float2bfloat16(z0 - __bfloat162float(h0));
                        ll.y = __float2bfloat16(z1 - __bfloat162float(h1));
                        *(__nv_bfloat162*)(Ch + o) = hh;
                        *(__nv_bfloat162*)(Cl + o) = ll;
                    }
                }
            }
        }
    }
}

// ---------------- merged fp32 -> bf16 hi/lo split of all inputs ----------------
#define NX (BATCH * CH * NPTS)
#define NW (CH * CH)
#define NQW (CQK * CH)

__global__ void __launch_bounds__(256)
split_all(const float* __restrict__ x,  bf16* __restrict__ xh,  bf16* __restrict__ xl,
          const float* __restrict__ W1, bf16* __restrict__ W1h, bf16* __restrict__ W1l,
          const float* __restrict__ W2, bf16* __restrict__ W2h, bf16* __restrict__ W2l,
          const float* __restrict__ W3, bf16* __restrict__ W3h, bf16* __restrict__ W3l,
          const float* __restrict__ W4, bf16* __restrict__ W4h, bf16* __restrict__ W4l,
          const float* __restrict__ W5, bf16* __restrict__ W5h, bf16* __restrict__ W5l)
{
    size_t i = (size_t)blockIdx.x * 256 + threadIdx.x;
    const float* in; bf16 *oh, *ol; size_t li;
    if (i < NX)                       { in = x;  oh = xh;  ol = xl;  li = i; }
    else if (i < NX + NW)             { in = W1; oh = W1h; ol = W1l; li = i - NX; }
    else if (i < NX + 2 * NW)         { in = W2; oh = W2h; ol = W2l; li = i - NX - NW; }
    else if (i < NX + 2 * NW + NQW)   { in = W3; oh = W3h; ol = W3l; li = i - NX - 2 * NW; }
    else if (i < NX + 2 * NW + 2*NQW) { in = W4; oh = W4h; ol = W4l; li = i - NX - 2 * NW - NQW; }
    else                              { in = W5; oh = W5h; ol = W5l; li = i - NX - 2 * NW - 2 * NQW; }
    float v = in[li];
    bf16 h = __float2bfloat16(v);
    oh[li] = h;
    ol[li] = __float2bfloat16(v - __bfloat162float(h));
}

// ---------------- row softmax: fp32 in, bf16 hi/lo out ----------------
__global__ void __launch_bounds__(256)
softmax_kernel(const float* __restrict__ S, bf16* __restrict__ Sh, bf16* __restrict__ Sl)
{
    __shared__ float buf[NPTS];
    __shared__ float red[8];
    const float* p = S + (size_t)blockIdx.x * NPTS;
    bf16* ph = Sh + (size_t)blockIdx.x * NPTS;
    bf16* pl = Sl + (size_t)blockIdx.x * NPTS;
    int t = threadIdx.x;

    float mx = -3.402823466e38f;
    for (int i = t; i < NPTS; i += 256) { float v = p[i]; buf[i] = v; mx = fmaxf(mx, v); }
#pragma unroll
    for (int o = 16; o > 0; o >>= 1) mx = fmaxf(mx, __shfl_xor_sync(0xffffffffu, mx, o));
    if ((t & 31) == 0) red[t >> 5] = mx;
    __syncthreads();
    float bm = red[0];
#pragma unroll
    for (int i = 1; i < 8; i++) bm = fmaxf(bm, red[i]);
    __syncthreads();

    float sum = 0.f;
    for (int i = t; i < NPTS; i += 256) { float e = __expf(buf[i] - bm); buf[i] = e; sum += e; }
#pragma unroll
    for (int o = 16; o > 0; o >>= 1) sum += __shfl_xor_sync(0xffffffffu, sum, o);
    if ((t & 31) == 0) red[t >> 5] = sum;
    __syncthreads();
    float bs = 0.f;
#pragma unroll
    for (int i = 0; i < 8; i++) bs += red[i];
    float inv = 1.0f / bs;
    for (int i = t; i < NPTS; i += 256) {
        float v = buf[i] * inv;
        bf16 h = __float2bfloat16(v);
        ph[i] = h;
        pl[i] = __float2bfloat16(v - __bfloat162float(h));
    }
}

// ---------------- column sums -> 1/(eps+colsum) ----------------
__global__ void __launch_bounds__(256)
colsum_kernel(const bf16* __restrict__ Sh, const bf16* __restrict__ Sl,
              float* __restrict__ rdiv)
{
    int idx = blockIdx.x * 256 + threadIdx.x;
    int b = idx / NPTS, m = idx - b * NPTS;
    const bf16* ph = Sh + (size_t)b * NPTS * NPTS + m;
    const bf16* pl = Sl + (size_t)b * NPTS * NPTS + m;
    float s[4] = {0.f, 0.f, 0.f, 0.f};
    for (int n = 0; n < NPTS; n += 4) {
#pragma unroll
        for (int u = 0; u < 4; u++) {
            size_t o = (size_t)(n + u) * NPTS;
            s[u] += __bfloat162float(ph[o]) + __bfloat162float(pl[o]);
        }
    }
    rdiv[idx] = 1.0f / (EPS_RENORM + ((s[0] + s[1]) + (s[2] + s[3])));
}

// ---------------- launch ----------------
#define SMEM_GEMM (NSTG * 49152)

extern "C" void kernel_launch(void* const* d_in, const int* in_sizes, int n_in,
                              void* d_out, int out_size)
{
    (void)in_sizes; (void)n_in; (void)out_size;
    const float* x  = (const float*)d_in[0];
    const float *W1 = (const float*)d_in[1],  *g1 = (const float*)d_in[2],
                *b1 = (const float*)d_in[3],  *m1 = (const float*)d_in[4],
                *v1 = (const float*)d_in[5];
    const float *W2 = (const float*)d_in[6],  *g2 = (const float*)d_in[7],
                *b2 = (const float*)d_in[8],  *m2 = (const float*)d_in[9],
                *v2 = (const float*)d_in[10];
    const float *W3 = (const float*)d_in[11], *g3 = (const float*)d_in[12],
                *b3 = (const float*)d_in[13], *m3 = (const float*)d_in[14],
                *v3 = (const float*)d_in[15];
    const float *W4 = (const float*)d_in[16], *g4 = (const float*)d_in[17],
                *b4 = (const float*)d_in[18], *m4 = (const float*)d_in[19],
                *v4 = (const float*)d_in[20];
    const float *W5 = (const float*)d_in[21], *g5 = (const float*)d_in[22],
                *b5 = (const float*)d_in[23], *m5 = (const float*)d_in[24],
                *v5 = (const float*)d_in[25];
    float* out = (float*)d_out;

    float *x1, *S, *rd;
    bf16 *xh, *xl, *x1h, *x1l, *vh, *vl, *th, *tl, *qh, *ql, *kh, *kl, *Sh, *Sl;
    bf16 *W1h, *W1l, *W2h, *W2l, *W3h, *W3l, *W4h, *W4l, *W5h, *W5l;
    cudaGetSymbolAddress((void**)&x1, g_x1);
    cudaGetSymbolAddress((void**)&S,  g_S);
    cudaGetSymbolAddress((void**)&rd, g_rd);
    cudaGetSymbolAddress((void**)&xh, g_xh);   cudaGetSymbolAddress((void**)&xl, g_xl);
    cudaGetSymbolAddress((void**)&x1h, g_x1h); cudaGetSymbolAddress((void**)&x1l, g_x1l);
    cudaGetSymbolAddress((void**)&vh, g_vh);   cudaGetSymbolAddress((void**)&vl, g_vl);
    cudaGetSymbolAddress((void**)&th, g_th);   cudaGetSymbolAddress((void**)&tl, g_tl);
    cudaGetSymbolAddress((void**)&qh, g_qh);   cudaGetSymbolAddress((void**)&ql, g_ql);
    cudaGetSymbolAddress((void**)&kh, g_kh);   cudaGetSymbolAddress((void**)&kl, g_kl);
    cudaGetSymbolAddress((void**)&Sh, g_Sh);   cudaGetSymbolAddress((void**)&Sl, g_Sl);
    cudaGetSymbolAddress((void**)&W1h, g_W1h); cudaGetSymbolAddress((void**)&W1l, g_W1l);
    cudaGetSymbolAddress((void**)&W2h, g_W2h); cudaGetSymbolAddress((void**)&W2l, g_W2l);
    cudaGetSymbolAddress((void**)&W3h, g_W3h); cudaGetSymbolAddress((void**)&W3l, g_W3l);
    cudaGetSymbolAddress((void**)&W4h, g_W4h); cudaGetSymbolAddress((void**)&W4l, g_W4l);
    cudaGetSymbolAddress((void**)&W5h, g_W5h); cudaGetSymbolAddress((void**)&W5l, g_W5l);

    cudaFuncSetAttribute(mma_gemm<EP_X1, false, 256, 128>,    cudaFuncAttributeMaxDynamicSharedMemorySize, SMEM_GEMM);
    cudaFuncSetAttribute(mma_gemm<EP_BNR, false, 256, 128>,   cudaFuncAttributeMaxDynamicSharedMemorySize, SMEM_GEMM);
    cudaFuncSetAttribute(mma_gemm<EP_BNR_T, false, 128, 256>, cudaFuncAttributeMaxDynamicSharedMemorySize, SMEM_GEMM);
    cudaFuncSetAttribute(mma_gemm<EP_BNR, false, 128, 256>,   cudaFuncAttributeMaxDynamicSharedMemorySize, SMEM_GEMM);
    cudaFuncSetAttribute(mma_gemm<EP_S, true, 256, 128>,      cudaFuncAttributeMaxDynamicSharedMemorySize, SMEM_GEMM);
    cudaFuncSetAttribute(mma_gemm<EP_SUBDIV, true, 256, 128>, cudaFuncAttributeMaxDynamicSharedMemorySize, SMEM_GEMM);
    cudaFuncSetAttribute(mma_gemm<EP_FINAL, false, 256, 128>, cudaFuncAttributeMaxDynamicSharedMemorySize, SMEM_GEMM);

    const size_t sX  = (size_t)CH * NPTS;
    const size_t sQT = (size_t)NPTS * CQK;
    const size_t sK  = (size_t)CQK * NPTS;
    const size_t sS  = (size_t)NPTS * NPTS;

    // 0) merged hi/lo split of x and all weights  (1 launch)
    const int splitTotal = NX + 2 * NW + 2 * NQW + NW;
    split_all<<<splitTotal / 256, 256>>>(x, xh, xl, W1, W1h, W1l, W2, W2h, W2l,
                                         W3, W3h, W3l, W4, W4h, W4l, W5, W5h, W5l);
    // 1) x1 = relu(bn1(W1 @ x))
    mma_gemm<EP_X1, false, 256, 128><<<dim3(16, 4, 8), 256, SMEM_GEMM>>>(
        W1h, W1l, 0, xh, xl, sX, CH, CH,
        x1, x1h, x1l, g1, b1, m1, v1, nullptr, nullptr);
    // 2) v = relu(bn2(W2 @ x1))
    mma_gemm<EP_BNR, false, 256, 128><<<dim3(16, 4, 8), 256, SMEM_GEMM>>>(
        W2h, W2l, 0, x1h, x1l, sX, CH, CH,
        nullptr, vh, vl, g2, b2, m2, v2, nullptr, nullptr);
    // 3) q (stored transposed q^T [n][c])
    mma_gemm<EP_BNR_T, false, 128, 256><<<dim3(8, 1, 8), 256, SMEM_GEMM>>>(
        W3h, W3l, 0, x1h, x1l, sX, CQK, CH,
        nullptr, qh, ql, g3, b3, m3, v3, nullptr, nullptr);
    // 4) k
    mma_gemm<EP_BNR, false, 128, 256><<<dim3(8, 1, 8), 256, SMEM_GEMM>>>(
        W4h, W4l, 0, x1h, x1l, sX, CQK, CH,
        nullptr, kh, kl, g4, b4, m4, v4, nullptr, nullptr);
    // 5) scores S[n][m] = sum_c qT[n][c] k[c][m]   <- ncu -s 5 captures this
    mma_gemm<EP_S, true, 256, 128><<<dim3(16, 8, 8), 256, SMEM_GEMM>>>(
        qh, ql, sQT, kh, kl, sK, NPTS, CQK,
        S, nullptr, nullptr, nullptr, nullptr, nullptr, nullptr, nullptr, nullptr);
    // 6) row softmax -> bf16 hi/lo
    softmax_kernel<<<BATCH * NPTS, 256>>>(S, Sh, Sl);
    // 7) renorm divisor
    colsum_kernel<<<(BATCH * NPTS) / 256, 256>>>(Sh, Sl, rd);
    // 8) t = x1 - (v @ S) * rdiv[col]
    mma_gemm<EP_SUBDIV, true, 256, 128><<<dim3(16, 4, 8), 256, SMEM_GEMM>>>(
        vh, vl, sX, Sh, Sl, sS, CH, NPTS,
        nullptr, th, tl, nullptr, nullptr, nullptr, nullptr, x1, rd);
    // 9) out = x1 + relu(bn5(W5 @ t))
    mma_gemm<EP_FINAL, false, 256, 128><<<dim3(16, 4, 8), 256, SMEM_GEMM>>>(
        W5h, W5l, 0, th, tl, sX, CH, CH,
        out, nullptr, nullptr, g5, b5, m5, v5, x1, nullptr);
}

// round 10
// speedup vs baseline: 1.2021x; 1.2021x over previous
#include <cuda_runtime.h>
#include <cuda_bf16.h>
#include <cstdint>

#define EPS_BN 1e-5f
#define EPS_RENORM 1e-9f

#define BATCH 8
#define CH    1024
#define NPTS  2048
#define CQK   128

typedef __nv_bfloat16 bf16;

// ---------------- scratch (no allocations allowed) ----------------
__device__ float g_x1[BATCH * CH * NPTS];
__device__ float g_S [(size_t)BATCH * NPTS * NPTS];
__device__ float g_rd[BATCH * NPTS];
__device__ bf16 g_xh [BATCH * CH * NPTS], g_xl [BATCH * CH * NPTS];
__device__ bf16 g_x1h[BATCH * CH * NPTS], g_x1l[BATCH * CH * NPTS];
__device__ bf16 g_vh [BATCH * CH * NPTS], g_vl [BATCH * CH * NPTS];
__device__ bf16 g_th [BATCH * CH * NPTS], g_tl [BATCH * CH * NPTS];
__device__ bf16 g_qh [BATCH * NPTS * CQK], g_ql[BATCH * NPTS * CQK];
__device__ bf16 g_kh [BATCH * CQK * NPTS], g_kl[BATCH * CQK * NPTS];
__device__ bf16 g_Sh [(size_t)BATCH * NPTS * NPTS], g_Sl[(size_t)BATCH * NPTS * NPTS];
__device__ bf16 g_W1h[CH * CH],  g_W1l[CH * CH];
__device__ bf16 g_W2h[CH * CH],  g_W2l[CH * CH];
__device__ bf16 g_W5h[CH * CH],  g_W5l[CH * CH];
__device__ bf16 g_W3h[CQK * CH], g_W3l[CQK * CH];
__device__ bf16 g_W4h[CQK * CH], g_W4l[CQK * CH];

// ---------------- PTX helpers ----------------
__device__ __forceinline__ uint32_t s2u(const void* p) {
    uint32_t a;
    asm("{ .reg .u64 t; cvta.to.shared.u64 t, %1; cvt.u32.u64 %0, t; }"
        : "=r"(a) : "l"(p));
    return a;
}
__device__ __forceinline__ void cp16(uint32_t saddr, const void* g) {
    asm volatile("cp.async.cg.shared.global [%0], [%1], 16;"
                 :: "r"(saddr), "l"(g) : "memory");
}
#define CP_COMMIT() asm volatile("cp.async.commit_group;" ::: "memory")
#define CP_WAIT(n)  asm volatile("cp.async.wait_group %0;" :: "n"(n) : "memory")

__device__ __forceinline__ void ldsm4(uint32_t* r, uint32_t a) {
    asm volatile("ldmatrix.sync.aligned.m8n8.x4.shared.b16 {%0,%1,%2,%3}, [%4];"
                 : "=r"(r[0]), "=r"(r[1]), "=r"(r[2]), "=r"(r[3]) : "r"(a));
}
__device__ __forceinline__ void ldsm4t(uint32_t* r, uint32_t a) {
    asm volatile("ldmatrix.sync.aligned.m8n8.x4.trans.shared.b16 {%0,%1,%2,%3}, [%4];"
                 : "=r"(r[0]), "=r"(r[1]), "=r"(r[2]), "=r"(r[3]) : "r"(a));
}
__device__ __forceinline__ void mma16816(float* d, const uint32_t* a, const uint32_t* b) {
    asm volatile("mma.sync.aligned.m16n8k16.row.col.f32.bf16.bf16.f32 "
                 "{%0,%1,%2,%3}, {%4,%5,%6,%7}, {%8,%9}, {%0,%1,%2,%3};"
                 : "+f"(d[0]), "+f"(d[1]), "+f"(d[2]), "+f"(d[3])
                 : "r"(a[0]), "r"(a[1]), "r"(a[2]), "r"(a[3]), "r"(b[0]), "r"(b[1]));
}

// ---------------- split-bf16 MMA GEMM ----------------
// C[b] (M x N) = (Ah+Al)[b] @ (Bh+Bl)[b] ; 3-term split product.
// A row-major [M][K], B row-major [K][N], N == NPTS.
// CTA 128x128, BK=32, 8 warps (warp tile 32x64), 3-stage cp.async, 2 CTAs/SM.
#define NSTG   3
#define STG_B  32768
#define SMEM_GEMM (NSTG * STG_B)      // 96 KiB dynamic -> 2 CTAs/SM

enum { EP_X1 = 0, EP_BNR = 1, EP_BNR_T = 2, EP_S = 3, EP_SUBDIV = 4, EP_FINAL = 5 };

template<int EPI, bool ABATCH>
__global__ void __launch_bounds__(256, 2)
mma_gemm(const bf16* __restrict__ Ahp, const bf16* __restrict__ Alp, size_t sA,
         const bf16* __restrict__ Bhp, const bf16* __restrict__ Blp, size_t sB,
         int M, int K,
         float* __restrict__ C32, bf16* __restrict__ Ch, bf16* __restrict__ Cl,
         const float* __restrict__ gg, const float* __restrict__ bb,
         const float* __restrict__ mm, const float* __restrict__ vv,
         const float* __restrict__ add, const float* __restrict__ rdiv)
{
    extern __shared__ __align__(256) char smraw[];
    const uint32_t smb = s2u(smraw);
    const int tid  = threadIdx.x;
    const int lane = tid & 31;
    const int wid  = tid >> 5;
    const int m_w  = (wid & 3) * 32;     // warp M offset
    const int n_w  = (wid >> 2) * 64;    // warp N offset
    const int bz   = blockIdx.z;
    const int rowStart = blockIdx.y * 128;
    const int colStart = blockIdx.x * 128;
    const int N = NPTS;

    const bf16* Ah_ = Ahp + (ABATCH ? (size_t)bz * sA : 0);
    const bf16* Al_ = Alp + (ABATCH ? (size_t)bz * sA : 0);
    const bf16* Bh_ = Bhp + (size_t)bz * sB;
    const bf16* Bl_ = Blp + (size_t)bz * sB;

    float acc[2][8][4];
#pragma unroll
    for (int i = 0; i < 2; i++)
#pragma unroll
        for (int j = 0; j < 8; j++)
#pragma unroll
            for (int r = 0; r < 4; r++) acc[i][j][r] = 0.f;

    // stage layout: Ah @0 (8K) | Al @8192 | Bh @16384 | Bl @24576
    auto loadStage = [&](int t) {
        const int s = t % NSTG;
        const uint32_t base = smb + (uint32_t)s * STG_B;
        const int k0 = t * 32;
#pragma unroll
        for (int i = 0; i < 2; i++) {            // A: 128 rows x 4 chunks (16B)
            int idx = tid + i * 256;
            int row = idx >> 2, c = idx & 3;
            uint32_t off = (uint32_t)(row * 64 + ((c ^ ((row >> 1) & 3)) << 4));
            size_t go = (size_t)(rowStart + row) * K + k0 + c * 8;
            cp16(base + off,        Ah_ + go);
            cp16(base + 8192 + off, Al_ + go);
        }
#pragma unroll
        for (int i = 0; i < 2; i++) {            // B: 32 rows x 16 chunks
            int idx = tid + i * 256;
            int k = idx >> 4, cn = idx & 15;
            uint32_t off = (uint32_t)(k * 256 + ((cn ^ (k & 7)) << 4));
            size_t go = (size_t)(k0 + k) * N + colStart + cn * 8;
            cp16(base + 16384 + off, Bh_ + go);
            cp16(base + 24576 + off, Bl_ + go);
        }
        CP_COMMIT();
    };

    const int T = K / 32;
    const int P = (T < 2) ? T : 2;
    for (int t = 0; t < P; t++) loadStage(t);

    for (int t = 0; t < T; t++) {
        if (t + 1 < T) { CP_WAIT(1); } else { CP_WAIT(0); }
        __syncthreads();
        if (t + 2 < T) loadStage(t + 2);

        const uint32_t Ab = smb + (uint32_t)(t % NSTG) * STG_B;
#pragma unroll
        for (int ks = 0; ks < 2; ks++) {
            uint32_t ah[2][4], al[2][4];
#pragma unroll
            for (int i = 0; i < 2; i++) {
                int row = m_w + i * 16 + (lane & 15);
                int c = ks * 2 + (lane >> 4);
                uint32_t off = (uint32_t)(row * 64 + ((c ^ ((row >> 1) & 3)) << 4));
                ldsm4(ah[i], Ab + off);
                ldsm4(al[i], Ab + 8192 + off);
            }
#pragma unroll
            for (int p = 0; p < 4; p++) {
                int g = lane >> 3, j8 = lane & 7;
                int k = ks * 16 + (g & 1) * 8 + j8;
                int cn = (n_w >> 3) + p * 2 + (g >> 1);
                uint32_t off = (uint32_t)(k * 256 + ((cn ^ (k & 7)) << 4));
                uint32_t bh[4], bl[4];
                ldsm4t(bh, Ab + 16384 + off);
                ldsm4t(bl, Ab + 24576 + off);
#pragma unroll
                for (int i = 0; i < 2; i++) {
                    mma16816(acc[i][2 * p],     ah[i], bh);
                    mma16816(acc[i][2 * p],     ah[i], bl);
                    mma16816(acc[i][2 * p],     al[i], bh);
                    mma16816(acc[i][2 * p + 1], ah[i], bh + 2);
                    mma16816(acc[i][2 * p + 1], ah[i], bl + 2);
                    mma16816(acc[i][2 * p + 1], al[i], bh + 2);
                }
            }
        }
        __syncthreads();
    }

    // ---------------- epilogue ----------------
    __shared__ float s_scl[128], s_off[128];
    if (EPI == EP_X1 || EPI == EP_BNR || EPI == EP_BNR_T || EPI == EP_FINAL) {
        if (tid < 128) {
            int rg = rowStart + tid;
            float inv = rsqrtf(vv[rg] + EPS_BN);
            float sc = gg[rg] * inv;
            s_scl[tid] = sc;
            s_off[tid] = bb[rg] - mm[rg] * sc;
        }
        __syncthreads();
    }

    const size_t sC = (size_t)M * N;
#pragma unroll
    for (int i = 0; i < 2; i++) {
#pragma unroll
        for (int j = 0; j < 8; j++) {
#pragma unroll
            for (int hseg = 0; hseg < 2; hseg++) {
                const int rl = m_w + i * 16 + (lane >> 2) + hseg * 8;
                const int cl = n_w + j * 8 + (lane & 3) * 2;
                const float y0 = acc[i][j][hseg * 2];
                const float y1 = acc[i][j][hseg * 2 + 1];
                const int rg = rowStart + rl;
                const int cg = colStart + cl;
                const size_t o = (size_t)bz * sC + (size_t)rg * N + cg;

                if (EPI == EP_S) {
                    float2 v2; v2.x = y0; v2.y = y1;
                    *(float2*)(C32 + o) = v2;
                } else if (EPI == EP_SUBDIV) {
                    float2 ad  = *(const float2*)(add + o);
                    float2 rdv = *(const float2*)(rdiv + (size_t)bz * N + cg);
                    float z0 = ad.x - y0 * rdv.x;
                    float z1 = ad.y - y1 * rdv.y;
                    bf16 h0 = __float2bfloat16(z0), h1 = __float2bfloat16(z1);
                    __nv_bfloat162 hh; hh.x = h0; hh.y = h1;
                    __nv_bfloat162 ll;
                    ll.x = __float2bfloat16(z0 - __bfloat162float(h0));
                    ll.y = __float2bfloat16(z1 - __bfloat162float(h1));
                    *(__nv_bfloat162*)(Ch + o) = hh;
                    *(__nv_bfloat162*)(Cl + o) = ll;
                } else {
                    const float sc = s_scl[rl], of = s_off[rl];
                    float z0 = fmaxf(y0 * sc + of, 0.f);
                    float z1 = fmaxf(y1 * sc + of, 0.f);
                    if (EPI == EP_BNR_T) {
                        size_t ot = (size_t)bz * ((size_t)NPTS * CQK);
                        size_t o0 = ot + (size_t)cg * CQK + rg;
                        size_t o1 = o0 + CQK;
                        bf16 h0 = __float2bfloat16(z0), h1 = __float2bfloat16(z1);
                        Ch[o0] = h0; Cl[o0] = __float2bfloat16(z0 - __bfloat162float(h0));
                        Ch[o1] = h1; Cl[o1] = __float2bfloat16(z1 - __bfloat162float(h1));
                    } else if (EPI == EP_FINAL) {
                        float2 ad = *(const float2*)(add + o);
                        float2 v2; v2.x = ad.x + z0; v2.y = ad.y + z1;
                        *(float2*)(C32 + o) = v2;
                    } else {
                        if (EPI == EP_X1) {
                            float2 v2; v2.x = z0; v2.y = z1;
                            *(float2*)(C32 + o) = v2;
                        }
                        bf16 h0 = __float2bfloat16(z0), h1 = __float2bfloat16(z1);
                        __nv_bfloat162 hh; hh.x = h0; hh.y = h1;
                        __nv_bfloat162 ll;
                        ll.x = __float2bfloat16(z0 - __bfloat162float(h0));
                        ll.y = __float2bfloat16(z1 - __bfloat162float(h1));
                        *(__nv_bfloat162*)(Ch + o) = hh;
                        *(__nv_bfloat162*)(Cl + o) = ll;
                    }
                }
            }
        }
    }
}

// ---------------- merged fp32 -> bf16 hi/lo split of all inputs ----------------
#define NX (BATCH * CH * NPTS)
#define NW (CH * CH)
#define NQW (CQK * CH)

__global__ void __launch_bounds__(256)
split_all(const float* __restrict__ x,  bf16* __restrict__ xh,  bf16* __restrict__ xl,
          const float* __restrict__ W1, bf16* __restrict__ W1h, bf16* __restrict__ W1l,
          const float* __restrict__ W2, bf16* __restrict__ W2h, bf16* __restrict__ W2l,
          const float* __restrict__ W3, bf16* __restrict__ W3h, bf16* __restrict__ W3l,
          const float* __restrict__ W4, bf16* __restrict__ W4h, bf16* __restrict__ W4l,
          const float* __restrict__ W5, bf16* __restrict__ W5h, bf16* __restrict__ W5l)
{
    size_t i = (size_t)blockIdx.x * 256 + threadIdx.x;
    const float* in; bf16 *oh, *ol; size_t li;
    if (i < NX)                       { in = x;  oh = xh;  ol = xl;  li = i; }
    else if (i < NX + NW)             { in = W1; oh = W1h; ol = W1l; li = i - NX; }
    else if (i < NX + 2 * NW)         { in = W2; oh = W2h; ol = W2l; li = i - NX - NW; }
    else if (i < NX + 2 * NW + NQW)   { in = W3; oh = W3h; ol = W3l; li = i - NX - 2 * NW; }
    else if (i < NX + 2 * NW + 2*NQW) { in = W4; oh = W4h; ol = W4l; li = i - NX - 2 * NW - NQW; }
    else                              { in = W5; oh = W5h; ol = W5l; li = i - NX - 2 * NW - 2 * NQW; }
    float v = in[li];
    bf16 h = __float2bfloat16(v);
    oh[li] = h;
    ol[li] = __float2bfloat16(v - __bfloat162float(h));
}

// ---------------- row softmax: fp32 in, bf16 hi/lo out ----------------
__global__ void __launch_bounds__(256)
softmax_kernel(const float* __restrict__ S, bf16* __restrict__ Sh, bf16* __restrict__ Sl)
{
    __shared__ float buf[NPTS];
    __shared__ float red[8];
    const float* p = S + (size_t)blockIdx.x * NPTS;
    bf16* ph = Sh + (size_t)blockIdx.x * NPTS;
    bf16* pl = Sl + (size_t)blockIdx.x * NPTS;
    int t = threadIdx.x;

    float mx = -3.402823466e38f;
    for (int i = t; i < NPTS; i += 256) { float v = p[i]; buf[i] = v; mx = fmaxf(mx, v); }
#pragma unroll
    for (int o = 16; o > 0; o >>= 1) mx = fmaxf(mx, __shfl_xor_sync(0xffffffffu, mx, o));
    if ((t & 31) == 0) red[t >> 5] = mx;
    __syncthreads();
    float bm = red[0];
#pragma unroll
    for (int i = 1; i < 8; i++) bm = fmaxf(bm, red[i]);
    __syncthreads();

    float sum = 0.f;
    for (int i = t; i < NPTS; i += 256) { float e = __expf(buf[i] - bm); buf[i] = e; sum += e; }
#pragma unroll
    for (int o = 16; o > 0; o >>= 1) sum += __shfl_xor_sync(0xffffffffu, sum, o);
    if ((t & 31) == 0) red[t >> 5] = sum;
    __syncthreads();
    float bs = 0.f;
#pragma unroll
    for (int i = 0; i < 8; i++) bs += red[i];
    float inv = 1.0f / bs;
    for (int i = t; i < NPTS; i += 256) {
        float v = buf[i] * inv;
        bf16 h = __float2bfloat16(v);
        ph[i] = h;
        pl[i] = __float2bfloat16(v - __bfloat162float(h));
    }
}

// ---------------- column sums -> 1/(eps+colsum) ----------------
__global__ void __launch_bounds__(256)
colsum_kernel(const bf16* __restrict__ Sh, const bf16* __restrict__ Sl,
              float* __restrict__ rdiv)
{
    int idx = blockIdx.x * 256 + threadIdx.x;
    int b = idx / NPTS, m = idx - b * NPTS;
    const bf16* ph = Sh + (size_t)b * NPTS * NPTS + m;
    const bf16* pl = Sl + (size_t)b * NPTS * NPTS + m;
    float s[4] = {0.f, 0.f, 0.f, 0.f};
    for (int n = 0; n < NPTS; n += 4) {
#pragma unroll
        for (int u = 0; u < 4; u++) {
            size_t o = (size_t)(n + u) * NPTS;
            s[u] += __bfloat162float(ph[o]) + __bfloat162float(pl[o]);
        }
    }
    rdiv[idx] = 1.0f / (EPS_RENORM + ((s[0] + s[1]) + (s[2] + s[3])));
}

// ---------------- launch ----------------
extern "C" void kernel_launch(void* const* d_in, const int* in_sizes, int n_in,
                              void* d_out, int out_size)
{
    (void)in_sizes; (void)n_in; (void)out_size;
    const float* x  = (const float*)d_in[0];
    const float *W1 = (const float*)d_in[1],  *g1 = (const float*)d_in[2],
                *b1 = (const float*)d_in[3],  *m1 = (const float*)d_in[4],
                *v1 = (const float*)d_in[5];
    const float *W2 = (const float*)d_in[6],  *g2 = (const float*)d_in[7],
                *b2 = (const float*)d_in[8],  *m2 = (const float*)d_in[9],
                *v2 = (const float*)d_in[10];
    const float *W3 = (const float*)d_in[11], *g3 = (const float*)d_in[12],
                *b3 = (const float*)d_in[13], *m3 = (const float*)d_in[14],
                *v3 = (const float*)d_in[15];
    const float *W4 = (const float*)d_in[16], *g4 = (const float*)d_in[17],
                *b4 = (const float*)d_in[18], *m4 = (const float*)d_in[19],
                *v4 = (const float*)d_in[20];
    const float *W5 = (const float*)d_in[21], *g5 = (const float*)d_in[22],
                *b5 = (const float*)d_in[23], *m5 = (const float*)d_in[24],
                *v5 = (const float*)d_in[25];
    float* out = (float*)d_out;

    float *x1, *S, *rd;
    bf16 *xh, *xl, *x1h, *x1l, *vh, *vl, *th, *tl, *qh, *ql, *kh, *kl, *Sh, *Sl;
    bf16 *W1h, *W1l, *W2h, *W2l, *W3h, *W3l, *W4h, *W4l, *W5h, *W5l;
    cudaGetSymbolAddress((void**)&x1, g_x1);
    cudaGetSymbolAddress((void**)&S,  g_S);
    cudaGetSymbolAddress((void**)&rd, g_rd);
    cudaGetSymbolAddress((void**)&xh, g_xh);   cudaGetSymbolAddress((void**)&xl, g_xl);
    cudaGetSymbolAddress((void**)&x1h, g_x1h); cudaGetSymbolAddress((void**)&x1l, g_x1l);
    cudaGetSymbolAddress((void**)&vh, g_vh);   cudaGetSymbolAddress((void**)&vl, g_vl);
    cudaGetSymbolAddress((void**)&th, g_th);   cudaGetSymbolAddress((void**)&tl, g_tl);
    cudaGetSymbolAddress((void**)&qh, g_qh);   cudaGetSymbolAddress((void**)&ql, g_ql);
    cudaGetSymbolAddress((void**)&kh, g_kh);   cudaGetSymbolAddress((void**)&kl, g_kl);
    cudaGetSymbolAddress((void**)&Sh, g_Sh);   cudaGetSymbolAddress((void**)&Sl, g_Sl);
    cudaGetSymbolAddress((void**)&W1h, g_W1h); cudaGetSymbolAddress((void**)&W1l, g_W1l);
    cudaGetSymbolAddress((void**)&W2h, g_W2h); cudaGetSymbolAddress((void**)&W2l, g_W2l);
    cudaGetSymbolAddress((void**)&W3h, g_W3h); cudaGetSymbolAddress((void**)&W3l, g_W3l);
    cudaGetSymbolAddress((void**)&W4h, g_W4h); cudaGetSymbolAddress((void**)&W4l, g_W4l);
    cudaGetSymbolAddress((void**)&W5h, g_W5h); cudaGetSymbolAddress((void**)&W5l, g_W5l);

    cudaFuncSetAttribute(mma_gemm<EP_X1, false>,    cudaFuncAttributeMaxDynamicSharedMemorySize, SMEM_GEMM);
    cudaFuncSetAttribute(mma_gemm<EP_BNR, false>,   cudaFuncAttributeMaxDynamicSharedMemorySize, SMEM_GEMM);
    cudaFuncSetAttribute(mma_gemm<EP_BNR_T, false>, cudaFuncAttributeMaxDynamicSharedMemorySize, SMEM_GEMM);
    cudaFuncSetAttribute(mma_gemm<EP_S, true>,      cudaFuncAttributeMaxDynamicSharedMemorySize, SMEM_GEMM);
    cudaFuncSetAttribute(mma_gemm<EP_SUBDIV, true>, cudaFuncAttributeMaxDynamicSharedMemorySize, SMEM_GEMM);
    cudaFuncSetAttribute(mma_gemm<EP_FINAL, false>, cudaFuncAttributeMaxDynamicSharedMemorySize, SMEM_GEMM);

    const size_t sX  = (size_t)CH * NPTS;
    const size_t sQT = (size_t)NPTS * CQK;
    const size_t sK  = (size_t)CQK * NPTS;
    const size_t sS  = (size_t)NPTS * NPTS;

    // 0) merged hi/lo split of x and all weights (1 launch)
    const int splitTotal = NX + 2 * NW + 2 * NQW + NW;
    split_all<<<splitTotal / 256, 256>>>(x, xh, xl, W1, W1h, W1l, W2, W2h, W2l,
                                         W3, W3h, W3l, W4, W4h, W4l, W5, W5h, W5l);
    // 1) x1 = relu(bn1(W1 @ x))
    mma_gemm<EP_X1, false><<<dim3(16, 8, 8), 256, SMEM_GEMM>>>(
        W1h, W1l, 0, xh, xl, sX, CH, CH,
        x1, x1h, x1l, g1, b1, m1, v1, nullptr, nullptr);
    // 2) v = relu(bn2(W2 @ x1))
    mma_gemm<EP_BNR, false><<<dim3(16, 8, 8), 256, SMEM_GEMM>>>(
        W2h, W2l, 0, x1h, x1l, sX, CH, CH,
        nullptr, vh, vl, g2, b2, m2, v2, nullptr, nullptr);
    // 3) q (stored transposed q^T [n][c])
    mma_gemm<EP_BNR_T, false><<<dim3(16, 1, 8), 256, SMEM_GEMM>>>(
        W3h, W3l, 0, x1h, x1l, sX, CQK, CH,
        nullptr, qh, ql, g3, b3, m3, v3, nullptr, nullptr);
    // 4) k
    mma_gemm<EP_BNR, false><<<dim3(16, 1, 8), 256, SMEM_GEMM>>>(
        W4h, W4l, 0, x1h, x1l, sX, CQK, CH,
        nullptr, kh, kl, g4, b4, m4, v4, nullptr, nullptr);
    // 5) scores S[n][m] = sum_c qT[n][c] k[c][m]
    mma_gemm<EP_S, true><<<dim3(16, 16, 8), 256, SMEM_GEMM>>>(
        qh, ql, sQT, kh, kl, sK, NPTS, CQK,
        S, nullptr, nullptr, nullptr, nullptr, nullptr, nullptr, nullptr, nullptr);
    // 6) row softmax -> bf16 hi/lo
    softmax_kernel<<<BATCH * NPTS, 256>>>(S, Sh, Sl);
    // 7) renorm divisor
    colsum_kernel<<<(BATCH * NPTS) / 256, 256>>>(Sh, Sl, rd);
    // 8) t = x1 - (v @ S) * rdiv[col]
    mma_gemm<EP_SUBDIV, true><<<dim3(16, 8, 8), 256, SMEM_GEMM>>>(
        vh, vl, sX, Sh, Sl, sS, CH, NPTS,
        nullptr, th, tl, nullptr, nullptr, nullptr, nullptr, x1, rd);
    // 9) out = x1 + relu(bn5(W5 @ t))
    mma_gemm<EP_FINAL, false><<<dim3(16, 8, 8), 256, SMEM_GEMM>>>(
        W5h, W5l, 0, th, tl, sX, CH, CH,
        out, nullptr, nullptr, g5, b5, m5, v5, x1, nullptr);
}

// round 11
// speedup vs baseline: 1.3254x; 1.1025x over previous
#include <cuda_runtime.h>
#include <cuda_fp16.h>
#include <cstdint>

#define EPS_BN 1e-5f
#define EPS_RENORM 1e-9f

#define BATCH 8
#define CH    1024
#define NPTS  2048
#define CQK   128

typedef __half fp16;

// ---------------- scratch (no allocations allowed) ----------------
__device__ float g_x1[BATCH * CH * NPTS];
__device__ float g_S [(size_t)BATCH * NPTS * NPTS];
__device__ float g_rd[BATCH * NPTS];
__device__ fp16 g_xh [BATCH * CH * NPTS], g_xl [BATCH * CH * NPTS];
__device__ fp16 g_x1h[BATCH * CH * NPTS], g_x1l[BATCH * CH * NPTS];
__device__ fp16 g_vh [BATCH * CH * NPTS], g_vl [BATCH * CH * NPTS];
__device__ fp16 g_th [BATCH * CH * NPTS], g_tl [BATCH * CH * NPTS];
__device__ fp16 g_qh [BATCH * NPTS * CQK], g_ql[BATCH * NPTS * CQK];
__device__ fp16 g_kh [BATCH * CQK * NPTS], g_kl[BATCH * CQK * NPTS];
__device__ fp16 g_Sh [(size_t)BATCH * NPTS * NPTS], g_Sl[(size_t)BATCH * NPTS * NPTS];
__device__ fp16 g_W1h[CH * CH],  g_W1l[CH * CH];
__device__ fp16 g_W2h[CH * CH],  g_W2l[CH * CH];
__device__ fp16 g_W5h[CH * CH],  g_W5l[CH * CH];
__device__ fp16 g_W3h[CQK * CH], g_W3l[CQK * CH];
__device__ fp16 g_W4h[CQK * CH], g_W4l[CQK * CH];

// ---------------- PTX helpers ----------------
__device__ __forceinline__ uint32_t s2u(const void* p) {
    uint32_t a;
    asm("{ .reg .u64 t; cvta.to.shared.u64 t, %1; cvt.u32.u64 %0, t; }"
        : "=r"(a) : "l"(p));
    return a;
}
__device__ __forceinline__ void cp16(uint32_t saddr, const void* g) {
    asm volatile("cp.async.cg.shared.global [%0], [%1], 16;"
                 :: "r"(saddr), "l"(g) : "memory");
}
#define CP_COMMIT() asm volatile("cp.async.commit_group;" ::: "memory")
#define CP_WAIT(n)  asm volatile("cp.async.wait_group %0;" :: "n"(n) : "memory")

__device__ __forceinline__ void ldsm4(uint32_t* r, uint32_t a) {
    asm volatile("ldmatrix.sync.aligned.m8n8.x4.shared.b16 {%0,%1,%2,%3}, [%4];"
                 : "=r"(r[0]), "=r"(r[1]), "=r"(r[2]), "=r"(r[3]) : "r"(a));
}
__device__ __forceinline__ void ldsm4t(uint32_t* r, uint32_t a) {
    asm volatile("ldmatrix.sync.aligned.m8n8.x4.trans.shared.b16 {%0,%1,%2,%3}, [%4];"
                 : "=r"(r[0]), "=r"(r[1]), "=r"(r[2]), "=r"(r[3]) : "r"(a));
}
__device__ __forceinline__ void mma16816(float* d, const uint32_t* a, const uint32_t* b) {
    asm volatile("mma.sync.aligned.m16n8k16.row.col.f32.f16.f16.f32 "
                 "{%0,%1,%2,%3}, {%4,%5,%6,%7}, {%8,%9}, {%0,%1,%2,%3};"
                 : "+f"(d[0]), "+f"(d[1]), "+f"(d[2]), "+f"(d[3])
                 : "r"(a[0]), "r"(a[1]), "r"(a[2]), "r"(a[3]), "r"(b[0]), "r"(b[1]));
}

// ---------------- split-fp16 MMA GEMM ----------------
// C[b] (M x N) = (Ah+Al)[b] @ (Bh+Bl)[b]
// NTERM==3: Ah·Bh + Ah·Bl + Al·Bh ; NTERM==2: Ah·Bh + Ah·Bl (A-lo dropped).
// A row-major [M][K], B row-major [K][N], N == NPTS.
// CTA 128x128, BK=32, 8 warps (warp tile 32x64), 3-stage cp.async, 2 CTAs/SM.
#define NSTG   3
#define STG_B  32768
#define SMEM_GEMM (NSTG * STG_B)      // 96 KiB dynamic -> 2 CTAs/SM

enum { EP_X1 = 0, EP_BNR = 1, EP_BNR_T = 2, EP_S = 3, EP_SUBDIV = 4, EP_FINAL = 5 };

template<int EPI, bool ABATCH, int NTERM>
__global__ void __launch_bounds__(256, 2)
mma_gemm(const fp16* __restrict__ Ahp, const fp16* __restrict__ Alp, size_t sA,
         const fp16* __restrict__ Bhp, const fp16* __restrict__ Blp, size_t sB,
         int M, int K,
         float* __restrict__ C32, fp16* __restrict__ Ch, fp16* __restrict__ Cl,
         const float* __restrict__ gg, const float* __restrict__ bb,
         const float* __restrict__ mm, const float* __restrict__ vv,
         const float* __restrict__ add, const float* __restrict__ rdiv)
{
    extern __shared__ __align__(256) char smraw[];
    const uint32_t smb = s2u(smraw);
    const int tid  = threadIdx.x;
    const int lane = tid & 31;
    const int wid  = tid >> 5;
    const int m_w  = (wid & 3) * 32;     // warp M offset
    const int n_w  = (wid >> 2) * 64;    // warp N offset
    const int bz   = blockIdx.z;
    const int rowStart = blockIdx.y * 128;
    const int colStart = blockIdx.x * 128;
    const int N = NPTS;

    const fp16* Ah_ = Ahp + (ABATCH ? (size_t)bz * sA : 0);
    const fp16* Al_ = Alp + (ABATCH ? (size_t)bz * sA : 0);
    const fp16* Bh_ = Bhp + (size_t)bz * sB;
    const fp16* Bl_ = Blp + (size_t)bz * sB;

    float acc[2][8][4];
#pragma unroll
    for (int i = 0; i < 2; i++)
#pragma unroll
        for (int j = 0; j < 8; j++)
#pragma unroll
            for (int r = 0; r < 4; r++) acc[i][j][r] = 0.f;

    // stage layout: Ah @0 (8K) | Al @8192 | Bh @16384 | Bl @24576
    auto loadStage = [&](int t) {
        const int s = t % NSTG;
        const uint32_t base = smb + (uint32_t)s * STG_B;
        const int k0 = t * 32;
#pragma unroll
        for (int i = 0; i < 2; i++) {            // A: 128 rows x 4 chunks (16B)
            int idx = tid + i * 256;
            int row = idx >> 2, c = idx & 3;
            uint32_t off = (uint32_t)(row * 64 + ((c ^ ((row >> 1) & 3)) << 4));
            size_t go = (size_t)(rowStart + row) * K + k0 + c * 8;
            cp16(base + off, Ah_ + go);
            if (NTERM == 3) cp16(base + 8192 + off, Al_ + go);
        }
#pragma unroll
        for (int i = 0; i < 2; i++) {            // B: 32 rows x 16 chunks
            int idx = tid + i * 256;
            int k = idx >> 4, cn = idx & 15;
            uint32_t off = (uint32_t)(k * 256 + ((cn ^ (k & 7)) << 4));
            size_t go = (size_t)(k0 + k) * N + colStart + cn * 8;
            cp16(base + 16384 + off, Bh_ + go);
            cp16(base + 24576 + off, Bl_ + go);
        }
        CP_COMMIT();
    };

    const int T = K / 32;
    const int P = (T < 2) ? T : 2;
    for (int t = 0; t < P; t++) loadStage(t);

    for (int t = 0; t < T; t++) {
        if (t + 1 < T) { CP_WAIT(1); } else { CP_WAIT(0); }
        __syncthreads();
        // NOTE: no bottom barrier needed — this top barrier at tile t also
        // guarantees all warps finished reading stage (t-1), which is the
        // stage loadStage(t+2) overwrites.
        if (t + 2 < T) loadStage(t + 2);

        const uint32_t Ab = smb + (uint32_t)(t % NSTG) * STG_B;
#pragma unroll
        for (int ks = 0; ks < 2; ks++) {
            uint32_t ah[2][4], al[2][4];
#pragma unroll
            for (int i = 0; i < 2; i++) {
                int row = m_w + i * 16 + (lane & 15);
                int c = ks * 2 + (lane >> 4);
                uint32_t off = (uint32_t)(row * 64 + ((c ^ ((row >> 1) & 3)) << 4));
                ldsm4(ah[i], Ab + off);
                if (NTERM == 3) ldsm4(al[i], Ab + 8192 + off);
            }
#pragma unroll
            for (int p = 0; p < 4; p++) {
                int g = lane >> 3, j8 = lane & 7;
                int k = ks * 16 + (g & 1) * 8 + j8;
                int cn = (n_w >> 3) + p * 2 + (g >> 1);
                uint32_t off = (uint32_t)(k * 256 + ((cn ^ (k & 7)) << 4));
                uint32_t bh[4], bl[4];
                ldsm4t(bh, Ab + 16384 + off);
                ldsm4t(bl, Ab + 24576 + off);
#pragma unroll
                for (int i = 0; i < 2; i++) {
                    mma16816(acc[i][2 * p],     ah[i], bh);
                    mma16816(acc[i][2 * p],     ah[i], bl);
                    if (NTERM == 3) mma16816(acc[i][2 * p], al[i], bh);
                    mma16816(acc[i][2 * p + 1], ah[i], bh + 2);
                    mma16816(acc[i][2 * p + 1], ah[i], bl + 2);
                    if (NTERM == 3) mma16816(acc[i][2 * p + 1], al[i], bh + 2);
                }
            }
        }
    }

    // ---------------- epilogue ----------------
    __shared__ float s_scl[128], s_off[128];
    if (EPI == EP_X1 || EPI == EP_BNR || EPI == EP_BNR_T || EPI == EP_FINAL) {
        __syncthreads();              // mainloop fully drained before BN staging
        if (tid < 128) {
            int rg = rowStart + tid;
            float inv = rsqrtf(vv[rg] + EPS_BN);
            float sc = gg[rg] * inv;
            s_scl[tid] = sc;
            s_off[tid] = bb[rg] - mm[rg] * sc;
        }
        __syncthreads();
    }

    const size_t sC = (size_t)M * N;
#pragma unroll
    for (int i = 0; i < 2; i++) {
#pragma unroll
        for (int j = 0; j < 8; j++) {
#pragma unroll
            for (int hseg = 0; hseg < 2; hseg++) {
                const int rl = m_w + i * 16 + (lane >> 2) + hseg * 8;
                const int cl = n_w + j * 8 + (lane & 3) * 2;
                const float y0 = acc[i][j][hseg * 2];
                const float y1 = acc[i][j][hseg * 2 + 1];
                const int rg = rowStart + rl;
                const int cg = colStart + cl;
                const size_t o = (size_t)bz * sC + (size_t)rg * N + cg;

                if (EPI == EP_S) {
                    float2 v2; v2.x = y0; v2.y = y1;
                    *(float2*)(C32 + o) = v2;
                } else if (EPI == EP_SUBDIV) {
                    float2 ad  = *(const float2*)(add + o);
                    float2 rdv = *(const float2*)(rdiv + (size_t)bz * N + cg);
                    float z0 = ad.x - y0 * rdv.x;
                    float z1 = ad.y - y1 * rdv.y;
                    fp16 h0 = __float2half_rn(z0), h1 = __float2half_rn(z1);
                    __half2 hh = __halves2half2(h0, h1);
                    __half2 ll = __halves2half2(
                        __float2half_rn(z0 - __half2float(h0)),
                        __float2half_rn(z1 - __half2float(h1)));
                    *(__half2*)(Ch + o) = hh;
                    *(__half2*)(Cl + o) = ll;
                } else {
                    const float sc = s_scl[rl], of = s_off[rl];
                    float z0 = fmaxf(y0 * sc + of, 0.f);
                    float z1 = fmaxf(y1 * sc + of, 0.f);
                    if (EPI == EP_BNR_T) {
                        size_t ot = (size_t)bz * ((size_t)NPTS * CQK);
                        size_t o0 = ot + (size_t)cg * CQK + rg;
                        size_t o1 = o0 + CQK;
                        fp16 h0 = __float2half_rn(z0), h1 = __float2half_rn(z1);
                        Ch[o0] = h0; Cl[o0] = __float2half_rn(z0 - __half2float(h0));
                        Ch[o1] = h1; Cl[o1] = __float2half_rn(z1 - __half2float(h1));
                    } else if (EPI == EP_FINAL) {
                        float2 ad = *(const float2*)(add + o);
                        float2 v2; v2.x = ad.x + z0; v2.y = ad.y + z1;
                        *(float2*)(C32 + o) = v2;
                    } else {
                        if (EPI == EP_X1) {
                            float2 v2; v2.x = z0; v2.y = z1;
                            *(float2*)(C32 + o) = v2;
                        }
                        fp16 h0 = __float2half_rn(z0), h1 = __float2half_rn(z1);
                        __half2 hh = __halves2half2(h0, h1);
                        __half2 ll = __halves2half2(
                            __float2half_rn(z0 - __half2float(h0)),
                            __float2half_rn(z1 - __half2float(h1)));
                        *(__half2*)(Ch + o) = hh;
                        *(__half2*)(Cl + o) = ll;
                    }
                }
            }
        }
    }
}

// ---------------- merged fp32 -> fp16 hi/lo split of all inputs ----------------
#define NX (BATCH * CH * NPTS)
#define NW (CH * CH)
#define NQW (CQK * CH)

__global__ void __launch_bounds__(256)
split_all(const float* __restrict__ x,  fp16* __restrict__ xh,  fp16* __restrict__ xl,
          const float* __restrict__ W1, fp16* __restrict__ W1h, fp16* __restrict__ W1l,
          const float* __restrict__ W2, fp16* __restrict__ W2h, fp16* __restrict__ W2l,
          const float* __restrict__ W3, fp16* __restrict__ W3h, fp16* __restrict__ W3l,
          const float* __restrict__ W4, fp16* __restrict__ W4h, fp16* __restrict__ W4l,
          const float* __restrict__ W5, fp16* __restrict__ W5h, fp16* __restrict__ W5l)
{
    size_t i = (size_t)blockIdx.x * 256 + threadIdx.x;
    const float* in; fp16 *oh, *ol; size_t li;
    if (i < NX)                       { in = x;  oh = xh;  ol = xl;  li = i; }
    else if (i < NX + NW)             { in = W1; oh = W1h; ol = W1l; li = i - NX; }
    else if (i < NX + 2 * NW)         { in = W2; oh = W2h; ol = W2l; li = i - NX - NW; }
    else if (i < NX + 2 * NW + NQW)   { in = W3; oh = W3h; ol = W3l; li = i - NX - 2 * NW; }
    else if (i < NX + 2 * NW + 2*NQW) { in = W4; oh = W4h; ol = W4l; li = i - NX - 2 * NW - NQW; }
    else                              { in = W5; oh = W5h; ol = W5l; li = i - NX - 2 * NW - 2 * NQW; }
    float v = in[li];
    fp16 h = __float2half_rn(v);
    oh[li] = h;
    ol[li] = __float2half_rn(v - __half2float(h));
}

// ---------------- row softmax: fp32 in, fp16 hi/lo out ----------------
__global__ void __launch_bounds__(256)
softmax_kernel(const float* __restrict__ S, fp16* __restrict__ Sh, fp16* __restrict__ Sl)
{
    __shared__ float buf[NPTS];
    __shared__ float red[8];
    const float* p = S + (size_t)blockIdx.x * NPTS;
    fp16* ph = Sh + (size_t)blockIdx.x * NPTS;
    fp16* pl = Sl + (size_t)blockIdx.x * NPTS;
    int t = threadIdx.x;

    float mx = -3.402823466e38f;
    for (int i = t; i < NPTS; i += 256) { float v = p[i]; buf[i] = v; mx = fmaxf(mx, v); }
#pragma unroll
    for (int o = 16; o > 0; o >>= 1) mx = fmaxf(mx, __shfl_xor_sync(0xffffffffu, mx, o));
    if ((t & 31) == 0) red[t >> 5] = mx;
    __syncthreads();
    float bm = red[0];
#pragma unroll
    for (int i = 1; i < 8; i++) bm = fmaxf(bm, red[i]);
    __syncthreads();

    float sum = 0.f;
    for (int i = t; i < NPTS; i += 256) { float e = __expf(buf[i] - bm); buf[i] = e; sum += e; }
#pragma unroll
    for (int o = 16; o > 0; o >>= 1) sum += __shfl_xor_sync(0xffffffffu, sum, o);
    if ((t & 31) == 0) red[t >> 5] = sum;
    __syncthreads();
    float bs = 0.f;
#pragma unroll
    for (int i = 0; i < 8; i++) bs += red[i];
    float inv = 1.0f / bs;
    for (int i = t; i < NPTS; i += 256) {
        float v = buf[i] * inv;
        fp16 h = __float2half_rn(v);
        ph[i] = h;
        pl[i] = __float2half_rn(v - __half2float(h));
    }
}

// ---------------- column sums -> 1/(eps+colsum) ----------------
__global__ void __launch_bounds__(256)
colsum_kernel(const fp16* __restrict__ Sh, const fp16* __restrict__ Sl,
              float* __restrict__ rdiv)
{
    int idx = blockIdx.x * 256 + threadIdx.x;
    int b = idx / NPTS, m = idx - b * NPTS;
    const fp16* ph = Sh + (size_t)b * NPTS * NPTS + m;
    const fp16* pl = Sl + (size_t)b * NPTS * NPTS + m;
    float s[4] = {0.f, 0.f, 0.f, 0.f};
    for (int n = 0; n < NPTS; n += 4) {
#pragma unroll
        for (int u = 0; u < 4; u++) {
            size_t o = (size_t)(n + u) * NPTS;
            s[u] += __half2float(ph[o]) + __half2float(pl[o]);
        }
    }
    rdiv[idx] = 1.0f / (EPS_RENORM + ((s[0] + s[1]) + (s[2] + s[3])));
}

// ---------------- launch ----------------
extern "C" void kernel_launch(void* const* d_in, const int* in_sizes, int n_in,
                              void* d_out, int out_size)
{
    (void)in_sizes; (void)n_in; (void)out_size;
    const float* x  = (const float*)d_in[0];
    const float *W1 = (const float*)d_in[1],  *g1 = (const float*)d_in[2],
                *b1 = (const float*)d_in[3],  *m1 = (const float*)d_in[4],
                *v1 = (const float*)d_in[5];
    const float *W2 = (const float*)d_in[6],  *g2 = (const float*)d_in[7],
                *b2 = (const float*)d_in[8],  *m2 = (const float*)d_in[9],
                *v2 = (const float*)d_in[10];
    const float *W3 = (const float*)d_in[11], *g3 = (const float*)d_in[12],
                *b3 = (const float*)d_in[13], *m3 = (const float*)d_in[14],
                *v3 = (const float*)d_in[15];
    const float *W4 = (const float*)d_in[16], *g4 = (const float*)d_in[17],
                *b4 = (const float*)d_in[18], *m4 = (const float*)d_in[19],
                *v4 = (const float*)d_in[20];
    const float *W5 = (const float*)d_in[21], *g5 = (const float*)d_in[22],
                *b5 = (const float*)d_in[23], *m5 = (const float*)d_in[24],
                *v5 = (const float*)d_in[25];
    float* out = (float*)d_out;

    float *x1, *S, *rd;
    fp16 *xh, *xl, *x1h, *x1l, *vh, *vl, *th, *tl, *qh, *ql, *kh, *kl, *Sh, *Sl;
    fp16 *W1h, *W1l, *W2h, *W2l, *W3h, *W3l, *W4h, *W4l, *W5h, *W5l;
    cudaGetSymbolAddress((void**)&x1, g_x1);
    cudaGetSymbolAddress((void**)&S,  g_S);
    cudaGetSymbolAddress((void**)&rd, g_rd);
    cudaGetSymbolAddress((void**)&xh, g_xh);   cudaGetSymbolAddress((void**)&xl, g_xl);
    cudaGetSymbolAddress((void**)&x1h, g_x1h); cudaGetSymbolAddress((void**)&x1l, g_x1l);
    cudaGetSymbolAddress((void**)&vh, g_vh);   cudaGetSymbolAddress((void**)&vl, g_vl);
    cudaGetSymbolAddress((void**)&th, g_th);   cudaGetSymbolAddress((void**)&tl, g_tl);
    cudaGetSymbolAddress((void**)&qh, g_qh);   cudaGetSymbolAddress((void**)&ql, g_ql);
    cudaGetSymbolAddress((void**)&kh, g_kh);   cudaGetSymbolAddress((void**)&kl, g_kl);
    cudaGetSymbolAddress((void**)&Sh, g_Sh);   cudaGetSymbolAddress((void**)&Sl, g_Sl);
    cudaGetSymbolAddress((void**)&W1h, g_W1h); cudaGetSymbolAddress((void**)&W1l, g_W1l);
    cudaGetSymbolAddress((void**)&W2h, g_W2h); cudaGetSymbolAddress((void**)&W2l, g_W2l);
    cudaGetSymbolAddress((void**)&W3h, g_W3h); cudaGetSymbolAddress((void**)&W3l, g_W3l);
    cudaGetSymbolAddress((void**)&W4h, g_W4h); cudaGetSymbolAddress((void**)&W4l, g_W4l);
    cudaGetSymbolAddress((void**)&W5h, g_W5h); cudaGetSymbolAddress((void**)&W5l, g_W5l);

    cudaFuncSetAttribute(mma_gemm<EP_X1, false, 3>,    cudaFuncAttributeMaxDynamicSharedMemorySize, SMEM_GEMM);
    cudaFuncSetAttribute(mma_gemm<EP_BNR, false, 3>,   cudaFuncAttributeMaxDynamicSharedMemorySize, SMEM_GEMM);
    cudaFuncSetAttribute(mma_gemm<EP_BNR_T, false, 3>, cudaFuncAttributeMaxDynamicSharedMemorySize, SMEM_GEMM);
    cudaFuncSetAttribute(mma_gemm<EP_S, true, 3>,      cudaFuncAttributeMaxDynamicSharedMemorySize, SMEM_GEMM);
    cudaFuncSetAttribute(mma_gemm<EP_SUBDIV, true, 2>, cudaFuncAttributeMaxDynamicSharedMemorySize, SMEM_GEMM);
    cudaFuncSetAttribute(mma_gemm<EP_FINAL, false, 3>, cudaFuncAttributeMaxDynamicSharedMemorySize, SMEM_GEMM);

    const size_t sX  = (size_t)CH * NPTS;
    const size_t sQT = (size_t)NPTS * CQK;
    const size_t sK  = (size_t)CQK * NPTS;
    const size_t sS  = (size_t)NPTS * NPTS;

    // 0) merged hi/lo split of x and all weights (1 launch)
    const int splitTotal = NX + 2 * NW + 2 * NQW + NW;
    split_all<<<splitTotal / 256, 256>>>(x, xh, xl, W1, W1h, W1l, W2, W2h, W2l,
                                         W3, W3h, W3l, W4, W4h, W4l, W5, W5h, W5l);
    // 1) x1 = relu(bn1(W1 @ x))
    mma_gemm<EP_X1, false, 3><<<dim3(16, 8, 8), 256, SMEM_GEMM>>>(
        W1h, W1l, 0, xh, xl, sX, CH, CH,
        x1, x1h, x1l, g1, b1, m1, v1, nullptr, nullptr);
    // 2) v = relu(bn2(W2 @ x1))
    mma_gemm<EP_BNR, false, 3><<<dim3(16, 8, 8), 256, SMEM_GEMM>>>(
        W2h, W2l, 0, x1h, x1l, sX, CH, CH,
        nullptr, vh, vl, g2, b2, m2, v2, nullptr, nullptr);
    // 3) q (stored transposed q^T [n][c])
    mma_gemm<EP_BNR_T, false, 3><<<dim3(16, 1, 8), 256, SMEM_GEMM>>>(
        W3h, W3l, 0, x1h, x1l, sX, CQK, CH,
        nullptr, qh, ql, g3, b3, m3, v3, nullptr, nullptr);
    // 4) k
    mma_gemm<EP_BNR, false, 3><<<dim3(16, 1, 8), 256, SMEM_GEMM>>>(
        W4h, W4l, 0, x1h, x1l, sX, CQK, CH,
        nullptr, kh, kl, g4, b4, m4, v4, nullptr, nullptr);
    // 5) scores S[n][m] = sum_c qT[n][c] k[c][m]
    mma_gemm<EP_S, true, 3><<<dim3(16, 16, 8), 256, SMEM_GEMM>>>(
        qh, ql, sQT, kh, kl, sK, NPTS, CQK,
        S, nullptr, nullptr, nullptr, nullptr, nullptr, nullptr, nullptr, nullptr);
    // 6) row softmax -> fp16 hi/lo
    softmax_kernel<<<BATCH * NPTS, 256>>>(S, Sh, Sl);
    // 7) renorm divisor
    colsum_kernel<<<(BATCH * NPTS) / 256, 256>>>(Sh, Sl, rd);
    // 8) t = x1 - (v @ S) * rdiv[col]   (2-term: v-lo dropped, v,S >= 0)
    mma_gemm<EP_SUBDIV, true, 2><<<dim3(16, 8, 8), 256, SMEM_GEMM>>>(
        vh, vl, sX, Sh, Sl, sS, CH, NPTS,
        nullptr, th, tl, nullptr, nullptr, nullptr, nullptr, x1, rd);
    // 9) out = x1 + relu(bn5(W5 @ t))
    mma_gemm<EP_FINAL, false, 3><<<dim3(16, 8, 8), 256, SMEM_GEMM>>>(
        W5h, W5l, 0, th, tl, sX, CH, CH,
        out, nullptr, nullptr, g5, b5, m5, v5, x1, nullptr);
}

// round 12
// speedup vs baseline: 1.7042x; 1.2858x over previous
#include <cuda_runtime.h>
#include <cuda_fp16.h>
#include <cstdint>

#define EPS_BN 1e-5f
#define EPS_RENORM 1e-9f

#define BATCH 8
#define CH    1024
#define NPTS  2048
#define CQK   128

typedef __half fp16;

// ---------------- scratch (no allocations allowed) ----------------
__device__ float g_x1[BATCH * CH * NPTS];
__device__ float g_S [(size_t)BATCH * NPTS * NPTS];
__device__ float g_rd[BATCH * NPTS];
__device__ fp16 g_xh [BATCH * CH * NPTS], g_xl [BATCH * CH * NPTS];
__device__ fp16 g_x1h[BATCH * CH * NPTS], g_x1l[BATCH * CH * NPTS];
__device__ fp16 g_vh [BATCH * CH * NPTS], g_vl [BATCH * CH * NPTS];
__device__ fp16 g_th [BATCH * CH * NPTS], g_tl [BATCH * CH * NPTS];
__device__ fp16 g_qh [BATCH * NPTS * CQK], g_ql[BATCH * NPTS * CQK];
__device__ fp16 g_kh [BATCH * CQK * NPTS], g_kl[BATCH * CQK * NPTS];
__device__ fp16 g_Sh [(size_t)BATCH * NPTS * NPTS];
__device__ fp16 g_W1h[CH * CH],  g_W1l[CH * CH];
__device__ fp16 g_W2h[CH * CH],  g_W2l[CH * CH];
__device__ fp16 g_W5h[CH * CH],  g_W5l[CH * CH];
__device__ fp16 g_W3h[CQK * CH], g_W3l[CQK * CH];
__device__ fp16 g_W4h[CQK * CH], g_W4l[CQK * CH];

// ---------------- PTX helpers ----------------
__device__ __forceinline__ uint32_t s2u(const void* p) {
    uint32_t a;
    asm("{ .reg .u64 t; cvta.to.shared.u64 t, %1; cvt.u32.u64 %0, t; }"
        : "=r"(a) : "l"(p));
    return a;
}
__device__ __forceinline__ void cp16(uint32_t saddr, const void* g) {
    asm volatile("cp.async.cg.shared.global [%0], [%1], 16;"
                 :: "r"(saddr), "l"(g) : "memory");
}
#define CP_COMMIT() asm volatile("cp.async.commit_group;" ::: "memory")
#define CP_WAIT(n)  asm volatile("cp.async.wait_group %0;" :: "n"(n) : "memory")

__device__ __forceinline__ void ldsm4(uint32_t* r, uint32_t a) {
    asm volatile("ldmatrix.sync.aligned.m8n8.x4.shared.b16 {%0,%1,%2,%3}, [%4];"
                 : "=r"(r[0]), "=r"(r[1]), "=r"(r[2]), "=r"(r[3]) : "r"(a));
}
__device__ __forceinline__ void ldsm4t(uint32_t* r, uint32_t a) {
    asm volatile("ldmatrix.sync.aligned.m8n8.x4.trans.shared.b16 {%0,%1,%2,%3}, [%4];"
                 : "=r"(r[0]), "=r"(r[1]), "=r"(r[2]), "=r"(r[3]) : "r"(a));
}
__device__ __forceinline__ void mma16816(float* d, const uint32_t* a, const uint32_t* b) {
    asm volatile("mma.sync.aligned.m16n8k16.row.col.f32.f16.f16.f32 "
                 "{%0,%1,%2,%3}, {%4,%5,%6,%7}, {%8,%9}, {%0,%1,%2,%3};"
                 : "+f"(d[0]), "+f"(d[1]), "+f"(d[2]), "+f"(d[3])
                 : "r"(a[0]), "r"(a[1]), "r"(a[2]), "r"(a[3]), "r"(b[0]), "r"(b[1]));
}

// ---------------- split-fp16 MMA GEMM ----------------
// C[b] (M x N) = (Ah+Al)[b] @ (Bh+Bl)[b]
// NTERM==3: Ah·Bh + Ah·Bl + Al·Bh
// NTERM==2: Ah·Bh + Ah·Bl          (A-lo dropped)
// NTERM==1: Ah·Bh                  (both lo dropped)
// A row-major [M][K], B row-major [K][N], N == NPTS.
// CTA 128x128, BK=32, 8 warps (warp tile 32x64), 3-stage cp.async, 2 CTAs/SM.
#define NSTG   3
#define STG_B  32768
#define SMEM_GEMM (NSTG * STG_B)      // 96 KiB dynamic -> 2 CTAs/SM

enum { EP_X1 = 0, EP_BNR = 1, EP_BNR_T = 2, EP_S = 3, EP_SUBDIV = 4, EP_FINAL = 5 };

template<int EPI, bool ABATCH, int NTERM>
__global__ void __launch_bounds__(256, 2)
mma_gemm(const fp16* __restrict__ Ahp, const fp16* __restrict__ Alp, size_t sA,
         const fp16* __restrict__ Bhp, const fp16* __restrict__ Blp, size_t sB,
         int M, int K,
         float* __restrict__ C32, fp16* __restrict__ Ch, fp16* __restrict__ Cl,
         const float* __restrict__ gg, const float* __restrict__ bb,
         const float* __restrict__ mm, const float* __restrict__ vv,
         const float* __restrict__ add, const float* __restrict__ rdiv)
{
    extern __shared__ __align__(256) char smraw[];
    const uint32_t smb = s2u(smraw);
    const int tid  = threadIdx.x;
    const int lane = tid & 31;
    const int wid  = tid >> 5;
    const int m_w  = (wid & 3) * 32;     // warp M offset
    const int n_w  = (wid >> 2) * 64;    // warp N offset
    const int bz   = blockIdx.z;
    const int rowStart = blockIdx.y * 128;
    const int colStart = blockIdx.x * 128;
    const int N = NPTS;

    const fp16* Ah_ = Ahp + (ABATCH ? (size_t)bz * sA : 0);
    const fp16* Al_ = Alp + (ABATCH ? (size_t)bz * sA : 0);
    const fp16* Bh_ = Bhp + (size_t)bz * sB;
    const fp16* Bl_ = Blp + (size_t)bz * sB;

    float acc[2][8][4];
#pragma unroll
    for (int i = 0; i < 2; i++)
#pragma unroll
        for (int j = 0; j < 8; j++)
#pragma unroll
            for (int r = 0; r < 4; r++) acc[i][j][r] = 0.f;

    // stage layout: Ah @0 (8K) | Al @8192 | Bh @16384 | Bl @24576
    auto loadStage = [&](int t) {
        const int s = t % NSTG;
        const uint32_t base = smb + (uint32_t)s * STG_B;
        const int k0 = t * 32;
#pragma unroll
        for (int i = 0; i < 2; i++) {            // A: 128 rows x 4 chunks (16B)
            int idx = tid + i * 256;
            int row = idx >> 2, c = idx & 3;
            uint32_t off = (uint32_t)(row * 64 + ((c ^ ((row >> 1) & 3)) << 4));
            size_t go = (size_t)(rowStart + row) * K + k0 + c * 8;
            cp16(base + off, Ah_ + go);
            if (NTERM >= 3) cp16(base + 8192 + off, Al_ + go);
        }
#pragma unroll
        for (int i = 0; i < 2; i++) {            // B: 32 rows x 16 chunks
            int idx = tid + i * 256;
            int k = idx >> 4, cn = idx & 15;
            uint32_t off = (uint32_t)(k * 256 + ((cn ^ (k & 7)) << 4));
            size_t go = (size_t)(k0 + k) * N + colStart + cn * 8;
            cp16(base + 16384 + off, Bh_ + go);
            if (NTERM >= 2) cp16(base + 24576 + off, Bl_ + go);
        }
        CP_COMMIT();
    };

    const int T = K / 32;
    const int P = (T < 2) ? T : 2;
    for (int t = 0; t < P; t++) loadStage(t);

    for (int t = 0; t < T; t++) {
        if (t + 1 < T) { CP_WAIT(1); } else { CP_WAIT(0); }
        __syncthreads();
        // top barrier of tile t also protects stage (t-1) from the overwrite
        // issued below (loadStage(t+2) targets stage (t+2)%3 == (t-1)%3).
        if (t + 2 < T) loadStage(t + 2);

        const uint32_t Ab = smb + (uint32_t)(t % NSTG) * STG_B;
#pragma unroll
        for (int ks = 0; ks < 2; ks++) {
            uint32_t ah[2][4], al[2][4];
#pragma unroll
            for (int i = 0; i < 2; i++) {
                int row = m_w + i * 16 + (lane & 15);
                int c = ks * 2 + (lane >> 4);
                uint32_t off = (uint32_t)(row * 64 + ((c ^ ((row >> 1) & 3)) << 4));
                ldsm4(ah[i], Ab + off);
                if (NTERM >= 3) ldsm4(al[i], Ab + 8192 + off);
            }
#pragma unroll
            for (int p = 0; p < 4; p++) {
                int g = lane >> 3, j8 = lane & 7;
                int k = ks * 16 + (g & 1) * 8 + j8;
                int cn = (n_w >> 3) + p * 2 + (g >> 1);
                uint32_t off = (uint32_t)(k * 256 + ((cn ^ (k & 7)) << 4));
                uint32_t bh[4], bl[4];
                ldsm4t(bh, Ab + 16384 + off);
                if (NTERM >= 2) ldsm4t(bl, Ab + 24576 + off);
#pragma unroll
                for (int i = 0; i < 2; i++) {
                    mma16816(acc[i][2 * p], ah[i], bh);
                    if (NTERM >= 2) mma16816(acc[i][2 * p], ah[i], bl);
                    if (NTERM >= 3) mma16816(acc[i][2 * p], al[i], bh);
                    mma16816(acc[i][2 * p + 1], ah[i], bh + 2);
                    if (NTERM >= 2) mma16816(acc[i][2 * p + 1], ah[i], bl + 2);
                    if (NTERM >= 3) mma16816(acc[i][2 * p + 1], al[i], bh + 2);
                }
            }
        }
    }

    // ---------------- epilogue ----------------
    __shared__ float s_scl[128], s_off[128];
    if (EPI == EP_X1 || EPI == EP_BNR || EPI == EP_BNR_T || EPI == EP_FINAL) {
        __syncthreads();
        if (tid < 128) {
            int rg = rowStart + tid;
            float inv = rsqrtf(vv[rg] + EPS_BN);
            float sc = gg[rg] * inv;
            s_scl[tid] = sc;
            s_off[tid] = bb[rg] - mm[rg] * sc;
        }
        __syncthreads();
    }

    const size_t sC = (size_t)M * N;
#pragma unroll
    for (int i = 0; i < 2; i++) {
#pragma unroll
        for (int j = 0; j < 8; j++) {
#pragma unroll
            for (int hseg = 0; hseg < 2; hseg++) {
                const int rl = m_w + i * 16 + (lane >> 2) + hseg * 8;
                const int cl = n_w + j * 8 + (lane & 3) * 2;
                const float y0 = acc[i][j][hseg * 2];
                const float y1 = acc[i][j][hseg * 2 + 1];
                const int rg = rowStart + rl;
                const int cg = colStart + cl;
                const size_t o = (size_t)bz * sC + (size_t)rg * N + cg;

                if (EPI == EP_S) {
                    float2 v2; v2.x = y0; v2.y = y1;
                    *(float2*)(C32 + o) = v2;
                } else if (EPI == EP_SUBDIV) {
                    float2 ad  = *(const float2*)(add + o);
                    float2 rdv = *(const float2*)(rdiv + (size_t)bz * N + cg);
                    float z0 = ad.x - y0 * rdv.x;
                    float z1 = ad.y - y1 * rdv.y;
                    fp16 h0 = __float2half_rn(z0), h1 = __float2half_rn(z1);
                    __half2 hh = __halves2half2(h0, h1);
                    __half2 ll = __halves2half2(
                        __float2half_rn(z0 - __half2float(h0)),
                        __float2half_rn(z1 - __half2float(h1)));
                    *(__half2*)(Ch + o) = hh;
                    *(__half2*)(Cl + o) = ll;
                } else {
                    const float sc = s_scl[rl], of = s_off[rl];
                    float z0 = fmaxf(y0 * sc + of, 0.f);
                    float z1 = fmaxf(y1 * sc + of, 0.f);
                    if (EPI == EP_BNR_T) {
                        size_t ot = (size_t)bz * ((size_t)NPTS * CQK);
                        size_t o0 = ot + (size_t)cg * CQK + rg;
                        size_t o1 = o0 + CQK;
                        fp16 h0 = __float2half_rn(z0), h1 = __float2half_rn(z1);
                        Ch[o0] = h0; Cl[o0] = __float2half_rn(z0 - __half2float(h0));
                        Ch[o1] = h1; Cl[o1] = __float2half_rn(z1 - __half2float(h1));
                    } else if (EPI == EP_FINAL) {
                        float2 ad = *(const float2*)(add + o);
                        float2 v2; v2.x = ad.x + z0; v2.y = ad.y + z1;
                        *(float2*)(C32 + o) = v2;
                    } else {
                        if (EPI == EP_X1) {
                            float2 v2; v2.x = z0; v2.y = z1;
                            *(float2*)(C32 + o) = v2;
                        }
                        fp16 h0 = __float2half_rn(z0), h1 = __float2half_rn(z1);
                        __half2 hh = __halves2half2(h0, h1);
                        __half2 ll = __halves2half2(
                            __float2half_rn(z0 - __half2float(h0)),
                            __float2half_rn(z1 - __half2float(h1)));
                        *(__half2*)(Ch + o) = hh;
                        *(__half2*)(Cl + o) = ll;
                    }
                }
            }
        }
    }
}

// ---------------- merged fp32 -> fp16 hi/lo split of all inputs ----------------
#define NX (BATCH * CH * NPTS)
#define NW (CH * CH)
#define NQW (CQK * CH)

__global__ void __launch_bounds__(256)
split_all(const float* __restrict__ x,  fp16* __restrict__ xh,  fp16* __restrict__ xl,
          const float* __restrict__ W1, fp16* __restrict__ W1h, fp16* __restrict__ W1l,
          const float* __restrict__ W2, fp16* __restrict__ W2h, fp16* __restrict__ W2l,
          const float* __restrict__ W3, fp16* __restrict__ W3h, fp16* __restrict__ W3l,
          const float* __restrict__ W4, fp16* __restrict__ W4h, fp16* __restrict__ W4l,
          const float* __restrict__ W5, fp16* __restrict__ W5h, fp16* __restrict__ W5l)
{
    size_t i = (size_t)blockIdx.x * 256 + threadIdx.x;
    const float* in; fp16 *oh, *ol; size_t li;
    if (i < NX)                       { in = x;  oh = xh;  ol = xl;  li = i; }
    else if (i < NX + NW)             { in = W1; oh = W1h; ol = W1l; li = i - NX; }
    else if (i < NX + 2 * NW)         { in = W2; oh = W2h; ol = W2l; li = i - NX - NW; }
    else if (i < NX + 2 * NW + NQW)   { in = W3; oh = W3h; ol = W3l; li = i - NX - 2 * NW; }
    else if (i < NX + 2 * NW + 2*NQW) { in = W4; oh = W4h; ol = W4l; li = i - NX - 2 * NW - NQW; }
    else                              { in = W5; oh = W5h; ol = W5l; li = i - NX - 2 * NW - 2 * NQW; }
    float v = in[li];
    fp16 h = __float2half_rn(v);
    oh[li] = h;
    ol[li] = __float2half_rn(v - __half2float(h));
}

// ---------------- row softmax: fp32 in, fp16 (hi only) out ----------------
__global__ void __launch_bounds__(256)
softmax_kernel(const float* __restrict__ S, fp16* __restrict__ Sh)
{
    __shared__ float buf[NPTS];
    __shared__ float red[8];
    const float* p = S + (size_t)blockIdx.x * NPTS;
    fp16* ph = Sh + (size_t)blockIdx.x * NPTS;
    int t = threadIdx.x;

    float mx = -3.402823466e38f;
    for (int i = t; i < NPTS; i += 256) { float v = p[i]; buf[i] = v; mx = fmaxf(mx, v); }
#pragma unroll
    for (int o = 16; o > 0; o >>= 1) mx = fmaxf(mx, __shfl_xor_sync(0xffffffffu, mx, o));
    if ((t & 31) == 0) red[t >> 5] = mx;
    __syncthreads();
    float bm = red[0];
#pragma unroll
    for (int i = 1; i < 8; i++) bm = fmaxf(bm, red[i]);
    __syncthreads();

    float sum = 0.f;
    for (int i = t; i < NPTS; i += 256) { float e = __expf(buf[i] - bm); buf[i] = e; sum += e; }
#pragma unroll
    for (int o = 16; o > 0; o >>= 1) sum += __shfl_xor_sync(0xffffffffu, sum, o);
    if ((t & 31) == 0) red[t >> 5] = sum;
    __syncthreads();
    float bs = 0.f;
#pragma unroll
    for (int i = 0; i < 8; i++) bs += red[i];
    float inv = 1.0f / bs;
    for (int i = t; i < NPTS; i += 256)
        ph[i] = __float2half_rn(buf[i] * inv);
}

// ---------------- column sums of Sh -> 1/(eps+colsum) ----------------
__global__ void __launch_bounds__(256)
colsum_kernel(const fp16* __restrict__ Sh, float* __restrict__ rdiv)
{
    int idx = blockIdx.x * 256 + threadIdx.x;
    int b = idx / NPTS, m = idx - b * NPTS;
    const fp16* ph = Sh + (size_t)b * NPTS * NPTS + m;
    float s[4] = {0.f, 0.f, 0.f, 0.f};
    for (int n = 0; n < NPTS; n += 4) {
#pragma unroll
        for (int u = 0; u < 4; u++)
            s[u] += __half2float(ph[(size_t)(n + u) * NPTS]);
    }
    rdiv[idx] = 1.0f / (EPS_RENORM + ((s[0] + s[1]) + (s[2] + s[3])));
}

// ---------------- launch ----------------
extern "C" void kernel_launch(void* const* d_in, const int* in_sizes, int n_in,
                              void* d_out, int out_size)
{
    (void)in_sizes; (void)n_in; (void)out_size;
    const float* x  = (const float*)d_in[0];
    const float *W1 = (const float*)d_in[1],  *g1 = (const float*)d_in[2],
                *b1 = (const float*)d_in[3],  *m1 = (const float*)d_in[4],
                *v1 = (const float*)d_in[5];
    const float *W2 = (const float*)d_in[6],  *g2 = (const float*)d_in[7],
                *b2 = (const float*)d_in[8],  *m2 = (const float*)d_in[9],
                *v2 = (const float*)d_in[10];
    const float *W3 = (const float*)d_in[11], *g3 = (const float*)d_in[12],
                *b3 = (const float*)d_in[13], *m3 = (const float*)d_in[14],
                *v3 = (const float*)d_in[15];
    const float *W4 = (const float*)d_in[16], *g4 = (const float*)d_in[17],
                *b4 = (const float*)d_in[18], *m4 = (const float*)d_in[19],
                *v4 = (const float*)d_in[20];
    const float *W5 = (const float*)d_in[21], *g5 = (const float*)d_in[22],
                *b5 = (const float*)d_in[23], *m5 = (const float*)d_in[24],
                *v5 = (const float*)d_in[25];
    float* out = (float*)d_out;

    float *x1, *S, *rd;
    fp16 *xh, *xl, *x1h, *x1l, *vh, *vl, *th, *tl, *qh, *ql, *kh, *kl, *Sh;
    fp16 *W1h, *W1l, *W2h, *W2l, *W3h, *W3l, *W4h, *W4l, *W5h, *W5l;
    cudaGetSymbolAddress((void**)&x1, g_x1);
    cudaGetSymbolAddress((void**)&S,  g_S);
    cudaGetSymbolAddress((void**)&rd, g_rd);
    cudaGetSymbolAddress((void**)&xh, g_xh);   cudaGetSymbolAddress((void**)&xl, g_xl);
    cudaGetSymbolAddress((void**)&x1h, g_x1h); cudaGetSymbolAddress((void**)&x1l, g_x1l);
    cudaGetSymbolAddress((void**)&vh, g_vh);   cudaGetSymbolAddress((void**)&vl, g_vl);
    cudaGetSymbolAddress((void**)&th, g_th);   cudaGetSymbolAddress((void**)&tl, g_tl);
    cudaGetSymbolAddress((void**)&qh, g_qh);   cudaGetSymbolAddress((void**)&ql, g_ql);
    cudaGetSymbolAddress((void**)&kh, g_kh);   cudaGetSymbolAddress((void**)&kl, g_kl);
    cudaGetSymbolAddress((void**)&Sh, g_Sh);
    cudaGetSymbolAddress((void**)&W1h, g_W1h); cudaGetSymbolAddress((void**)&W1l, g_W1l);
    cudaGetSymbolAddress((void**)&W2h, g_W2h); cudaGetSymbolAddress((void**)&W2l, g_W2l);
    cudaGetSymbolAddress((void**)&W3h, g_W3h); cudaGetSymbolAddress((void**)&W3l, g_W3l);
    cudaGetSymbolAddress((void**)&W4h, g_W4h); cudaGetSymbolAddress((void**)&W4l, g_W4l);
    cudaGetSymbolAddress((void**)&W5h, g_W5h); cudaGetSymbolAddress((void**)&W5l, g_W5l);

    cudaFuncSetAttribute(mma_gemm<EP_X1, false, 3>,    cudaFuncAttributeMaxDynamicSharedMemorySize, SMEM_GEMM);
    cudaFuncSetAttribute(mma_gemm<EP_BNR, false, 2>,   cudaFuncAttributeMaxDynamicSharedMemorySize, SMEM_GEMM);
    cudaFuncSetAttribute(mma_gemm<EP_BNR_T, false, 3>, cudaFuncAttributeMaxDynamicSharedMemorySize, SMEM_GEMM);
    cudaFuncSetAttribute(mma_gemm<EP_BNR, false, 3>,   cudaFuncAttributeMaxDynamicSharedMemorySize, SMEM_GEMM);
    cudaFuncSetAttribute(mma_gemm<EP_S, true, 3>,      cudaFuncAttributeMaxDynamicSharedMemorySize, SMEM_GEMM);
    cudaFuncSetAttribute(mma_gemm<EP_SUBDIV, true, 1>, cudaFuncAttributeMaxDynamicSharedMemorySize, SMEM_GEMM);
    cudaFuncSetAttribute(mma_gemm<EP_FINAL, false, 2>, cudaFuncAttributeMaxDynamicSharedMemorySize, SMEM_GEMM);

    const size_t sX  = (size_t)CH * NPTS;
    const size_t sQT = (size_t)NPTS * CQK;
    const size_t sK  = (size_t)CQK * NPTS;
    const size_t sS  = (size_t)NPTS * NPTS;

    // 0) merged hi/lo split of x and all weights (1 launch)
    const int splitTotal = NX + 2 * NW + 2 * NQW + NW;
    split_all<<<splitTotal / 256, 256>>>(x, xh, xl, W1, W1h, W1l, W2, W2h, W2l,
                                         W3, W3h, W3l, W4, W4h, W4l, W5, W5h, W5l);
    // 1) x1 = relu(bn1(W1 @ x))          [3-term: feeds softmax path]
    mma_gemm<EP_X1, false, 3><<<dim3(16, 8, 8), 256, SMEM_GEMM>>>(
        W1h, W1l, 0, xh, xl, sX, CH, CH,
        x1, x1h, x1l, g1, b1, m1, v1, nullptr, nullptr);
    // 2) v = relu(bn2(W2 @ x1))          [2-term: value path, self-averaging]
    mma_gemm<EP_BNR, false, 2><<<dim3(16, 8, 8), 256, SMEM_GEMM>>>(
        W2h, W2l, 0, x1h, x1l, sX, CH, CH,
        nullptr, vh, vl, g2, b2, m2, v2, nullptr, nullptr);
    // 3) q (stored transposed q^T [n][c]) [3-term: softmax exponent]
    mma_gemm<EP_BNR_T, false, 3><<<dim3(16, 1, 8), 256, SMEM_GEMM>>>(
        W3h, W3l, 0, x1h, x1l, sX, CQK, CH,
        nullptr, qh, ql, g3, b3, m3, v3, nullptr, nullptr);
    // 4) k                               [3-term: softmax exponent]
    mma_gemm<EP_BNR, false, 3><<<dim3(16, 1, 8), 256, SMEM_GEMM>>>(
        W4h, W4l, 0, x1h, x1l, sX, CQK, CH,
        nullptr, kh, kl, g4, b4, m4, v4, nullptr, nullptr);
    // 5) scores S[n][m]                  [3-term: softmax exponent]
    mma_gemm<EP_S, true, 3><<<dim3(16, 16, 8), 256, SMEM_GEMM>>>(
        qh, ql, sQT, kh, kl, sK, NPTS, CQK,
        S, nullptr, nullptr, nullptr, nullptr, nullptr, nullptr, nullptr, nullptr);
    // 6) row softmax -> fp16 hi only
    softmax_kernel<<<BATCH * NPTS, 256>>>(S, Sh);
    // 7) renorm divisor from Sh (consistent with GEMM operand)
    colsum_kernel<<<(BATCH * NPTS) / 256, 256>>>(Sh, rd);
    // 8) t = x1 - (v @ S) * rdiv[col]    [1-term: vh·Sh, positive sum]
    mma_gemm<EP_SUBDIV, true, 1><<<dim3(16, 8, 8), 256, SMEM_GEMM>>>(
        vh, vl, sX, Sh, Sh, sS, CH, NPTS,
        nullptr, th, tl, nullptr, nullptr, nullptr, nullptr, x1, rd);
    // 9) out = x1 + relu(bn5(W5 @ t))    [2-term: output path]
    mma_gemm<EP_FINAL, false, 2><<<dim3(16, 8, 8), 256, SMEM_GEMM>>>(
        W5h, W5l, 0, th, tl, sX, CH, CH,
        out, nullptr, nullptr, g5, b5, m5, v5, x1, nullptr);
}

// round 13
// speedup vs baseline: 1.8280x; 1.0727x over previous
#include <cuda_runtime.h>
#include <cuda_fp16.h>
#include <cstdint>

#define EPS_BN 1e-5f
#define EPS_RENORM 1e-9f

#define BATCH 8
#define CH    1024
#define NPTS  2048
#define CQK   128

typedef __half fp16;

// ---------------- scratch (no allocations allowed) ----------------
__device__ float g_x1[BATCH * CH * NPTS];
__device__ float g_S [(size_t)BATCH * NPTS * NPTS];
__device__ float g_rd[BATCH * NPTS];
__device__ fp16 g_xh [BATCH * CH * NPTS], g_xl [BATCH * CH * NPTS];
__device__ fp16 g_x1h[BATCH * CH * NPTS], g_x1l[BATCH * CH * NPTS];
__device__ fp16 g_vh [BATCH * CH * NPTS];
__device__ fp16 g_th [BATCH * CH * NPTS], g_tl [BATCH * CH * NPTS];
__device__ fp16 g_qh [BATCH * NPTS * CQK], g_ql[BATCH * NPTS * CQK];
__device__ fp16 g_kh [BATCH * CQK * NPTS], g_kl[BATCH * CQK * NPTS];
__device__ fp16 g_Sh [(size_t)BATCH * NPTS * NPTS];
__device__ fp16 g_W1h[CH * CH],  g_W1l[CH * CH];
__device__ fp16 g_W2h[CH * CH],  g_W2l[CH * CH];
__device__ fp16 g_W5h[CH * CH],  g_W5l[CH * CH];
__device__ fp16 g_W3h[CQK * CH], g_W3l[CQK * CH];
__device__ fp16 g_W4h[CQK * CH], g_W4l[CQK * CH];

// ---------------- PTX helpers ----------------
__device__ __forceinline__ uint32_t s2u(const void* p) {
    uint32_t a;
    asm("{ .reg .u64 t; cvta.to.shared.u64 t, %1; cvt.u32.u64 %0, t; }"
        : "=r"(a) : "l"(p));
    return a;
}
__device__ __forceinline__ void cp16(uint32_t saddr, const void* g) {
    asm volatile("cp.async.cg.shared.global [%0], [%1], 16;"
                 :: "r"(saddr), "l"(g) : "memory");
}
#define CP_COMMIT() asm volatile("cp.async.commit_group;" ::: "memory")
#define CP_WAIT(n)  asm volatile("cp.async.wait_group %0;" :: "n"(n) : "memory")

__device__ __forceinline__ void ldsm4(uint32_t* r, uint32_t a) {
    asm volatile("ldmatrix.sync.aligned.m8n8.x4.shared.b16 {%0,%1,%2,%3}, [%4];"
                 : "=r"(r[0]), "=r"(r[1]), "=r"(r[2]), "=r"(r[3]) : "r"(a));
}
__device__ __forceinline__ void ldsm4t(uint32_t* r, uint32_t a) {
    asm volatile("ldmatrix.sync.aligned.m8n8.x4.trans.shared.b16 {%0,%1,%2,%3}, [%4];"
                 : "=r"(r[0]), "=r"(r[1]), "=r"(r[2]), "=r"(r[3]) : "r"(a));
}
__device__ __forceinline__ void mma16816(float* d, const uint32_t* a, const uint32_t* b) {
    asm volatile("mma.sync.aligned.m16n8k16.row.col.f32.f16.f16.f32 "
                 "{%0,%1,%2,%3}, {%4,%5,%6,%7}, {%8,%9}, {%0,%1,%2,%3};"
                 : "+f"(d[0]), "+f"(d[1]), "+f"(d[2]), "+f"(d[3])
                 : "r"(a[0]), "r"(a[1]), "r"(a[2]), "r"(a[3]), "r"(b[0]), "r"(b[1]));
}

// ---------------- split-fp16 MMA GEMM ----------------
// C[b] (M x N) = (Ah+Al)[b] @ (Bh+Bl)[b]
// NTERM 3: Ah·Bh + Ah·Bl + Al·Bh ; 2: Ah·Bh + Ah·Bl ; 1: Ah·Bh
// A row-major [M][K], B row-major [K][N], N == NPTS.
// CTA 128x128, BK=32, 8 warps (warp tile 32x64), 3-stage cp.async, 2 CTAs/SM.
// EP_QK: fused q/k projection — blockIdx.y==0 -> q (A=W3, transposed store),
//        blockIdx.y==1 -> k (A=A2=W4, normal store into C2).
#define NSTG   3
#define STG_B  32768
#define SMEM_GEMM (NSTG * STG_B)      // 96 KiB dynamic -> 2 CTAs/SM

enum { EP_X1 = 0, EP_BNR = 1, EP_S = 3, EP_SUBDIV = 4, EP_FINAL = 5, EP_QK = 6 };

template<int EPI, bool ABATCH, int NTERM>
__global__ void __launch_bounds__(256, 2)
mma_gemm(const fp16* __restrict__ Ahp, const fp16* __restrict__ Alp, size_t sA,
         const fp16* __restrict__ Bhp, const fp16* __restrict__ Blp, size_t sB,
         int M, int K,
         float* __restrict__ C32, fp16* __restrict__ Ch, fp16* __restrict__ Cl,
         const float* __restrict__ gg, const float* __restrict__ bb,
         const float* __restrict__ mm, const float* __restrict__ vv,
         const float* __restrict__ add, const float* __restrict__ rdiv,
         const fp16* __restrict__ A2h, const fp16* __restrict__ A2l,
         fp16* __restrict__ C2h, fp16* __restrict__ C2l,
         const float* __restrict__ gg2, const float* __restrict__ bb2,
         const float* __restrict__ mm2, const float* __restrict__ vv2)
{
    extern __shared__ __align__(256) char smraw[];
    const uint32_t smb = s2u(smraw);
    const int tid  = threadIdx.x;
    const int lane = tid & 31;
    const int wid  = tid >> 5;
    const int m_w  = (wid & 3) * 32;     // warp M offset
    const int n_w  = (wid >> 2) * 64;    // warp N offset
    const int bz   = blockIdx.z;
    const int rowStart = blockIdx.y * 128;
    const int colStart = blockIdx.x * 128;
    const int N = NPTS;
    const bool isK2 = (EPI == EP_QK) && (blockIdx.y != 0);
    const int rowA = (EPI == EP_QK) ? 0 : rowStart;   // per-matrix local rows

    const fp16* Asel_h = isK2 ? A2h : Ahp;
    const fp16* Asel_l = isK2 ? A2l : Alp;
    const fp16* Ah_ = Asel_h + (ABATCH ? (size_t)bz * sA : 0);
    const fp16* Al_ = Asel_l + (ABATCH ? (size_t)bz * sA : 0);
    const fp16* Bh_ = Bhp + (size_t)bz * sB;
    const fp16* Bl_ = Blp + (size_t)bz * sB;

    float acc[2][8][4];
#pragma unroll
    for (int i = 0; i < 2; i++)
#pragma unroll
        for (int j = 0; j < 8; j++)
#pragma unroll
            for (int r = 0; r < 4; r++) acc[i][j][r] = 0.f;

    // stage layout: Ah @0 (8K) | Al @8192 | Bh @16384 | Bl @24576
    auto loadStage = [&](int t) {
        const int s = t % NSTG;
        const uint32_t base = smb + (uint32_t)s * STG_B;
        const int k0 = t * 32;
#pragma unroll
        for (int i = 0; i < 2; i++) {            // A: 128 rows x 4 chunks (16B)
            int idx = tid + i * 256;
            int row = idx >> 2, c = idx & 3;
            uint32_t off = (uint32_t)(row * 64 + ((c ^ ((row >> 1) & 3)) << 4));
            size_t go = (size_t)(rowA + row) * K + k0 + c * 8;
            cp16(base + off, Ah_ + go);
            if (NTERM >= 3) cp16(base + 8192 + off, Al_ + go);
        }
#pragma unroll
        for (int i = 0; i < 2; i++) {            // B: 32 rows x 16 chunks
            int idx = tid + i * 256;
            int k = idx >> 4, cn = idx & 15;
            uint32_t off = (uint32_t)(k * 256 + ((cn ^ (k & 7)) << 4));
            size_t go = (size_t)(k0 + k) * N + colStart + cn * 8;
            cp16(base + 16384 + off, Bh_ + go);
            if (NTERM >= 2) cp16(base + 24576 + off, Bl_ + go);
        }
        CP_COMMIT();
    };

    const int T = K / 32;
    const int P = (T < 2) ? T : 2;
    for (int t = 0; t < P; t++) loadStage(t);

    for (int t = 0; t < T; t++) {
        if (t + 1 < T) { CP_WAIT(1); } else { CP_WAIT(0); }
        __syncthreads();
        // top barrier of tile t also protects stage (t-1) from the overwrite
        // issued below (loadStage(t+2) targets stage (t+2)%3 == (t-1)%3).
        if (t + 2 < T) loadStage(t + 2);

        const uint32_t Ab = smb + (uint32_t)(t % NSTG) * STG_B;
#pragma unroll
        for (int ks = 0; ks < 2; ks++) {
            uint32_t ah[2][4], al[2][4];
#pragma unroll
            for (int i = 0; i < 2; i++) {
                int row = m_w + i * 16 + (lane & 15);
                int c = ks * 2 + (lane >> 4);
                uint32_t off = (uint32_t)(row * 64 + ((c ^ ((row >> 1) & 3)) << 4));
                ldsm4(ah[i], Ab + off);
                if (NTERM >= 3) ldsm4(al[i], Ab + 8192 + off);
            }
#pragma unroll
            for (int p = 0; p < 4; p++) {
                int g = lane >> 3, j8 = lane & 7;
                int k = ks * 16 + (g & 1) * 8 + j8;
                int cn = (n_w >> 3) + p * 2 + (g >> 1);
                uint32_t off = (uint32_t)(k * 256 + ((cn ^ (k & 7)) << 4));
                uint32_t bh[4], bl[4];
                ldsm4t(bh, Ab + 16384 + off);
                if (NTERM >= 2) ldsm4t(bl, Ab + 24576 + off);
#pragma unroll
                for (int i = 0; i < 2; i++) {
                    mma16816(acc[i][2 * p], ah[i], bh);
                    if (NTERM >= 2) mma16816(acc[i][2 * p], ah[i], bl);
                    if (NTERM >= 3) mma16816(acc[i][2 * p], al[i], bh);
                    mma16816(acc[i][2 * p + 1], ah[i], bh + 2);
                    if (NTERM >= 2) mma16816(acc[i][2 * p + 1], ah[i], bl + 2);
                    if (NTERM >= 3) mma16816(acc[i][2 * p + 1], al[i], bh + 2);
                }
            }
        }
    }

    // ---------------- epilogue ----------------
    __shared__ float s_scl[128], s_off[128];
    if (EPI == EP_X1 || EPI == EP_BNR || EPI == EP_QK || EPI == EP_FINAL) {
        __syncthreads();
        if (tid < 128) {
            const float* G = (EPI == EP_QK && isK2) ? gg2 : gg;
            const float* B = (EPI == EP_QK && isK2) ? bb2 : bb;
            const float* Mn = (EPI == EP_QK && isK2) ? mm2 : mm;
            const float* V = (EPI == EP_QK && isK2) ? vv2 : vv;
            int rg = rowA + tid;   // local channel for EP_QK, global row else
            float inv = rsqrtf(V[rg] + EPS_BN);
            float sc = G[rg] * inv;
            s_scl[tid] = sc;
            s_off[tid] = B[rg] - Mn[rg] * sc;
        }
        __syncthreads();
    }

    const bool wantLo = (Cl != nullptr);
    const size_t sC = (size_t)M * N;
#pragma unroll
    for (int i = 0; i < 2; i++) {
#pragma unroll
        for (int j = 0; j < 8; j++) {
#pragma unroll
            for (int hseg = 0; hseg < 2; hseg++) {
                const int rl = m_w + i * 16 + (lane >> 2) + hseg * 8;
                const int cl = n_w + j * 8 + (lane & 3) * 2;
                const float y0 = acc[i][j][hseg * 2];
                const float y1 = acc[i][j][hseg * 2 + 1];
                const int rg = rowStart + rl;
                const int cg = colStart + cl;
                const size_t o = (size_t)bz * sC + (size_t)rg * N + cg;

                if (EPI == EP_S) {
                    float2 v2; v2.x = y0; v2.y = y1;
                    *(float2*)(C32 + o) = v2;
                } else if (EPI == EP_SUBDIV) {
                    float2 ad  = *(const float2*)(add + o);
                    float2 rdv = *(const float2*)(rdiv + (size_t)bz * N + cg);
                    float z0 = ad.x - y0 * rdv.x;
                    float z1 = ad.y - y1 * rdv.y;
                    fp16 h0 = __float2half_rn(z0), h1 = __float2half_rn(z1);
                    *(__half2*)(Ch + o) = __halves2half2(h0, h1);
                    *(__half2*)(Cl + o) = __halves2half2(
                        __float2half_rn(z0 - __half2float(h0)),
                        __float2half_rn(z1 - __half2float(h1)));
                } else if (EPI == EP_QK) {
                    const float sc = s_scl[rl], of = s_off[rl];
                    float z0 = fmaxf(y0 * sc + of, 0.f);
                    float z1 = fmaxf(y1 * sc + of, 0.f);
                    fp16 h0 = __float2half_rn(z0), h1 = __float2half_rn(z1);
                    if (!isK2) {
                        // q: transposed store [point][channel], channel = rl
                        size_t ot = (size_t)bz * ((size_t)NPTS * CQK);
                        size_t o0 = ot + (size_t)cg * CQK + rl;
                        size_t o1 = o0 + CQK;
                        Ch[o0] = h0; Cl[o0] = __float2half_rn(z0 - __half2float(h0));
                        Ch[o1] = h1; Cl[o1] = __float2half_rn(z1 - __half2float(h1));
                    } else {
                        // k: [channel][point], channel = rl
                        size_t ok = (size_t)bz * ((size_t)CQK * NPTS)
                                  + (size_t)rl * N + cg;
                        *(__half2*)(C2h + ok) = __halves2half2(h0, h1);
                        *(__half2*)(C2l + ok) = __halves2half2(
                            __float2half_rn(z0 - __half2float(h0)),
                            __float2half_rn(z1 - __half2float(h1)));
                    }
                } else {
                    const float sc = s_scl[rl], of = s_off[rl];
                    float z0 = fmaxf(y0 * sc + of, 0.f);
                    float z1 = fmaxf(y1 * sc + of, 0.f);
                    if (EPI == EP_FINAL) {
                        float2 ad = *(const float2*)(add + o);
                        float2 v2; v2.x = ad.x + z0; v2.y = ad.y + z1;
                        *(float2*)(C32 + o) = v2;
                    } else {
                        if (EPI == EP_X1) {
                            float2 v2; v2.x = z0; v2.y = z1;
                            *(float2*)(C32 + o) = v2;
                        }
                        fp16 h0 = __float2half_rn(z0), h1 = __float2half_rn(z1);
                        *(__half2*)(Ch + o) = __halves2half2(h0, h1);
                        if (wantLo)
                            *(__half2*)(Cl + o) = __halves2half2(
                                __float2half_rn(z0 - __half2float(h0)),
                                __float2half_rn(z1 - __half2float(h1)));
                    }
                }
            }
        }
    }
}

// ---------------- merged fp32 -> fp16 hi/lo split of all inputs ----------------
#define NX (BATCH * CH * NPTS)
#define NW (CH * CH)
#define NQW (CQK * CH)

__global__ void __launch_bounds__(256)
split_all(const float* __restrict__ x,  fp16* __restrict__ xh,  fp16* __restrict__ xl,
          const float* __restrict__ W1, fp16* __restrict__ W1h, fp16* __restrict__ W1l,
          const float* __restrict__ W2, fp16* __restrict__ W2h, fp16* __restrict__ W2l,
          const float* __restrict__ W3, fp16* __restrict__ W3h, fp16* __restrict__ W3l,
          const float* __restrict__ W4, fp16* __restrict__ W4h, fp16* __restrict__ W4l,
          const float* __restrict__ W5, fp16* __restrict__ W5h, fp16* __restrict__ W5l)
{
    size_t i = (size_t)blockIdx.x * 256 + threadIdx.x;
    const float* in; fp16 *oh, *ol; size_t li;
    if (i < NX)                       { in = x;  oh = xh;  ol = xl;  li = i; }
    else if (i < NX + NW)             { in = W1; oh = W1h; ol = W1l; li = i - NX; }
    else if (i < NX + 2 * NW)         { in = W2; oh = W2h; ol = W2l; li = i - NX - NW; }
    else if (i < NX + 2 * NW + NQW)   { in = W3; oh = W3h; ol = W3l; li = i - NX - 2 * NW; }
    else if (i < NX + 2 * NW + 2*NQW) { in = W4; oh = W4h; ol = W4l; li = i - NX - 2 * NW - NQW; }
    else                              { in = W5; oh = W5h; ol = W5l; li = i - NX - 2 * NW - 2 * NQW; }
    float v = in[li];
    fp16 h = __float2half_rn(v);
    oh[li] = h;
    ol[li] = __float2half_rn(v - __half2float(h));
}

// ---------------- row softmax: fp32 in, fp16 (hi only) out ----------------
__global__ void __launch_bounds__(256)
softmax_kernel(const float* __restrict__ S, fp16* __restrict__ Sh)
{
    __shared__ float buf[NPTS];
    __shared__ float red[8];
    const float* p = S + (size_t)blockIdx.x * NPTS;
    fp16* ph = Sh + (size_t)blockIdx.x * NPTS;
    int t = threadIdx.x;

    float mx = -3.402823466e38f;
    for (int i = t; i < NPTS; i += 256) { float v = p[i]; buf[i] = v; mx = fmaxf(mx, v); }
#pragma unroll
    for (int o = 16; o > 0; o >>= 1) mx = fmaxf(mx, __shfl_xor_sync(0xffffffffu, mx, o));
    if ((t & 31) == 0) red[t >> 5] = mx;
    __syncthreads();
    float bm = red[0];
#pragma unroll
    for (int i = 1; i < 8; i++) bm = fmaxf(bm, red[i]);
    __syncthreads();

    float sum = 0.f;
    for (int i = t; i < NPTS; i += 256) { float e = __expf(buf[i] - bm); buf[i] = e; sum += e; }
#pragma unroll
    for (int o = 16; o > 0; o >>= 1) sum += __shfl_xor_sync(0xffffffffu, sum, o);
    if ((t & 31) == 0) red[t >> 5] = sum;
    __syncthreads();
    float bs = 0.f;
#pragma unroll
    for (int i = 0; i < 8; i++) bs += red[i];
    float inv = 1.0f / bs;
    for (int i = t; i < NPTS; i += 256)
        ph[i] = __float2half_rn(buf[i] * inv);
}

// ---------------- column sums of Sh -> 1/(eps+colsum) ----------------
__global__ void __launch_bounds__(256)
colsum_kernel(const fp16* __restrict__ Sh, float* __restrict__ rdiv)
{
    int idx = blockIdx.x * 256 + threadIdx.x;
    int b = idx / NPTS, m = idx - b * NPTS;
    const fp16* ph = Sh + (size_t)b * NPTS * NPTS + m;
    float s[4] = {0.f, 0.f, 0.f, 0.f};
    for (int n = 0; n < NPTS; n += 4) {
#pragma unroll
        for (int u = 0; u < 4; u++)
            s[u] += __half2float(ph[(size_t)(n + u) * NPTS]);
    }
    rdiv[idx] = 1.0f / (EPS_RENORM + ((s[0] + s[1]) + (s[2] + s[3])));
}

// ---------------- launch ----------------
#define NP8 nullptr, nullptr, nullptr, nullptr, nullptr, nullptr, nullptr, nullptr

extern "C" void kernel_launch(void* const* d_in, const int* in_sizes, int n_in,
                              void* d_out, int out_size)
{
    (void)in_sizes; (void)n_in; (void)out_size;
    const float* x  = (const float*)d_in[0];
    const float *W1 = (const float*)d_in[1],  *g1 = (const float*)d_in[2],
                *b1 = (const float*)d_in[3],  *m1 = (const float*)d_in[4],
                *v1 = (const float*)d_in[5];
    const float *W2 = (const float*)d_in[6],  *g2 = (const float*)d_in[7],
                *b2 = (const float*)d_in[8],  *m2 = (const float*)d_in[9],
                *v2 = (const float*)d_in[10];
    const float *W3 = (const float*)d_in[11], *g3 = (const float*)d_in[12],
                *b3 = (const float*)d_in[13], *m3 = (const float*)d_in[14],
                *v3 = (const float*)d_in[15];
    const float *W4 = (const float*)d_in[16], *g4 = (const float*)d_in[17],
                *b4 = (const float*)d_in[18], *m4 = (const float*)d_in[19],
                *v4 = (const float*)d_in[20];
    const float *W5 = (const float*)d_in[21], *g5 = (const float*)d_in[22],
                *b5 = (const float*)d_in[23], *m5 = (const float*)d_in[24],
                *v5 = (const float*)d_in[25];
    float* out = (float*)d_out;

    float *x1, *S, *rd;
    fp16 *xh, *xl, *x1h, *x1l, *vh, *th, *tl, *qh, *ql, *kh, *kl, *Sh;
    fp16 *W1h, *W1l, *W2h, *W2l, *W3h, *W3l, *W4h, *W4l, *W5h, *W5l;
    cudaGetSymbolAddress((void**)&x1, g_x1);
    cudaGetSymbolAddress((void**)&S,  g_S);
    cudaGetSymbolAddress((void**)&rd, g_rd);
    cudaGetSymbolAddress((void**)&xh, g_xh);   cudaGetSymbolAddress((void**)&xl, g_xl);
    cudaGetSymbolAddress((void**)&x1h, g_x1h); cudaGetSymbolAddress((void**)&x1l, g_x1l);
    cudaGetSymbolAddress((void**)&vh, g_vh);
    cudaGetSymbolAddress((void**)&th, g_th);   cudaGetSymbolAddress((void**)&tl, g_tl);
    cudaGetSymbolAddress((void**)&qh, g_qh);   cudaGetSymbolAddress((void**)&ql, g_ql);
    cudaGetSymbolAddress((void**)&kh, g_kh);   cudaGetSymbolAddress((void**)&kl, g_kl);
    cudaGetSymbolAddress((void**)&Sh, g_Sh);
    cudaGetSymbolAddress((void**)&W1h, g_W1h); cudaGetSymbolAddress((void**)&W1l, g_W1l);
    cudaGetSymbolAddress((void**)&W2h, g_W2h); cudaGetSymbolAddress((void**)&W2l, g_W2l);
    cudaGetSymbolAddress((void**)&W3h, g_W3h); cudaGetSymbolAddress((void**)&W3l, g_W3l);
    cudaGetSymbolAddress((void**)&W4h, g_W4h); cudaGetSymbolAddress((void**)&W4l, g_W4l);
    cudaGetSymbolAddress((void**)&W5h, g_W5h); cudaGetSymbolAddress((void**)&W5l, g_W5l);

    cudaFuncSetAttribute(mma_gemm<EP_X1, false, 3>,    cudaFuncAttributeMaxDynamicSharedMemorySize, SMEM_GEMM);
    cudaFuncSetAttribute(mma_gemm<EP_BNR, false, 1>,   cudaFuncAttributeMaxDynamicSharedMemorySize, SMEM_GEMM);
    cudaFuncSetAttribute(mma_gemm<EP_QK, false, 3>,    cudaFuncAttributeMaxDynamicSharedMemorySize, SMEM_GEMM);
    cudaFuncSetAttribute(mma_gemm<EP_S, true, 3>,      cudaFuncAttributeMaxDynamicSharedMemorySize, SMEM_GEMM);
    cudaFuncSetAttribute(mma_gemm<EP_SUBDIV, true, 1>, cudaFuncAttributeMaxDynamicSharedMemorySize, SMEM_GEMM);
    cudaFuncSetAttribute(mma_gemm<EP_FINAL, false, 2>, cudaFuncAttributeMaxDynamicSharedMemorySize, SMEM_GEMM);

    const size_t sX  = (size_t)CH * NPTS;
    const size_t sQT = (size_t)NPTS * CQK;
    const size_t sK  = (size_t)CQK * NPTS;
    const size_t sS  = (size_t)NPTS * NPTS;

    // 0) merged hi/lo split of x and all weights (1 launch)
    const int splitTotal = NX + 2 * NW + 2 * NQW + NW;
    split_all<<<splitTotal / 256, 256>>>(x, xh, xl, W1, W1h, W1l, W2, W2h, W2l,
                                         W3, W3h, W3l, W4, W4h, W4l, W5, W5h, W5l);
    // 1) x1 = relu(bn1(W1 @ x))           [3-term: softmax path]
    mma_gemm<EP_X1, false, 3><<<dim3(16, 8, 8), 256, SMEM_GEMM>>>(
        W1h, W1l, 0, xh, xl, sX, CH, CH,
        x1, x1h, x1l, g1, b1, m1, v1, nullptr, nullptr, NP8);
    // 2) v = relu(bn2(W2 @ x1))           [1-term: value path; no vl needed]
    mma_gemm<EP_BNR, false, 1><<<dim3(16, 8, 8), 256, SMEM_GEMM>>>(
        W2h, W2l, 0, x1h, x1l, sX, CH, CH,
        nullptr, vh, nullptr, g2, b2, m2, v2, nullptr, nullptr, NP8);
    // 3+4) fused q (y=0, transposed) + k (y=1)  [3-term: softmax exponent]
    mma_gemm<EP_QK, false, 3><<<dim3(16, 2, 8), 256, SMEM_GEMM>>>(
        W3h, W3l, 0, x1h, x1l, sX, CQK, CH,
        nullptr, qh, ql, g3, b3, m3, v3, nullptr, nullptr,
        W4h, W4l, kh, kl, g4, b4, m4, v4);
    // 5) scores S[n][m]                   [3-term: softmax exponent]
    mma_gemm<EP_S, true, 3><<<dim3(16, 16, 8), 256, SMEM_GEMM>>>(
        qh, ql, sQT, kh, kl, sK, NPTS, CQK,
        S, nullptr, nullptr, nullptr, nullptr, nullptr, nullptr,
        nullptr, nullptr, NP8);
    // 6) row softmax -> fp16 hi only
    softmax_kernel<<<BATCH * NPTS, 256>>>(S, Sh);
    // 7) renorm divisor from Sh (consistent with GEMM operand)
    colsum_kernel<<<(BATCH * NPTS) / 256, 256>>>(Sh, rd);
    // 8) t = x1 - (v @ S) * rdiv[col]     [1-term: vh·Sh, positive sum]
    mma_gemm<EP_SUBDIV, true, 1><<<dim3(16, 8, 8), 256, SMEM_GEMM>>>(
        vh, vh, sX, Sh, Sh, sS, CH, NPTS,
        nullptr, th, tl, nullptr, nullptr, nullptr, nullptr, x1, rd, NP8);
    // 9) out = x1 + relu(bn5(W5 @ t))     [2-term: output path]
    mma_gemm<EP_FINAL, false, 2><<<dim3(16, 8, 8), 256, SMEM_GEMM>>>(
        W5h, W5l, 0, th, tl, sX, CH, CH,
        out, nullptr, nullptr, g5, b5, m5, v5, x1, nullptr, NP8);
}

// round 14
// speedup vs baseline: 1.9841x; 1.0854x over previous
#include <cuda_runtime.h>
#include <cuda_fp16.h>
#include <cstdint>

#define EPS_BN 1e-5f
#define EPS_RENORM 1e-9f

#define BATCH 8
#define CH    1024
#define NPTS  2048
#define CQK   128

typedef __half fp16;

// ---------------- scratch (no allocations allowed) ----------------
__device__ float g_x1[BATCH * CH * NPTS];
__device__ float g_S [(size_t)BATCH * NPTS * NPTS];
__device__ float g_rd[BATCH * NPTS];
__device__ fp16 g_xh [BATCH * CH * NPTS], g_xl [BATCH * CH * NPTS];
__device__ fp16 g_x1h[BATCH * CH * NPTS], g_x1l[BATCH * CH * NPTS];
__device__ fp16 g_vh [BATCH * CH * NPTS];
__device__ fp16 g_th [BATCH * CH * NPTS], g_tl [BATCH * CH * NPTS];
__device__ fp16 g_qh [BATCH * NPTS * CQK], g_ql[BATCH * NPTS * CQK];
__device__ fp16 g_kh [BATCH * CQK * NPTS], g_kl[BATCH * CQK * NPTS];
__device__ fp16 g_Sh [(size_t)BATCH * NPTS * NPTS];
__device__ fp16 g_W1h[CH * CH],  g_W1l[CH * CH];
__device__ fp16 g_W2h[CH * CH],  g_W2l[CH * CH];
__device__ fp16 g_W5h[CH * CH],  g_W5l[CH * CH];
__device__ fp16 g_W3h[CQK * CH], g_W3l[CQK * CH];
__device__ fp16 g_W4h[CQK * CH], g_W4l[CQK * CH];

// ---------------- PTX helpers ----------------
__device__ __forceinline__ uint32_t s2u(const void* p) {
    uint32_t a;
    asm("{ .reg .u64 t; cvta.to.shared.u64 t, %1; cvt.u32.u64 %0, t; }"
        : "=r"(a) : "l"(p));
    return a;
}
__device__ __forceinline__ void cp16(uint32_t saddr, const void* g) {
    asm volatile("cp.async.cg.shared.global [%0], [%1], 16;"
                 :: "r"(saddr), "l"(g) : "memory");
}
#define CP_COMMIT() asm volatile("cp.async.commit_group;" ::: "memory")
#define CP_WAIT(n)  asm volatile("cp.async.wait_group %0;" :: "n"(n) : "memory")

__device__ __forceinline__ void ldsm4(uint32_t* r, uint32_t a) {
    asm volatile("ldmatrix.sync.aligned.m8n8.x4.shared.b16 {%0,%1,%2,%3}, [%4];"
                 : "=r"(r[0]), "=r"(r[1]), "=r"(r[2]), "=r"(r[3]) : "r"(a));
}
__device__ __forceinline__ void ldsm4t(uint32_t* r, uint32_t a) {
    asm volatile("ldmatrix.sync.aligned.m8n8.x4.trans.shared.b16 {%0,%1,%2,%3}, [%4];"
                 : "=r"(r[0]), "=r"(r[1]), "=r"(r[2]), "=r"(r[3]) : "r"(a));
}
__device__ __forceinline__ void mma16816(float* d, const uint32_t* a, const uint32_t* b) {
    asm volatile("mma.sync.aligned.m16n8k16.row.col.f32.f16.f16.f32 "
                 "{%0,%1,%2,%3}, {%4,%5,%6,%7}, {%8,%9}, {%0,%1,%2,%3};"
                 : "+f"(d[0]), "+f"(d[1]), "+f"(d[2]), "+f"(d[3])
                 : "r"(a[0]), "r"(a[1]), "r"(a[2]), "r"(a[3]), "r"(b[0]), "r"(b[1]));
}

// ---------------- split-fp16 MMA GEMM ----------------
// C[b] (M x N) = (Ah+Al)[b] @ (Bh+Bl)[b]
// NTERM 3: Ah·Bh + Ah·Bl + Al·Bh ; 2: Ah·Bh + Ah·Bl ; 1: Ah·Bh
// KPS: k32-tiles per pipeline stage (2 only allowed for NTERM==1 — the lo
//      operand slots in the 32KB stage are reused for the 2nd sub-tile).
// A row-major [M][K], B row-major [K][N], N == NPTS.
// CTA 128x128, 8 warps (warp tile 32x64), 3-stage cp.async, 2 CTAs/SM.
// EP_QK: fused q/k — blockIdx.y==0 -> q (A=W3, transposed store),
//        blockIdx.y==1 -> k (A=A2=W4, store into C2).
#define NSTG   3
#define STG_B  32768
#define SMEM_GEMM (NSTG * STG_B)      // 96 KiB dynamic -> 2 CTAs/SM

enum { EP_X1 = 0, EP_BNR = 1, EP_S = 3, EP_SUBDIV = 4, EP_FINAL = 5, EP_QK = 6 };

template<int EPI, bool ABATCH, int NTERM, int KPS>
__global__ void __launch_bounds__(256, 2)
mma_gemm(const fp16* __restrict__ Ahp, const fp16* __restrict__ Alp, size_t sA,
         const fp16* __restrict__ Bhp, const fp16* __restrict__ Blp, size_t sB,
         int M, int K,
         float* __restrict__ C32, fp16* __restrict__ Ch, fp16* __restrict__ Cl,
         const float* __restrict__ gg, const float* __restrict__ bb,
         const float* __restrict__ mm, const float* __restrict__ vv,
         const float* __restrict__ add, const float* __restrict__ rdiv,
         const fp16* __restrict__ A2h, const fp16* __restrict__ A2l,
         fp16* __restrict__ C2h, fp16* __restrict__ C2l,
         const float* __restrict__ gg2, const float* __restrict__ bb2,
         const float* __restrict__ mm2, const float* __restrict__ vv2)
{
    static_assert(KPS == 1 || NTERM == 1, "KPS=2 requires 1-term");
    extern __shared__ __align__(256) char smraw[];
    const uint32_t smb = s2u(smraw);
    const int tid  = threadIdx.x;
    const int lane = tid & 31;
    const int wid  = tid >> 5;
    const int m_w  = (wid & 3) * 32;     // warp M offset
    const int n_w  = (wid >> 2) * 64;    // warp N offset
    const int bz   = blockIdx.z;
    const int rowStart = blockIdx.y * 128;
    const int colStart = blockIdx.x * 128;
    const int N = NPTS;
    const bool isK2 = (EPI == EP_QK) && (blockIdx.y != 0);
    const int rowA = (EPI == EP_QK) ? 0 : rowStart;   // per-matrix local rows

    const fp16* Asel_h = isK2 ? A2h : Ahp;
    const fp16* Asel_l = isK2 ? A2l : Alp;
    const fp16* Ah_ = Asel_h + (ABATCH ? (size_t)bz * sA : 0);
    const fp16* Al_ = Asel_l + (ABATCH ? (size_t)bz * sA : 0);
    const fp16* Bh_ = Bhp + (size_t)bz * sB;
    const fp16* Bl_ = Blp + (size_t)bz * sB;

    float acc[2][8][4];
#pragma unroll
    for (int i = 0; i < 2; i++)
#pragma unroll
        for (int j = 0; j < 8; j++)
#pragma unroll
            for (int r = 0; r < 4; r++) acc[i][j][r] = 0.f;

    // stage layout:
    //   KPS=1: Ah @0 | Al @8192 | Bh @16384 | Bl @24576
    //   KPS=2 (1-term): A0 @0 | A1 @8192 | B0 @16384 | B1 @24576
    auto loadStage = [&](int t) {
        const int s = t % NSTG;
        const uint32_t base = smb + (uint32_t)s * STG_B;
        const int k0 = t * 32 * KPS;
#pragma unroll
        for (int sub = 0; sub < KPS; sub++) {
#pragma unroll
            for (int i = 0; i < 2; i++) {        // A: 128 rows x 4 chunks (16B)
                int idx = tid + i * 256;
                int row = idx >> 2, c = idx & 3;
                uint32_t off = (uint32_t)(row * 64 + ((c ^ ((row >> 1) & 3)) << 4));
                size_t go = (size_t)(rowA + row) * K + k0 + sub * 32 + c * 8;
                cp16(base + (uint32_t)sub * 8192 + off, Ah_ + go);
                if (NTERM >= 3) cp16(base + 8192 + off, Al_ + go);
            }
#pragma unroll
            for (int i = 0; i < 2; i++) {        // B: 32 rows x 16 chunks
                int idx = tid + i * 256;
                int k = idx >> 4, cn = idx & 15;
                uint32_t off = (uint32_t)(k * 256 + ((cn ^ (k & 7)) << 4));
                size_t go = (size_t)(k0 + sub * 32 + k) * N + colStart + cn * 8;
                cp16(base + 16384 + (uint32_t)sub * 8192 + off, Bh_ + go);
                if (NTERM >= 2) cp16(base + 24576 + off, Bl_ + go);
            }
        }
        CP_COMMIT();
    };

    const int T = K / (32 * KPS);
    const int P = (T < 2) ? T : 2;
    for (int t = 0; t < P; t++) loadStage(t);

    for (int t = 0; t < T; t++) {
        if (t + 1 < T) { CP_WAIT(1); } else { CP_WAIT(0); }
        __syncthreads();
        // top barrier of tile t also protects stage (t-1) from the overwrite
        // issued below (loadStage(t+2) targets stage (t+2)%3 == (t-1)%3).
        if (t + 2 < T) loadStage(t + 2);

        const uint32_t Ab = smb + (uint32_t)(t % NSTG) * STG_B;
#pragma unroll
        for (int kk = 0; kk < 2 * KPS; kk++) {
            const int sub = kk >> 1;
            const int ks  = kk & 1;
            const uint32_t Asub = Ab + (uint32_t)sub * 8192;
            const uint32_t Bsub = Ab + 16384 + (uint32_t)sub * 8192;
            uint32_t ah[2][4], al[2][4];
#pragma unroll
            for (int i = 0; i < 2; i++) {
                int row = m_w + i * 16 + (lane & 15);
                int c = ks * 2 + (lane >> 4);
                uint32_t off = (uint32_t)(row * 64 + ((c ^ ((row >> 1) & 3)) << 4));
                ldsm4(ah[i], Asub + off);
                if (NTERM >= 3) ldsm4(al[i], Asub + 8192 + off);
            }
#pragma unroll
            for (int p = 0; p < 4; p++) {
                int g = lane >> 3, j8 = lane & 7;
                int k = ks * 16 + (g & 1) * 8 + j8;
                int cn = (n_w >> 3) + p * 2 + (g >> 1);
                uint32_t off = (uint32_t)(k * 256 + ((cn ^ (k & 7)) << 4));
                uint32_t bh[4], bl[4];
                ldsm4t(bh, Bsub + off);
                if (NTERM >= 2) ldsm4t(bl, Bsub + 8192 + off);
#pragma unroll
                for (int i = 0; i < 2; i++) {
                    mma16816(acc[i][2 * p], ah[i], bh);
                    if (NTERM >= 2) mma16816(acc[i][2 * p], ah[i], bl);
                    if (NTERM >= 3) mma16816(acc[i][2 * p], al[i], bh);
                    mma16816(acc[i][2 * p + 1], ah[i], bh + 2);
                    if (NTERM >= 2) mma16816(acc[i][2 * p + 1], ah[i], bl + 2);
                    if (NTERM >= 3) mma16816(acc[i][2 * p + 1], al[i], bh + 2);
                }
            }
        }
    }

    // ---------------- epilogue ----------------
    __shared__ float s_scl[128], s_off[128];
    if (EPI == EP_X1 || EPI == EP_BNR || EPI == EP_QK || EPI == EP_FINAL) {
        __syncthreads();
        if (tid < 128) {
            const float* G = (EPI == EP_QK && isK2) ? gg2 : gg;
            const float* B = (EPI == EP_QK && isK2) ? bb2 : bb;
            const float* Mn = (EPI == EP_QK && isK2) ? mm2 : mm;
            const float* V = (EPI == EP_QK && isK2) ? vv2 : vv;
            int rg = rowA + tid;   // local channel for EP_QK, global row else
            float inv = rsqrtf(V[rg] + EPS_BN);
            float sc = G[rg] * inv;
            s_scl[tid] = sc;
            s_off[tid] = B[rg] - Mn[rg] * sc;
        }
        __syncthreads();
    }

    const bool wantLo = (Cl != nullptr);
    const size_t sC = (size_t)M * N;
#pragma unroll
    for (int i = 0; i < 2; i++) {
#pragma unroll
        for (int j = 0; j < 8; j++) {
#pragma unroll
            for (int hseg = 0; hseg < 2; hseg++) {
                const int rl = m_w + i * 16 + (lane >> 2) + hseg * 8;
                const int cl = n_w + j * 8 + (lane & 3) * 2;
                const float y0 = acc[i][j][hseg * 2];
                const float y1 = acc[i][j][hseg * 2 + 1];
                const int rg = rowStart + rl;
                const int cg = colStart + cl;
                const size_t o = (size_t)bz * sC + (size_t)rg * N + cg;

                if (EPI == EP_S) {
                    float2 v2; v2.x = y0; v2.y = y1;
                    *(float2*)(C32 + o) = v2;
                } else if (EPI == EP_SUBDIV) {
                    float2 ad  = *(const float2*)(add + o);
                    float2 rdv = *(const float2*)(rdiv + (size_t)bz * N + cg);
                    float z0 = ad.x - y0 * rdv.x;
                    float z1 = ad.y - y1 * rdv.y;
                    fp16 h0 = __float2half_rn(z0), h1 = __float2half_rn(z1);
                    *(__half2*)(Ch + o) = __halves2half2(h0, h1);
                    if (wantLo)
                        *(__half2*)(Cl + o) = __halves2half2(
                            __float2half_rn(z0 - __half2float(h0)),
                            __float2half_rn(z1 - __half2float(h1)));
                } else if (EPI == EP_QK) {
                    const float sc = s_scl[rl], of = s_off[rl];
                    float z0 = fmaxf(y0 * sc + of, 0.f);
                    float z1 = fmaxf(y1 * sc + of, 0.f);
                    fp16 h0 = __float2half_rn(z0), h1 = __float2half_rn(z1);
                    if (!isK2) {
                        // q: transposed store [point][channel], channel = rl
                        size_t ot = (size_t)bz * ((size_t)NPTS * CQK);
                        size_t o0 = ot + (size_t)cg * CQK + rl;
                        size_t o1 = o0 + CQK;
                        Ch[o0] = h0; Cl[o0] = __float2half_rn(z0 - __half2float(h0));
                        Ch[o1] = h1; Cl[o1] = __float2half_rn(z1 - __half2float(h1));
                    } else {
                        // k: [channel][point], channel = rl
                        size_t ok = (size_t)bz * ((size_t)CQK * NPTS)
                                  + (size_t)rl * N + cg;
                        *(__half2*)(C2h + ok) = __halves2half2(h0, h1);
                        *(__half2*)(C2l + ok) = __halves2half2(
                            __float2half_rn(z0 - __half2float(h0)),
                            __float2half_rn(z1 - __half2float(h1)));
                    }
                } else {
                    const float sc = s_scl[rl], of = s_off[rl];
                    float z0 = fmaxf(y0 * sc + of, 0.f);
                    float z1 = fmaxf(y1 * sc + of, 0.f);
                    if (EPI == EP_FINAL) {
                        float2 ad = *(const float2*)(add + o);
                        float2 v2; v2.x = ad.x + z0; v2.y = ad.y + z1;
                        *(float2*)(C32 + o) = v2;
                    } else {
                        if (EPI == EP_X1) {
                            float2 v2; v2.x = z0; v2.y = z1;
                            *(float2*)(C32 + o) = v2;
                        }
                        fp16 h0 = __float2half_rn(z0), h1 = __float2half_rn(z1);
                        *(__half2*)(Ch + o) = __halves2half2(h0, h1);
                        if (wantLo)
                            *(__half2*)(Cl + o) = __halves2half2(
                                __float2half_rn(z0 - __half2float(h0)),
                                __float2half_rn(z1 - __half2float(h1)));
                    }
                }
            }
        }
    }
}

// ---------------- merged fp32 -> fp16 hi/lo split of all inputs ----------------
#define NX (BATCH * CH * NPTS)
#define NW (CH * CH)
#define NQW (CQK * CH)

__global__ void __launch_bounds__(256)
split_all(const float* __restrict__ x,  fp16* __restrict__ xh,  fp16* __restrict__ xl,
          const float* __restrict__ W1, fp16* __restrict__ W1h, fp16* __restrict__ W1l,
          const float* __restrict__ W2, fp16* __restrict__ W2h, fp16* __restrict__ W2l,
          const float* __restrict__ W3, fp16* __restrict__ W3h, fp16* __restrict__ W3l,
          const float* __restrict__ W4, fp16* __restrict__ W4h, fp16* __restrict__ W4l,
          const float* __restrict__ W5, fp16* __restrict__ W5h, fp16* __restrict__ W5l)
{
    size_t i = (size_t)blockIdx.x * 256 + threadIdx.x;
    const float* in; fp16 *oh, *ol; size_t li;
    if (i < NX)                       { in = x;  oh = xh;  ol = xl;  li = i; }
    else if (i < NX + NW)             { in = W1; oh = W1h; ol = W1l; li = i - NX; }
    else if (i < NX + 2 * NW)         { in = W2; oh = W2h; ol = W2l; li = i - NX - NW; }
    else if (i < NX + 2 * NW + NQW)   { in = W3; oh = W3h; ol = W3l; li = i - NX - 2 * NW; }
    else if (i < NX + 2 * NW + 2*NQW) { in = W4; oh = W4h; ol = W4l; li = i - NX - 2 * NW - NQW; }
    else                              { in = W5; oh = W5h; ol = W5l; li = i - NX - 2 * NW - 2 * NQW; }
    float v = in[li];
    fp16 h = __float2half_rn(v);
    oh[li] = h;
    ol[li] = __float2half_rn(v - __half2float(h));
}

// ---------------- row softmax: fp32 in, fp16 (hi only) out ----------------
__global__ void __launch_bounds__(256)
softmax_kernel(const float* __restrict__ S, fp16* __restrict__ Sh)
{
    __shared__ float buf[NPTS];
    __shared__ float red[8];
    const float* p = S + (size_t)blockIdx.x * NPTS;
    fp16* ph = Sh + (size_t)blockIdx.x * NPTS;
    int t = threadIdx.x;

    float mx = -3.402823466e38f;
    for (int i = t; i < NPTS; i += 256) { float v = p[i]; buf[i] = v; mx = fmaxf(mx, v); }
#pragma unroll
    for (int o = 16; o > 0; o >>= 1) mx = fmaxf(mx, __shfl_xor_sync(0xffffffffu, mx, o));
    if ((t & 31) == 0) red[t >> 5] = mx;
    __syncthreads();
    float bm = red[0];
#pragma unroll
    for (int i = 1; i < 8; i++) bm = fmaxf(bm, red[i]);
    __syncthreads();

    float sum = 0.f;
    for (int i = t; i < NPTS; i += 256) { float e = __expf(buf[i] - bm); buf[i] = e; sum += e; }
#pragma unroll
    for (int o = 16; o > 0; o >>= 1) sum += __shfl_xor_sync(0xffffffffu, sum, o);
    if ((t & 31) == 0) red[t >> 5] = sum;
    __syncthreads();
    float bs = 0.f;
#pragma unroll
    for (int i = 0; i < 8; i++) bs += red[i];
    float inv = 1.0f / bs;
    for (int i = t; i < NPTS; i += 256)
        ph[i] = __float2half_rn(buf[i] * inv);
}

// ---------------- column sums of Sh -> 1/(eps+colsum) ----------------
__global__ void __launch_bounds__(256)
colsum_kernel(const fp16* __restrict__ Sh, float* __restrict__ rdiv)
{
    int idx = blockIdx.x * 256 + threadIdx.x;
    int b = idx / NPTS, m = idx - b * NPTS;
    const fp16* ph = Sh + (size_t)b * NPTS * NPTS + m;
    float s[4] = {0.f, 0.f, 0.f, 0.f};
    for (int n = 0; n < NPTS; n += 4) {
#pragma unroll
        for (int u = 0; u < 4; u++)
            s[u] += __half2float(ph[(size_t)(n + u) * NPTS]);
    }
    rdiv[idx] = 1.0f / (EPS_RENORM + ((s[0] + s[1]) + (s[2] + s[3])));
}

// ---------------- launch ----------------
#define NP8 nullptr, nullptr, nullptr, nullptr, nullptr, nullptr, nullptr, nullptr

extern "C" void kernel_launch(void* const* d_in, const int* in_sizes, int n_in,
                              void* d_out, int out_size)
{
    (void)in_sizes; (void)n_in; (void)out_size;
    const float* x  = (const float*)d_in[0];
    const float *W1 = (const float*)d_in[1],  *g1 = (const float*)d_in[2],
                *b1 = (const float*)d_in[3],  *m1 = (const float*)d_in[4],
                *v1 = (const float*)d_in[5];
    const float *W2 = (const float*)d_in[6],  *g2 = (const float*)d_in[7],
                *b2 = (const float*)d_in[8],  *m2 = (const float*)d_in[9],
                *v2 = (const float*)d_in[10];
    const float *W3 = (const float*)d_in[11], *g3 = (const float*)d_in[12],
                *b3 = (const float*)d_in[13], *m3 = (const float*)d_in[14],
                *v3 = (const float*)d_in[15];
    const float *W4 = (const float*)d_in[16], *g4 = (const float*)d_in[17],
                *b4 = (const float*)d_in[18], *m4 = (const float*)d_in[19],
                *v4 = (const float*)d_in[20];
    const float *W5 = (const float*)d_in[21], *g5 = (const float*)d_in[22],
                *b5 = (const float*)d_in[23], *m5 = (const float*)d_in[24],
                *v5 = (const float*)d_in[25];
    float* out = (float*)d_out;

    float *x1, *S, *rd;
    fp16 *xh, *xl, *x1h, *x1l, *vh, *th, *qh, *ql, *kh, *kl, *Sh;
    fp16 *W1h, *W1l, *W2h, *W2l, *W3h, *W3l, *W4h, *W4l, *W5h, *W5l;
    cudaGetSymbolAddress((void**)&x1, g_x1);
    cudaGetSymbolAddress((void**)&S,  g_S);
    cudaGetSymbolAddress((void**)&rd, g_rd);
    cudaGetSymbolAddress((void**)&xh, g_xh);   cudaGetSymbolAddress((void**)&xl, g_xl);
    cudaGetSymbolAddress((void**)&x1h, g_x1h); cudaGetSymbolAddress((void**)&x1l, g_x1l);
    cudaGetSymbolAddress((void**)&vh, g_vh);
    cudaGetSymbolAddress((void**)&th, g_th);
    cudaGetSymbolAddress((void**)&qh, g_qh);   cudaGetSymbolAddress((void**)&ql, g_ql);
    cudaGetSymbolAddress((void**)&kh, g_kh);   cudaGetSymbolAddress((void**)&kl, g_kl);
    cudaGetSymbolAddress((void**)&Sh, g_Sh);
    cudaGetSymbolAddress((void**)&W1h, g_W1h); cudaGetSymbolAddress((void**)&W1l, g_W1l);
    cudaGetSymbolAddress((void**)&W2h, g_W2h); cudaGetSymbolAddress((void**)&W2l, g_W2l);
    cudaGetSymbolAddress((void**)&W3h, g_W3h); cudaGetSymbolAddress((void**)&W3l, g_W3l);
    cudaGetSymbolAddress((void**)&W4h, g_W4h); cudaGetSymbolAddress((void**)&W4l, g_W4l);
    cudaGetSymbolAddress((void**)&W5h, g_W5h); cudaGetSymbolAddress((void**)&W5l, g_W5l);

    cudaFuncSetAttribute(mma_gemm<EP_X1, false, 3, 1>,    cudaFuncAttributeMaxDynamicSharedMemorySize, SMEM_GEMM);
    cudaFuncSetAttribute(mma_gemm<EP_BNR, false, 1, 2>,   cudaFuncAttributeMaxDynamicSharedMemorySize, SMEM_GEMM);
    cudaFuncSetAttribute(mma_gemm<EP_QK, false, 3, 1>,    cudaFuncAttributeMaxDynamicSharedMemorySize, SMEM_GEMM);
    cudaFuncSetAttribute(mma_gemm<EP_S, true, 3, 1>,      cudaFuncAttributeMaxDynamicSharedMemorySize, SMEM_GEMM);
    cudaFuncSetAttribute(mma_gemm<EP_SUBDIV, true, 1, 2>, cudaFuncAttributeMaxDynamicSharedMemorySize, SMEM_GEMM);
    cudaFuncSetAttribute(mma_gemm<EP_FINAL, false, 1, 2>, cudaFuncAttributeMaxDynamicSharedMemorySize, SMEM_GEMM);

    const size_t sX  = (size_t)CH * NPTS;
    const size_t sQT = (size_t)NPTS * CQK;
    const size_t sK  = (size_t)CQK * NPTS;
    const size_t sS  = (size_t)NPTS * NPTS;

    // 0) merged hi/lo split of x and all weights (1 launch)
    const int splitTotal = NX + 2 * NW + 2 * NQW + NW;
    split_all<<<splitTotal / 256, 256>>>(x, xh, xl, W1, W1h, W1l, W2, W2h, W2l,
                                         W3, W3h, W3l, W4, W4h, W4l, W5, W5h, W5l);
    // 1) x1 = relu(bn1(W1 @ x))           [3-term: softmax path]
    mma_gemm<EP_X1, false, 3, 1><<<dim3(16, 8, 8), 256, SMEM_GEMM>>>(
        W1h, W1l, 0, xh, xl, sX, CH, CH,
        x1, x1h, x1l, g1, b1, m1, v1, nullptr, nullptr, NP8);
    // 2) v = relu(bn2(W2 @ x1))           [1-term, BK=64]
    mma_gemm<EP_BNR, false, 1, 2><<<dim3(16, 8, 8), 256, SMEM_GEMM>>>(
        W2h, W2l, 0, x1h, x1l, sX, CH, CH,
        nullptr, vh, nullptr, g2, b2, m2, v2, nullptr, nullptr, NP8);
    // 3+4) fused q (y=0, transposed) + k (y=1)  [3-term: softmax exponent]
    mma_gemm<EP_QK, false, 3, 1><<<dim3(16, 2, 8), 256, SMEM_GEMM>>>(
        W3h, W3l, 0, x1h, x1l, sX, CQK, CH,
        nullptr, qh, ql, g3, b3, m3, v3, nullptr, nullptr,
        W4h, W4l, kh, kl, g4, b4, m4, v4);
    // 5) scores S[n][m]                   [3-term: softmax exponent]
    mma_gemm<EP_S, true, 3, 1><<<dim3(16, 16, 8), 256, SMEM_GEMM>>>(
        qh, ql, sQT, kh, kl, sK, NPTS, CQK,
        S, nullptr, nullptr, nullptr, nullptr, nullptr, nullptr,
        nullptr, nullptr, NP8);
    // 6) row softmax -> fp16 hi only
    softmax_kernel<<<BATCH * NPTS, 256>>>(S, Sh);
    // 7) renorm divisor from Sh (consistent with GEMM operand)
    colsum_kernel<<<(BATCH * NPTS) / 256, 256>>>(Sh, rd);
    // 8) t = x1 - (v @ S) * rdiv[col]     [1-term vh·Sh, BK=64; th only]
    mma_gemm<EP_SUBDIV, true, 1, 2><<<dim3(16, 8, 8), 256, SMEM_GEMM>>>(
        vh, vh, sX, Sh, Sh, sS, CH, NPTS,
        nullptr, th, nullptr, nullptr, nullptr, nullptr, nullptr, x1, rd, NP8);
    // 9) out = x1 + relu(bn5(W5 @ t))     [1-term W5h·th, BK=64]
    mma_gemm<EP_FINAL, false, 1, 2><<<dim3(16, 8, 8), 256, SMEM_GEMM>>>(
        W5h, W5l, 0, th, th, sX, CH, CH,
        out, nullptr, nullptr, g5, b5, m5, v5, x1, nullptr, NP8);
}

// round 15
// speedup vs baseline: 2.0001x; 1.0081x over previous
#include <cuda_runtime.h>
#include <cuda_fp16.h>
#include <cstdint>

#define EPS_BN 1e-5f
#define EPS_RENORM 1e-9f

#define BATCH 8
#define CH    1024
#define NPTS  2048
#define CQK   128

typedef __half fp16;

// ---------------- scratch (no allocations allowed) ----------------
__device__ float g_x1[BATCH * CH * NPTS];
__device__ float g_S [(size_t)BATCH * NPTS * NPTS];
__device__ float g_rd[BATCH * NPTS];
__device__ fp16 g_xh [BATCH * CH * NPTS], g_xl [BATCH * CH * NPTS];
__device__ fp16 g_x1h[BATCH * CH * NPTS], g_x1l[BATCH * CH * NPTS];
__device__ fp16 g_vh [BATCH * CH * NPTS];
__device__ fp16 g_th [BATCH * CH * NPTS];
__device__ fp16 g_qh [BATCH * NPTS * CQK], g_ql[BATCH * NPTS * CQK];
__device__ fp16 g_kh [BATCH * CQK * NPTS], g_kl[BATCH * CQK * NPTS];
__device__ fp16 g_Sh [(size_t)BATCH * NPTS * NPTS];
__device__ fp16 g_W1h[CH * CH],  g_W1l[CH * CH];
__device__ fp16 g_W2h[CH * CH],  g_W2l[CH * CH];
__device__ fp16 g_W5h[CH * CH],  g_W5l[CH * CH];
__device__ fp16 g_W3h[CQK * CH], g_W3l[CQK * CH];
__device__ fp16 g_W4h[CQK * CH], g_W4l[CQK * CH];

// ---------------- PTX helpers ----------------
__device__ __forceinline__ uint32_t s2u(const void* p) {
    uint32_t a;
    asm("{ .reg .u64 t; cvta.to.shared.u64 t, %1; cvt.u32.u64 %0, t; }"
        : "=r"(a) : "l"(p));
    return a;
}
__device__ __forceinline__ void cp16(uint32_t saddr, const void* g) {
    asm volatile("cp.async.cg.shared.global [%0], [%1], 16;"
                 :: "r"(saddr), "l"(g) : "memory");
}
#define CP_COMMIT() asm volatile("cp.async.commit_group;" ::: "memory")
#define CP_WAIT(n)  asm volatile("cp.async.wait_group %0;" :: "n"(n) : "memory")

__device__ __forceinline__ void ldsm4(uint32_t* r, uint32_t a) {
    asm volatile("ldmatrix.sync.aligned.m8n8.x4.shared.b16 {%0,%1,%2,%3}, [%4];"
                 : "=r"(r[0]), "=r"(r[1]), "=r"(r[2]), "=r"(r[3]) : "r"(a));
}
__device__ __forceinline__ void ldsm4t(uint32_t* r, uint32_t a) {
    asm volatile("ldmatrix.sync.aligned.m8n8.x4.trans.shared.b16 {%0,%1,%2,%3}, [%4];"
                 : "=r"(r[0]), "=r"(r[1]), "=r"(r[2]), "=r"(r[3]) : "r"(a));
}
__device__ __forceinline__ void mma16816(float* d, const uint32_t* a, const uint32_t* b) {
    asm volatile("mma.sync.aligned.m16n8k16.row.col.f32.f16.f16.f32 "
                 "{%0,%1,%2,%3}, {%4,%5,%6,%7}, {%8,%9}, {%0,%1,%2,%3};"
                 : "+f"(d[0]), "+f"(d[1]), "+f"(d[2]), "+f"(d[3])
                 : "r"(a[0]), "r"(a[1]), "r"(a[2]), "r"(a[3]), "r"(b[0]), "r"(b[1]));
}

// ---------------- split-fp16 MMA GEMM ----------------
// C[b] (M x N) = (Ah+Al)[b] @ (Bh+Bl)[b]
// NTERM 3: Ah·Bh + Ah·Bl + Al·Bh ; 2: Ah·Bh + Ah·Bl ; 1: Ah·Bh
// KPS: k32-tiles per pipeline stage (2 only allowed for NTERM==1).
// A row-major [M][K], B row-major [K][N], N == NPTS.
// CTA 128x128, 8 warps (warp tile 32x64), 3-stage cp.async, 2 CTAs/SM.
// EP_QK: fused q/k — blockIdx.y==0 -> q (A=W3, transposed coalesced store),
//        blockIdx.y==1 -> k (A=A2=W4, store into C2).
#define NSTG   3
#define STG_B  32768
#define SMEM_GEMM (NSTG * STG_B)      // 96 KiB dynamic -> 2 CTAs/SM

enum { EP_X1 = 0, EP_BNR = 1, EP_S = 3, EP_SUBDIV = 4, EP_FINAL = 5, EP_QK = 6 };

template<int EPI, bool ABATCH, int NTERM, int KPS>
__global__ void __launch_bounds__(256, 2)
mma_gemm(const fp16* __restrict__ Ahp, const fp16* __restrict__ Alp, size_t sA,
         const fp16* __restrict__ Bhp, const fp16* __restrict__ Blp, size_t sB,
         int M, int K,
         float* __restrict__ C32, fp16* __restrict__ Ch, fp16* __restrict__ Cl,
         const float* __restrict__ gg, const float* __restrict__ bb,
         const float* __restrict__ mm, const float* __restrict__ vv,
         const float* __restrict__ add, const float* __restrict__ rdiv,
         const fp16* __restrict__ A2h, const fp16* __restrict__ A2l,
         fp16* __restrict__ C2h, fp16* __restrict__ C2l,
         const float* __restrict__ gg2, const float* __restrict__ bb2,
         const float* __restrict__ mm2, const float* __restrict__ vv2)
{
    static_assert(KPS == 1 || NTERM == 1, "KPS=2 requires 1-term");
    extern __shared__ __align__(256) char smraw[];
    const uint32_t smb = s2u(smraw);
    const int tid  = threadIdx.x;
    const int lane = tid & 31;
    const int wid  = tid >> 5;
    const int m_w  = (wid & 3) * 32;     // warp M offset
    const int n_w  = (wid >> 2) * 64;    // warp N offset
    const int bz   = blockIdx.z;
    const int rowStart = blockIdx.y * 128;
    const int colStart = blockIdx.x * 128;
    const int N = NPTS;
    const bool isK2 = (EPI == EP_QK) && (blockIdx.y != 0);
    const int rowA = (EPI == EP_QK) ? 0 : rowStart;   // per-matrix local rows

    const fp16* Asel_h = isK2 ? A2h : Ahp;
    const fp16* Asel_l = isK2 ? A2l : Alp;
    const fp16* Ah_ = Asel_h + (ABATCH ? (size_t)bz * sA : 0);
    const fp16* Al_ = Asel_l + (ABATCH ? (size_t)bz * sA : 0);
    const fp16* Bh_ = Bhp + (size_t)bz * sB;
    const fp16* Bl_ = Blp + (size_t)bz * sB;

    float acc[2][8][4];
#pragma unroll
    for (int i = 0; i < 2; i++)
#pragma unroll
        for (int j = 0; j < 8; j++)
#pragma unroll
            for (int r = 0; r < 4; r++) acc[i][j][r] = 0.f;

    // stage layout:
    //   KPS=1: Ah @0 | Al @8192 | Bh @16384 | Bl @24576
    //   KPS=2 (1-term): A0 @0 | A1 @8192 | B0 @16384 | B1 @24576
    auto loadStage = [&](int t) {
        const int s = t % NSTG;
        const uint32_t base = smb + (uint32_t)s * STG_B;
        const int k0 = t * 32 * KPS;
#pragma unroll
        for (int sub = 0; sub < KPS; sub++) {
#pragma unroll
            for (int i = 0; i < 2; i++) {        // A: 128 rows x 4 chunks (16B)
                int idx = tid + i * 256;
                int row = idx >> 2, c = idx & 3;
                uint32_t off = (uint32_t)(row * 64 + ((c ^ ((row >> 1) & 3)) << 4));
                size_t go = (size_t)(rowA + row) * K + k0 + sub * 32 + c * 8;
                cp16(base + (uint32_t)sub * 8192 + off, Ah_ + go);
                if (NTERM >= 3) cp16(base + 8192 + off, Al_ + go);
            }
#pragma unroll
            for (int i = 0; i < 2; i++) {        // B: 32 rows x 16 chunks
                int idx = tid + i * 256;
                int k = idx >> 4, cn = idx & 15;
                uint32_t off = (uint32_t)(k * 256 + ((cn ^ (k & 7)) << 4));
                size_t go = (size_t)(k0 + sub * 32 + k) * N + colStart + cn * 8;
                cp16(base + 16384 + (uint32_t)sub * 8192 + off, Bh_ + go);
                if (NTERM >= 2) cp16(base + 24576 + off, Bl_ + go);
            }
        }
        CP_COMMIT();
    };

    const int T = K / (32 * KPS);
    const int P = (T < 2) ? T : 2;
    for (int t = 0; t < P; t++) loadStage(t);

    for (int t = 0; t < T; t++) {
        if (t + 1 < T) { CP_WAIT(1); } else { CP_WAIT(0); }
        __syncthreads();
        // top barrier of tile t also protects stage (t-1) from the overwrite
        // issued below (loadStage(t+2) targets stage (t+2)%3 == (t-1)%3).
        if (t + 2 < T) loadStage(t + 2);

        const uint32_t Ab = smb + (uint32_t)(t % NSTG) * STG_B;
#pragma unroll
        for (int kk = 0; kk < 2 * KPS; kk++) {
            const int sub = kk >> 1;
            const int ks  = kk & 1;
            const uint32_t Asub = Ab + (uint32_t)sub * 8192;
            const uint32_t Bsub = Ab + 16384 + (uint32_t)sub * 8192;
            uint32_t ah[2][4], al[2][4];
#pragma unroll
            for (int i = 0; i < 2; i++) {
                int row = m_w + i * 16 + (lane & 15);
                int c = ks * 2 + (lane >> 4);
                uint32_t off = (uint32_t)(row * 64 + ((c ^ ((row >> 1) & 3)) << 4));
                ldsm4(ah[i], Asub + off);
                if (NTERM >= 3) ldsm4(al[i], Asub + 8192 + off);
            }
#pragma unroll
            for (int p = 0; p < 4; p++) {
                int g = lane >> 3, j8 = lane & 7;
                int k = ks * 16 + (g & 1) * 8 + j8;
                int cn = (n_w >> 3) + p * 2 + (g >> 1);
                uint32_t off = (uint32_t)(k * 256 + ((cn ^ (k & 7)) << 4));
                uint32_t bh[4], bl[4];
                ldsm4t(bh, Bsub + off);
                if (NTERM >= 2) ldsm4t(bl, Bsub + 8192 + off);
                // term-major order: 4 independent MMAs per term group
                // (per-accumulator term order unchanged -> identical numerics)
#pragma unroll
                for (int i = 0; i < 2; i++) {
                    mma16816(acc[i][2 * p],     ah[i], bh);
                    mma16816(acc[i][2 * p + 1], ah[i], bh + 2);
                }
                if (NTERM >= 2) {
#pragma unroll
                    for (int i = 0; i < 2; i++) {
                        mma16816(acc[i][2 * p],     ah[i], bl);
                        mma16816(acc[i][2 * p + 1], ah[i], bl + 2);
                    }
                }
                if (NTERM >= 3) {
#pragma unroll
                    for (int i = 0; i < 2; i++) {
                        mma16816(acc[i][2 * p],     al[i], bh);
                        mma16816(acc[i][2 * p + 1], al[i], bh + 2);
                    }
                }
            }
        }
    }

    // ---------------- epilogue ----------------
    __shared__ float s_scl[128], s_off[128];
    if (EPI == EP_X1 || EPI == EP_BNR || EPI == EP_QK || EPI == EP_FINAL) {
        __syncthreads();              // also: all warps out of mainloop smem
        if (tid < 128) {
            const float* G = (EPI == EP_QK && isK2) ? gg2 : gg;
            const float* B = (EPI == EP_QK && isK2) ? bb2 : bb;
            const float* Mn = (EPI == EP_QK && isK2) ? mm2 : mm;
            const float* V = (EPI == EP_QK && isK2) ? vv2 : vv;
            int rg = rowA + tid;   // local channel for EP_QK, global row else
            float inv = rsqrtf(V[rg] + EPS_BN);
            float sc = G[rg] * inv;
            s_scl[tid] = sc;
            s_off[tid] = B[rg] - Mn[rg] * sc;
        }
        __syncthreads();
    }

    if (EPI == EP_QK) {
        if (!isK2) {
            // q: stage BN+ReLU'd values transposed into padded smem, then
            // copy out fully coalesced (output block is contiguous 128x128).
            fp16* sq  = reinterpret_cast<fp16*>(smraw);            // [128][136]
            fp16* sql = reinterpret_cast<fp16*>(smraw + 34816);    // [128][136]
#pragma unroll
            for (int i = 0; i < 2; i++)
#pragma unroll
                for (int j = 0; j < 8; j++)
#pragma unroll
                    for (int hseg = 0; hseg < 2; hseg++) {
                        const int rl = m_w + i * 16 + (lane >> 2) + hseg * 8; // channel
                        const int cl = n_w + j * 8 + (lane & 3) * 2;          // point
                        const float sc = s_scl[rl], of = s_off[rl];
                        float z0 = fmaxf(acc[i][j][hseg * 2]     * sc + of, 0.f);
                        float z1 = fmaxf(acc[i][j][hseg * 2 + 1] * sc + of, 0.f);
                        fp16 h0 = __float2half_rn(z0), h1 = __float2half_rn(z1);
                        sq [(cl + 0) * 136 + rl] = h0;
                        sq [(cl + 1) * 136 + rl] = h1;
                        sql[(cl + 0) * 136 + rl] = __float2half_rn(z0 - __half2float(h0));
                        sql[(cl + 1) * 136 + rl] = __float2half_rn(z1 - __half2float(h1));
                    }
            __syncthreads();
            const size_t baseq = (size_t)bz * ((size_t)NPTS * CQK)
                               + (size_t)colStart * CQK;
#pragma unroll
            for (int kx = 0; kx < 8; kx++) {
                int idx = tid + kx * 256;
                int pt = idx >> 4, c8 = idx & 15;
                uint4 v4 = *reinterpret_cast<const uint4*>(sq + pt * 136 + c8 * 8);
                *reinterpret_cast<uint4*>(Ch + baseq + (size_t)pt * CQK + c8 * 8) = v4;
                uint4 w4 = *reinterpret_cast<const uint4*>(sql + pt * 136 + c8 * 8);
                *reinterpret_cast<uint4*>(Cl + baseq + (size_t)pt * CQK + c8 * 8) = w4;
            }
        } else {
            // k: [channel][point] half2 stores
#pragma unroll
            for (int i = 0; i < 2; i++)
#pragma unroll
                for (int j = 0; j < 8; j++)
#pragma unroll
                    for (int hseg = 0; hseg < 2; hseg++) {
                        const int rl = m_w + i * 16 + (lane >> 2) + hseg * 8;
                        const int cl = n_w + j * 8 + (lane & 3) * 2;
                        const float sc = s_scl[rl], of = s_off[rl];
                        float z0 = fmaxf(acc[i][j][hseg * 2]     * sc + of, 0.f);
                        float z1 = fmaxf(acc[i][j][hseg * 2 + 1] * sc + of, 0.f);
                        fp16 h0 = __float2half_rn(z0), h1 = __float2half_rn(z1);
                        size_t ok = (size_t)bz * ((size_t)CQK * NPTS)
                                  + (size_t)rl * N + colStart + cl;
                        *(__half2*)(C2h + ok) = __halves2half2(h0, h1);
                        *(__half2*)(C2l + ok) = __halves2half2(
                            __float2half_rn(z0 - __half2float(h0)),
                            __float2half_rn(z1 - __half2float(h1)));
                    }
        }
        return;
    }

    const bool wantLo = (Cl != nullptr);
    const size_t sC = (size_t)M * N;
#pragma unroll
    for (int i = 0; i < 2; i++) {
#pragma unroll
        for (int j = 0; j < 8; j++) {
#pragma unroll
            for (int hseg = 0; hseg < 2; hseg++) {
                const int rl = m_w + i * 16 + (lane >> 2) + hseg * 8;
                const int cl = n_w + j * 8 + (lane & 3) * 2;
                const float y0 = acc[i][j][hseg * 2];
                const float y1 = acc[i][j][hseg * 2 + 1];
                const int rg = rowStart + rl;
                const int cg = colStart + cl;
                const size_t o = (size_t)bz * sC + (size_t)rg * N + cg;

                if (EPI == EP_S) {
                    float2 v2; v2.x = y0; v2.y = y1;
                    *(float2*)(C32 + o) = v2;
                } else if (EPI == EP_SUBDIV) {
                    float2 ad  = *(const float2*)(add + o);
                    float2 rdv = *(const float2*)(rdiv + (size_t)bz * N + cg);
                    float z0 = ad.x - y0 * rdv.x;
                    float z1 = ad.y - y1 * rdv.y;
                    fp16 h0 = __float2half_rn(z0), h1 = __float2half_rn(z1);
                    *(__half2*)(Ch + o) = __halves2half2(h0, h1);
                    if (wantLo)
                        *(__half2*)(Cl + o) = __halves2half2(
                            __float2half_rn(z0 - __half2float(h0)),
                            __float2half_rn(z1 - __half2float(h1)));
                } else {
                    const float sc = s_scl[rl], of = s_off[rl];
                    float z0 = fmaxf(y0 * sc + of, 0.f);
                    float z1 = fmaxf(y1 * sc + of, 0.f);
                    if (EPI == EP_FINAL) {
                        float2 ad = *(const float2*)(add + o);
                        float2 v2; v2.x = ad.x + z0; v2.y = ad.y + z1;
                        *(float2*)(C32 + o) = v2;
                    } else {
                        if (EPI == EP_X1) {
                            float2 v2; v2.x = z0; v2.y = z1;
                            *(float2*)(C32 + o) = v2;
                        }
                        fp16 h0 = __float2half_rn(z0), h1 = __float2half_rn(z1);
                        *(__half2*)(Ch + o) = __halves2half2(h0, h1);
                        if (wantLo)
                            *(__half2*)(Cl + o) = __halves2half2(
                                __float2half_rn(z0 - __half2float(h0)),
                                __float2half_rn(z1 - __half2float(h1)));
                    }
                }
            }
        }
    }
}

// ---------------- merged fp32 -> fp16 hi/lo split of all inputs ----------------
#define NX (BATCH * CH * NPTS)
#define NW (CH * CH)
#define NQW (CQK * CH)

__global__ void __launch_bounds__(256)
split_all(const float* __restrict__ x,  fp16* __restrict__ xh,  fp16* __restrict__ xl,
          const float* __restrict__ W1, fp16* __restrict__ W1h, fp16* __restrict__ W1l,
          const float* __restrict__ W2, fp16* __restrict__ W2h, fp16* __restrict__ W2l,
          const float* __restrict__ W3, fp16* __restrict__ W3h, fp16* __restrict__ W3l,
          const float* __restrict__ W4, fp16* __restrict__ W4h, fp16* __restrict__ W4l,
          const float* __restrict__ W5, fp16* __restrict__ W5h, fp16* __restrict__ W5l)
{
    size_t i = (size_t)blockIdx.x * 256 + threadIdx.x;
    const float* in; fp16 *oh, *ol; size_t li;
    if (i < NX)                       { in = x;  oh = xh;  ol = xl;  li = i; }
    else if (i < NX + NW)             { in = W1; oh = W1h; ol = W1l; li = i - NX; }
    else if (i < NX + 2 * NW)         { in = W2; oh = W2h; ol = W2l; li = i - NX - NW; }
    else if (i < NX + 2 * NW + NQW)   { in = W3; oh = W3h; ol = W3l; li = i - NX - 2 * NW; }
    else if (i < NX + 2 * NW + 2*NQW) { in = W4; oh = W4h; ol = W4l; li = i - NX - 2 * NW - NQW; }
    else                              { in = W5; oh = W5h; ol = W5l; li = i - NX - 2 * NW - 2 * NQW; }
    float v = in[li];
    fp16 h = __float2half_rn(v);
    oh[li] = h;
    ol[li] = __float2half_rn(v - __half2float(h));
}

// ---------------- row softmax: fp32 in, fp16 (hi only) out ----------------
__global__ void __launch_bounds__(256)
softmax_kernel(const float* __restrict__ S, fp16* __restrict__ Sh)
{
    __shared__ float buf[NPTS];
    __shared__ float red[8];
    const float* p = S + (size_t)blockIdx.x * NPTS;
    fp16* ph = Sh + (size_t)blockIdx.x * NPTS;
    int t = threadIdx.x;

    float mx = -3.402823466e38f;
    for (int i = t; i < NPTS; i += 256) { float v = p[i]; buf[i] = v; mx = fmaxf(mx, v); }
#pragma unroll
    for (int o = 16; o > 0; o >>= 1) mx = fmaxf(mx, __shfl_xor_sync(0xffffffffu, mx, o));
    if ((t & 31) == 0) red[t >> 5] = mx;
    __syncthreads();
    float bm = red[0];
#pragma unroll
    for (int i = 1; i < 8; i++) bm = fmaxf(bm, red[i]);
    __syncthreads();

    float sum = 0.f;
    for (int i = t; i < NPTS; i += 256) { float e = __expf(buf[i] - bm); buf[i] = e; sum += e; }
#pragma unroll
    for (int o = 16; o > 0; o >>= 1) sum += __shfl_xor_sync(0xffffffffu, sum, o);
    if ((t & 31) == 0) red[t >> 5] = sum;
    __syncthreads();
    float bs = 0.f;
#pragma unroll
    for (int i = 0; i < 8; i++) bs += red[i];
    float inv = 1.0f / bs;
    for (int i = t; i < NPTS; i += 256)
        ph[i] = __float2half_rn(buf[i] * inv);
}

// ---------------- column sums of Sh -> 1/(eps+colsum) ----------------
__global__ void __launch_bounds__(256)
colsum_kernel(const fp16* __restrict__ Sh, float* __restrict__ rdiv)
{
    int idx = blockIdx.x * 256 + threadIdx.x;
    int b = idx / NPTS, m = idx - b * NPTS;
    const fp16* ph = Sh + (size_t)b * NPTS * NPTS + m;
    float s[4] = {0.f, 0.f, 0.f, 0.f};
    for (int n = 0; n < NPTS; n += 4) {
#pragma unroll
        for (int u = 0; u < 4; u++)
            s[u] += __half2float(ph[(size_t)(n + u) * NPTS]);
    }
    rdiv[idx] = 1.0f / (EPS_RENORM + ((s[0] + s[1]) + (s[2] + s[3])));
}

// ---------------- launch ----------------
#define NP8 nullptr, nullptr, nullptr, nullptr, nullptr, nullptr, nullptr, nullptr

extern "C" void kernel_launch(void* const* d_in, const int* in_sizes, int n_in,
                              void* d_out, int out_size)
{
    (void)in_sizes; (void)n_in; (void)out_size;
    const float* x  = (const float*)d_in[0];
    const float *W1 = (const float*)d_in[1],  *g1 = (const float*)d_in[2],
                *b1 = (const float*)d_in[3],  *m1 = (const float*)d_in[4],
                *v1 = (const float*)d_in[5];
    const float *W2 = (const float*)d_in[6],  *g2 = (const float*)d_in[7],
                *b2 = (const float*)d_in[8],  *m2 = (const float*)d_in[9],
                *v2 = (const float*)d_in[10];
    const float *W3 = (const float*)d_in[11], *g3 = (const float*)d_in[12],
                *b3 = (const float*)d_in[13], *m3 = (const float*)d_in[14],
                *v3 = (const float*)d_in[15];
    const float *W4 = (const float*)d_in[16], *g4 = (const float*)d_in[17],
                *b4 = (const float*)d_in[18], *m4 = (const float*)d_in[19],
                *v4 = (const float*)d_in[20];
    const float *W5 = (const float*)d_in[21], *g5 = (const float*)d_in[22],
                *b5 = (const float*)d_in[23], *m5 = (const float*)d_in[24],
                *v5 = (const float*)d_in[25];
    float* out = (float*)d_out;

    float *x1, *S, *rd;
    fp16 *xh, *xl, *x1h, *x1l, *vh, *th, *qh, *ql, *kh, *kl, *Sh;
    fp16 *W1h, *W1l, *W2h, *W2l, *W3h, *W3l, *W4h, *W4l, *W5h, *W5l;
    cudaGetSymbolAddress((void**)&x1, g_x1);
    cudaGetSymbolAddress((void**)&S,  g_S);
    cudaGetSymbolAddress((void**)&rd, g_rd);
    cudaGetSymbolAddress((void**)&xh, g_xh);   cudaGetSymbolAddress((void**)&xl, g_xl);
    cudaGetSymbolAddress((void**)&x1h, g_x1h); cudaGetSymbolAddress((void**)&x1l, g_x1l);
    cudaGetSymbolAddress((void**)&vh, g_vh);
    cudaGetSymbolAddress((void**)&th, g_th);
    cudaGetSymbolAddress((void**)&qh, g_qh);   cudaGetSymbolAddress((void**)&ql, g_ql);
    cudaGetSymbolAddress((void**)&kh, g_kh);   cudaGetSymbolAddress((void**)&kl, g_kl);
    cudaGetSymbolAddress((void**)&Sh, g_Sh);
    cudaGetSymbolAddress((void**)&W1h, g_W1h); cudaGetSymbolAddress((void**)&W1l, g_W1l);
    cudaGetSymbolAddress((void**)&W2h, g_W2h); cudaGetSymbolAddress((void**)&W2l, g_W2l);
    cudaGetSymbolAddress((void**)&W3h, g_W3h); cudaGetSymbolAddress((void**)&W3l, g_W3l);
    cudaGetSymbolAddress((void**)&W4h, g_W4h); cudaGetSymbolAddress((void**)&W4l, g_W4l);
    cudaGetSymbolAddress((void**)&W5h, g_W5h); cudaGetSymbolAddress((void**)&W5l, g_W5l);

    cudaFuncSetAttribute(mma_gemm<EP_X1, false, 3, 1>,    cudaFuncAttributeMaxDynamicSharedMemorySize, SMEM_GEMM);
    cudaFuncSetAttribute(mma_gemm<EP_BNR, false, 1, 2>,   cudaFuncAttributeMaxDynamicSharedMemorySize, SMEM_GEMM);
    cudaFuncSetAttribute(mma_gemm<EP_QK, false, 3, 1>,    cudaFuncAttributeMaxDynamicSharedMemorySize, SMEM_GEMM);
    cudaFuncSetAttribute(mma_gemm<EP_S, true, 3, 1>,      cudaFuncAttributeMaxDynamicSharedMemorySize, SMEM_GEMM);
    cudaFuncSetAttribute(mma_gemm<EP_SUBDIV, true, 1, 2>, cudaFuncAttributeMaxDynamicSharedMemorySize, SMEM_GEMM);
    cudaFuncSetAttribute(mma_gemm<EP_FINAL, false, 1, 2>, cudaFuncAttributeMaxDynamicSharedMemorySize, SMEM_GEMM);

    const size_t sX  = (size_t)CH * NPTS;
    const size_t sQT = (size_t)NPTS * CQK;
    const size_t sK  = (size_t)CQK * NPTS;
    const size_t sS  = (size_t)NPTS * NPTS;

    // 0) merged hi/lo split of x and all weights (1 launch)
    const int splitTotal = NX + 2 * NW + 2 * NQW + NW;
    split_all<<<splitTotal / 256, 256>>>(x, xh, xl, W1, W1h, W1l, W2, W2h, W2l,
                                         W3, W3h, W3l, W4, W4h, W4l, W5, W5h, W5l);
    // 1) x1 = relu(bn1(W1 @ x))           [3-term: softmax path]
    mma_gemm<EP_X1, false, 3, 1><<<dim3(16, 8, 8), 256, SMEM_GEMM>>>(
        W1h, W1l, 0, xh, xl, sX, CH, CH,
        x1, x1h, x1l, g1, b1, m1, v1, nullptr, nullptr, NP8);
    // 2) v = relu(bn2(W2 @ x1))           [1-term, BK=64]
    mma_gemm<EP_BNR, false, 1, 2><<<dim3(16, 8, 8), 256, SMEM_GEMM>>>(
        W2h, W2l, 0, x1h, x1l, sX, CH, CH,
        nullptr, vh, nullptr, g2, b2, m2, v2, nullptr, nullptr, NP8);
    // 3+4) fused q (y=0, transposed coalesced) + k (y=1)  [3-term]
    mma_gemm<EP_QK, false, 3, 1><<<dim3(16, 2, 8), 256, SMEM_GEMM>>>(
        W3h, W3l, 0, x1h, x1l, sX, CQK, CH,
        nullptr, qh, ql, g3, b3, m3, v3, nullptr, nullptr,
        W4h, W4l, kh, kl, g4, b4, m4, v4);
    // 5) scores S[n][m]                   [3-term: softmax exponent]
    mma_gemm<EP_S, true, 3, 1><<<dim3(16, 16, 8), 256, SMEM_GEMM>>>(
        qh, ql, sQT, kh, kl, sK, NPTS, CQK,
        S, nullptr, nullptr, nullptr, nullptr, nullptr, nullptr,
        nullptr, nullptr, NP8);
    // 6) row softmax -> fp16 hi only
    softmax_kernel<<<BATCH * NPTS, 256>>>(S, Sh);
    // 7) renorm divisor from Sh (consistent with GEMM operand)
    colsum_kernel<<<(BATCH * NPTS) / 256, 256>>>(Sh, rd);
    // 8) t = x1 - (v @ S) * rdiv[col]     [1-term vh·Sh, BK=64]
    mma_gemm<EP_SUBDIV, true, 1, 2><<<dim3(16, 8, 8), 256, SMEM_GEMM>>>(
        vh, vh, sX, Sh, Sh, sS, CH, NPTS,
        nullptr, th, nullptr, nullptr, nullptr, nullptr, nullptr, x1, rd, NP8);
    // 9) out = x1 + relu(bn5(W5 @ t))     [1-term W5h·th, BK=64]
    mma_gemm<EP_FINAL, false, 1, 2><<<dim3(16, 8, 8), 256, SMEM_GEMM>>>(
        W5h, W5l, 0, th, th, sX, CH, CH,
        out, nullptr, nullptr, g5, b5, m5, v5, x1, nullptr, NP8);
}

// round 16
// speedup vs baseline: 2.1640x; 1.0819x over previous
#include <cuda_runtime.h>
#include <cuda_fp16.h>
#include <cstdint>

#define EPS_BN 1e-5f
#define EPS_RENORM 1e-9f

#define BATCH 8
#define CH    1024
#define NPTS  2048
#define CQK   128

typedef __half fp16;

// ---------------- scratch (no allocations allowed) ----------------
__device__ float g_x1[BATCH * CH * NPTS];
__device__ float g_S [(size_t)BATCH * NPTS * NPTS];
__device__ float g_rd[BATCH * NPTS];
__device__ fp16 g_xh [BATCH * CH * NPTS], g_xl [BATCH * CH * NPTS];
__device__ fp16 g_x1h[BATCH * CH * NPTS], g_x1l[BATCH * CH * NPTS];
__device__ fp16 g_vh [BATCH * CH * NPTS];
__device__ fp16 g_th [BATCH * CH * NPTS];
__device__ fp16 g_qh [BATCH * NPTS * CQK];
__device__ fp16 g_kh [BATCH * CQK * NPTS], g_kl[BATCH * CQK * NPTS];
__device__ fp16 g_Sh [(size_t)BATCH * NPTS * NPTS];
__device__ fp16 g_W1h[CH * CH],  g_W1l[CH * CH];
__device__ fp16 g_W2h[CH * CH],  g_W2l[CH * CH];
__device__ fp16 g_W5h[CH * CH],  g_W5l[CH * CH];
__device__ fp16 g_W3h[CQK * CH], g_W3l[CQK * CH];
__device__ fp16 g_W4h[CQK * CH], g_W4l[CQK * CH];

// ---------------- PTX helpers ----------------
__device__ __forceinline__ uint32_t s2u(const void* p) {
    uint32_t a;
    asm("{ .reg .u64 t; cvta.to.shared.u64 t, %1; cvt.u32.u64 %0, t; }"
        : "=r"(a) : "l"(p));
    return a;
}
__device__ __forceinline__ void cp16(uint32_t saddr, const void* g) {
    asm volatile("cp.async.cg.shared.global [%0], [%1], 16;"
                 :: "r"(saddr), "l"(g) : "memory");
}
#define CP_COMMIT() asm volatile("cp.async.commit_group;" ::: "memory")
#define CP_WAIT(n)  asm volatile("cp.async.wait_group %0;" :: "n"(n) : "memory")

__device__ __forceinline__ void ldsm4(uint32_t* r, uint32_t a) {
    asm volatile("ldmatrix.sync.aligned.m8n8.x4.shared.b16 {%0,%1,%2,%3}, [%4];"
                 : "=r"(r[0]), "=r"(r[1]), "=r"(r[2]), "=r"(r[3]) : "r"(a));
}
__device__ __forceinline__ void ldsm4t(uint32_t* r, uint32_t a) {
    asm volatile("ldmatrix.sync.aligned.m8n8.x4.trans.shared.b16 {%0,%1,%2,%3}, [%4];"
                 : "=r"(r[0]), "=r"(r[1]), "=r"(r[2]), "=r"(r[3]) : "r"(a));
}
__device__ __forceinline__ void mma16816(float* d, const uint32_t* a, const uint32_t* b) {
    asm volatile("mma.sync.aligned.m16n8k16.row.col.f32.f16.f16.f32 "
                 "{%0,%1,%2,%3}, {%4,%5,%6,%7}, {%8,%9}, {%0,%1,%2,%3};"
                 : "+f"(d[0]), "+f"(d[1]), "+f"(d[2]), "+f"(d[3])
                 : "r"(a[0]), "r"(a[1]), "r"(a[2]), "r"(a[3]), "r"(b[0]), "r"(b[1]));
}

// ---------------- split-fp16 MMA GEMM ----------------
// C[b] (M x N) = (Ah+Al)[b] @ (Bh+Bl)[b]
// NTERM 3: Ah·Bh + Ah·Bl + Al·Bh ; 2: Ah·Bh + Ah·Bl ; 1: Ah·Bh
// KPS: k32-tiles per pipeline stage (2 only allowed for NTERM==1).
// A row-major [M][K], B row-major [K][N], N == NPTS.
// CTA 128x128, 8 warps (warp tile 32x64), 3-stage cp.async, 2 CTAs/SM.
// EP_QK: fused q/k — blockIdx.y==0 -> q (A=W3, transposed coalesced store),
//        blockIdx.y==1 -> k (A=A2=W4, store into C2).
#define NSTG   3
#define STG_B  32768
#define SMEM_GEMM (NSTG * STG_B)      // 96 KiB dynamic -> 2 CTAs/SM

enum { EP_X1 = 0, EP_BNR = 1, EP_S = 3, EP_SUBDIV = 4, EP_FINAL = 5, EP_QK = 6 };

template<int EPI, bool ABATCH, int NTERM, int KPS>
__global__ void __launch_bounds__(256, 2)
mma_gemm(const fp16* __restrict__ Ahp, const fp16* __restrict__ Alp, size_t sA,
         const fp16* __restrict__ Bhp, const fp16* __restrict__ Blp, size_t sB,
         int M, int K,
         float* __restrict__ C32, fp16* __restrict__ Ch, fp16* __restrict__ Cl,
         const float* __restrict__ gg, const float* __restrict__ bb,
         const float* __restrict__ mm, const float* __restrict__ vv,
         const float* __restrict__ add, const float* __restrict__ rdiv,
         const fp16* __restrict__ A2h, const fp16* __restrict__ A2l,
         fp16* __restrict__ C2h, fp16* __restrict__ C2l,
         const float* __restrict__ gg2, const float* __restrict__ bb2,
         const float* __restrict__ mm2, const float* __restrict__ vv2)
{
    static_assert(KPS == 1 || NTERM == 1, "KPS=2 requires 1-term");
    extern __shared__ __align__(256) char smraw[];
    const uint32_t smb = s2u(smraw);
    const int tid  = threadIdx.x;
    const int lane = tid & 31;
    const int wid  = tid >> 5;
    const int m_w  = (wid & 3) * 32;     // warp M offset
    const int n_w  = (wid >> 2) * 64;    // warp N offset
    const int bz   = blockIdx.z;
    const int rowStart = blockIdx.y * 128;
    const int colStart = blockIdx.x * 128;
    const int N = NPTS;
    const bool isK2 = (EPI == EP_QK) && (blockIdx.y != 0);
    const int rowA = (EPI == EP_QK) ? 0 : rowStart;   // per-matrix local rows

    const fp16* Asel_h = isK2 ? A2h : Ahp;
    const fp16* Asel_l = isK2 ? A2l : Alp;
    const fp16* Ah_ = Asel_h + (ABATCH ? (size_t)bz * sA : 0);
    const fp16* Al_ = Asel_l + (ABATCH ? (size_t)bz * sA : 0);
    const fp16* Bh_ = Bhp + (size_t)bz * sB;
    const fp16* Bl_ = Blp + (size_t)bz * sB;

    float acc[2][8][4];
#pragma unroll
    for (int i = 0; i < 2; i++)
#pragma unroll
        for (int j = 0; j < 8; j++)
#pragma unroll
            for (int r = 0; r < 4; r++) acc[i][j][r] = 0.f;

    // stage layout:
    //   KPS=1: Ah @0 | Al @8192 | Bh @16384 | Bl @24576
    //   KPS=2 (1-term): A0 @0 | A1 @8192 | B0 @16384 | B1 @24576
    auto loadStage = [&](int t) {
        const int s = t % NSTG;
        const uint32_t base = smb + (uint32_t)s * STG_B;
        const int k0 = t * 32 * KPS;
#pragma unroll
        for (int sub = 0; sub < KPS; sub++) {
#pragma unroll
            for (int i = 0; i < 2; i++) {        // A: 128 rows x 4 chunks (16B)
                int idx = tid + i * 256;
                int row = idx >> 2, c = idx & 3;
                uint32_t off = (uint32_t)(row * 64 + ((c ^ ((row >> 1) & 3)) << 4));
                size_t go = (size_t)(rowA + row) * K + k0 + sub * 32 + c * 8;
                cp16(base + (uint32_t)sub * 8192 + off, Ah_ + go);
                if (NTERM >= 3) cp16(base + 8192 + off, Al_ + go);
            }
#pragma unroll
            for (int i = 0; i < 2; i++) {        // B: 32 rows x 16 chunks
                int idx = tid + i * 256;
                int k = idx >> 4, cn = idx & 15;
                uint32_t off = (uint32_t)(k * 256 + ((cn ^ (k & 7)) << 4));
                size_t go = (size_t)(k0 + sub * 32 + k) * N + colStart + cn * 8;
                cp16(base + 16384 + (uint32_t)sub * 8192 + off, Bh_ + go);
                if (NTERM >= 2) cp16(base + 24576 + off, Bl_ + go);
            }
        }
        CP_COMMIT();
    };

    const int T = K / (32 * KPS);
    const int P = (T < 2) ? T : 2;
    for (int t = 0; t < P; t++) loadStage(t);

    for (int t = 0; t < T; t++) {
        if (t + 1 < T) { CP_WAIT(1); } else { CP_WAIT(0); }
        __syncthreads();
        // top barrier of tile t also protects stage (t-1) from the overwrite
        // issued below (loadStage(t+2) targets stage (t+2)%3 == (t-1)%3).
        if (t + 2 < T) loadStage(t + 2);

        const uint32_t Ab = smb + (uint32_t)(t % NSTG) * STG_B;
#pragma unroll
        for (int kk = 0; kk < 2 * KPS; kk++) {
            const int sub = kk >> 1;
            const int ks  = kk & 1;
            const uint32_t Asub = Ab + (uint32_t)sub * 8192;
            const uint32_t Bsub = Ab + 16384 + (uint32_t)sub * 8192;
            uint32_t ah[2][4], al[2][4];
#pragma unroll
            for (int i = 0; i < 2; i++) {
                int row = m_w + i * 16 + (lane & 15);
                int c = ks * 2 + (lane >> 4);
                uint32_t off = (uint32_t)(row * 64 + ((c ^ ((row >> 1) & 3)) << 4));
                ldsm4(ah[i], Asub + off);
                if (NTERM >= 3) ldsm4(al[i], Asub + 8192 + off);
            }
#pragma unroll
            for (int p = 0; p < 4; p++) {
                int g = lane >> 3, j8 = lane & 7;
                int k = ks * 16 + (g & 1) * 8 + j8;
                int cn = (n_w >> 3) + p * 2 + (g >> 1);
                uint32_t off = (uint32_t)(k * 256 + ((cn ^ (k & 7)) << 4));
                uint32_t bh[4], bl[4];
                ldsm4t(bh, Bsub + off);
                if (NTERM >= 2) ldsm4t(bl, Bsub + 8192 + off);
                // term-major order: independent MMA groups (numerics unchanged
                // per accumulator)
#pragma unroll
                for (int i = 0; i < 2; i++) {
                    mma16816(acc[i][2 * p],     ah[i], bh);
                    mma16816(acc[i][2 * p + 1], ah[i], bh + 2);
                }
                if (NTERM >= 2) {
#pragma unroll
                    for (int i = 0; i < 2; i++) {
                        mma16816(acc[i][2 * p],     ah[i], bl);
                        mma16816(acc[i][2 * p + 1], ah[i], bl + 2);
                    }
                }
                if (NTERM >= 3) {
#pragma unroll
                    for (int i = 0; i < 2; i++) {
                        mma16816(acc[i][2 * p],     al[i], bh);
                        mma16816(acc[i][2 * p + 1], al[i], bh + 2);
                    }
                }
            }
        }
    }

    // ---------------- epilogue ----------------
    __shared__ float s_scl[128], s_off[128];
    if (EPI == EP_X1 || EPI == EP_BNR || EPI == EP_QK || EPI == EP_FINAL) {
        __syncthreads();              // all warps out of mainloop smem
        if (tid < 128) {
            const float* G = (EPI == EP_QK && isK2) ? gg2 : gg;
            const float* B = (EPI == EP_QK && isK2) ? bb2 : bb;
            const float* Mn = (EPI == EP_QK && isK2) ? mm2 : mm;
            const float* V = (EPI == EP_QK && isK2) ? vv2 : vv;
            int rg = rowA + tid;   // local channel for EP_QK, global row else
            float inv = rsqrtf(V[rg] + EPS_BN);
            float sc = G[rg] * inv;
            s_scl[tid] = sc;
            s_off[tid] = B[rg] - Mn[rg] * sc;
        }
        __syncthreads();
    }

    if (EPI == EP_QK) {
        if (!isK2) {
            // q: stage BN+ReLU'd values transposed into padded smem, then
            // copy out fully coalesced (hi only — scores GEMM is 2-term and
            // never reads q-lo).
            fp16* sq = reinterpret_cast<fp16*>(smraw);             // [128][136]
#pragma unroll
            for (int i = 0; i < 2; i++)
#pragma unroll
                for (int j = 0; j < 8; j++)
#pragma unroll
                    for (int hseg = 0; hseg < 2; hseg++) {
                        const int rl = m_w + i * 16 + (lane >> 2) + hseg * 8; // channel
                        const int cl = n_w + j * 8 + (lane & 3) * 2;          // point
                        const float sc = s_scl[rl], of = s_off[rl];
                        float z0 = fmaxf(acc[i][j][hseg * 2]     * sc + of, 0.f);
                        float z1 = fmaxf(acc[i][j][hseg * 2 + 1] * sc + of, 0.f);
                        sq[(cl + 0) * 136 + rl] = __float2half_rn(z0);
                        sq[(cl + 1) * 136 + rl] = __float2half_rn(z1);
                    }
            __syncthreads();
            const size_t baseq = (size_t)bz * ((size_t)NPTS * CQK)
                               + (size_t)colStart * CQK;
#pragma unroll
            for (int kx = 0; kx < 8; kx++) {
                int idx = tid + kx * 256;
                int pt = idx >> 4, c8 = idx & 15;
                uint4 v4 = *reinterpret_cast<const uint4*>(sq + pt * 136 + c8 * 8);
                *reinterpret_cast<uint4*>(Ch + baseq + (size_t)pt * CQK + c8 * 8) = v4;
            }
        } else {
            // k: [channel][point] half2 stores, hi + lo (scores reads both)
#pragma unroll
            for (int i = 0; i < 2; i++)
#pragma unroll
                for (int j = 0; j < 8; j++)
#pragma unroll
                    for (int hseg = 0; hseg < 2; hseg++) {
                        const int rl = m_w + i * 16 + (lane >> 2) + hseg * 8;
                        const int cl = n_w + j * 8 + (lane & 3) * 2;
                        const float sc = s_scl[rl], of = s_off[rl];
                        float z0 = fmaxf(acc[i][j][hseg * 2]     * sc + of, 0.f);
                        float z1 = fmaxf(acc[i][j][hseg * 2 + 1] * sc + of, 0.f);
                        fp16 h0 = __float2half_rn(z0), h1 = __float2half_rn(z1);
                        size_t ok = (size_t)bz * ((size_t)CQK * NPTS)
                                  + (size_t)rl * N + colStart + cl;
                        *(__half2*)(C2h + ok) = __halves2half2(h0, h1);
                        *(__half2*)(C2l + ok) = __halves2half2(
                            __float2half_rn(z0 - __half2float(h0)),
                            __float2half_rn(z1 - __half2float(h1)));
                    }
        }
        return;
    }

    const bool wantLo = (Cl != nullptr);
    const size_t sC = (size_t)M * N;
#pragma unroll
    for (int i = 0; i < 2; i++) {
#pragma unroll
        for (int j = 0; j < 8; j++) {
#pragma unroll
            for (int hseg = 0; hseg < 2; hseg++) {
                const int rl = m_w + i * 16 + (lane >> 2) + hseg * 8;
                const int cl = n_w + j * 8 + (lane & 3) * 2;
                const float y0 = acc[i][j][hseg * 2];
                const float y1 = acc[i][j][hseg * 2 + 1];
                const int rg = rowStart + rl;
                const int cg = colStart + cl;
                const size_t o = (size_t)bz * sC + (size_t)rg * N + cg;

                if (EPI == EP_S) {
                    float2 v2; v2.x = y0; v2.y = y1;
                    *(float2*)(C32 + o) = v2;
                } else if (EPI == EP_SUBDIV) {
                    float2 ad  = *(const float2*)(add + o);
                    float2 rdv = *(const float2*)(rdiv + (size_t)bz * N + cg);
                    float z0 = ad.x - y0 * rdv.x;
                    float z1 = ad.y - y1 * rdv.y;
                    fp16 h0 = __float2half_rn(z0), h1 = __float2half_rn(z1);
                    *(__half2*)(Ch + o) = __halves2half2(h0, h1);
                    if (wantLo)
                        *(__half2*)(Cl + o) = __halves2half2(
                            __float2half_rn(z0 - __half2float(h0)),
                            __float2half_rn(z1 - __half2float(h1)));
                } else {
                    const float sc = s_scl[rl], of = s_off[rl];
                    float z0 = fmaxf(y0 * sc + of, 0.f);
                    float z1 = fmaxf(y1 * sc + of, 0.f);
                    if (EPI == EP_FINAL) {
                        float2 ad = *(const float2*)(add + o);
                        float2 v2; v2.x = ad.x + z0; v2.y = ad.y + z1;
                        *(float2*)(C32 + o) = v2;
                    } else {
                        if (EPI == EP_X1) {
                            float2 v2; v2.x = z0; v2.y = z1;
                            *(float2*)(C32 + o) = v2;
                        }
                        fp16 h0 = __float2half_rn(z0), h1 = __float2half_rn(z1);
                        *(__half2*)(Ch + o) = __halves2half2(h0, h1);
                        if (wantLo)
                            *(__half2*)(Cl + o) = __halves2half2(
                                __float2half_rn(z0 - __half2float(h0)),
                                __float2half_rn(z1 - __half2float(h1)));
                    }
                }
            }
        }
    }
}

// ---------------- merged fp32 -> fp16 hi/lo split of all inputs ----------------
#define NX (BATCH * CH * NPTS)
#define NW (CH * CH)
#define NQW (CQK * CH)

__global__ void __launch_bounds__(256)
split_all(const float* __restrict__ x,  fp16* __restrict__ xh,  fp16* __restrict__ xl,
          const float* __restrict__ W1, fp16* __restrict__ W1h, fp16* __restrict__ W1l,
          const float* __restrict__ W2, fp16* __restrict__ W2h, fp16* __restrict__ W2l,
          const float* __restrict__ W3, fp16* __restrict__ W3h, fp16* __restrict__ W3l,
          const float* __restrict__ W4, fp16* __restrict__ W4h, fp16* __restrict__ W4l,
          const float* __restrict__ W5, fp16* __restrict__ W5h, fp16* __restrict__ W5l)
{
    size_t i = (size_t)blockIdx.x * 256 + threadIdx.x;
    const float* in; fp16 *oh, *ol; size_t li;
    if (i < NX)                       { in = x;  oh = xh;  ol = xl;  li = i; }
    else if (i < NX + NW)             { in = W1; oh = W1h; ol = W1l; li = i - NX; }
    else if (i < NX + 2 * NW)         { in = W2; oh = W2h; ol = W2l; li = i - NX - NW; }
    else if (i < NX + 2 * NW + NQW)   { in = W3; oh = W3h; ol = W3l; li = i - NX - 2 * NW; }
    else if (i < NX + 2 * NW + 2*NQW) { in = W4; oh = W4h; ol = W4l; li = i - NX - 2 * NW - NQW; }
    else                              { in = W5; oh = W5h; ol = W5l; li = i - NX - 2 * NW - 2 * NQW; }
    float v = in[li];
    fp16 h = __float2half_rn(v);
    oh[li] = h;
    ol[li] = __float2half_rn(v - __half2float(h));
}

// ---------------- row softmax: fp32 in, fp16 (hi only) out ----------------
__global__ void __launch_bounds__(256)
softmax_kernel(const float* __restrict__ S, fp16* __restrict__ Sh)
{
    __shared__ float buf[NPTS];
    __shared__ float red[8];
    const float* p = S + (size_t)blockIdx.x * NPTS;
    fp16* ph = Sh + (size_t)blockIdx.x * NPTS;
    int t = threadIdx.x;

    float mx = -3.402823466e38f;
    for (int i = t; i < NPTS; i += 256) { float v = p[i]; buf[i] = v; mx = fmaxf(mx, v); }
#pragma unroll
    for (int o = 16; o > 0; o >>= 1) mx = fmaxf(mx, __shfl_xor_sync(0xffffffffu, mx, o));
    if ((t & 31) == 0) red[t >> 5] = mx;
    __syncthreads();
    float bm = red[0];
#pragma unroll
    for (int i = 1; i < 8; i++) bm = fmaxf(bm, red[i]);
    __syncthreads();

    float sum = 0.f;
    for (int i = t; i < NPTS; i += 256) { float e = __expf(buf[i] - bm); buf[i] = e; sum += e; }
#pragma unroll
    for (int o = 16; o > 0; o >>= 1) sum += __shfl_xor_sync(0xffffffffu, sum, o);
    if ((t & 31) == 0) red[t >> 5] = sum;
    __syncthreads();
    float bs = 0.f;
#pragma unroll
    for (int i = 0; i < 8; i++) bs += red[i];
    float inv = 1.0f / bs;
    for (int i = t; i < NPTS; i += 256)
        ph[i] = __float2half_rn(buf[i] * inv);
}

// ---------------- column sums of Sh -> 1/(eps+colsum) ----------------
__global__ void __launch_bounds__(256)
colsum_kernel(const fp16* __restrict__ Sh, float* __restrict__ rdiv)
{
    int idx = blockIdx.x * 256 + threadIdx.x;
    int b = idx / NPTS, m = idx - b * NPTS;
    const fp16* ph = Sh + (size_t)b * NPTS * NPTS + m;
    float s[4] = {0.f, 0.f, 0.f, 0.f};
    for (int n = 0; n < NPTS; n += 4) {
#pragma unroll
        for (int u = 0; u < 4; u++)
            s[u] += __half2float(ph[(size_t)(n + u) * NPTS]);
    }
    rdiv[idx] = 1.0f / (EPS_RENORM + ((s[0] + s[1]) + (s[2] + s[3])));
}

// ---------------- launch ----------------
#define NP8 nullptr, nullptr, nullptr, nullptr, nullptr, nullptr, nullptr, nullptr

extern "C" void kernel_launch(void* const* d_in, const int* in_sizes, int n_in,
                              void* d_out, int out_size)
{
    (void)in_sizes; (void)n_in; (void)out_size;
    const float* x  = (const float*)d_in[0];
    const float *W1 = (const float*)d_in[1],  *g1 = (const float*)d_in[2],
                *b1 = (const float*)d_in[3],  *m1 = (const float*)d_in[4],
                *v1 = (const float*)d_in[5];
    const float *W2 = (const float*)d_in[6],  *g2 = (const float*)d_in[7],
                *b2 = (const float*)d_in[8],  *m2 = (const float*)d_in[9],
                *v2 = (const float*)d_in[10];
    const float *W3 = (const float*)d_in[11], *g3 = (const float*)d_in[12],
                *b3 = (const float*)d_in[13], *m3 = (const float*)d_in[14],
                *v3 = (const float*)d_in[15];
    const float *W4 = (const float*)d_in[16], *g4 = (const float*)d_in[17],
                *b4 = (const float*)d_in[18], *m4 = (const float*)d_in[19],
                *v4 = (const float*)d_in[20];
    const float *W5 = (const float*)d_in[21], *g5 = (const float*)d_in[22],
                *b5 = (const float*)d_in[23], *m5 = (const float*)d_in[24],
                *v5 = (const float*)d_in[25];
    float* out = (float*)d_out;

    float *x1, *S, *rd;
    fp16 *xh, *xl, *x1h, *x1l, *vh, *th, *qh, *kh, *kl, *Sh;
    fp16 *W1h, *W1l, *W2h, *W2l, *W3h, *W3l, *W4h, *W4l, *W5h, *W5l;
    cudaGetSymbolAddress((void**)&x1, g_x1);
    cudaGetSymbolAddress((void**)&S,  g_S);
    cudaGetSymbolAddress((void**)&rd, g_rd);
    cudaGetSymbolAddress((void**)&xh, g_xh);   cudaGetSymbolAddress((void**)&xl, g_xl);
    cudaGetSymbolAddress((void**)&x1h, g_x1h); cudaGetSymbolAddress((void**)&x1l, g_x1l);
    cudaGetSymbolAddress((void**)&vh, g_vh);
    cudaGetSymbolAddress((void**)&th, g_th);
    cudaGetSymbolAddress((void**)&qh, g_qh);
    cudaGetSymbolAddress((void**)&kh, g_kh);   cudaGetSymbolAddress((void**)&kl, g_kl);
    cudaGetSymbolAddress((void**)&Sh, g_Sh);
    cudaGetSymbolAddress((void**)&W1h, g_W1h); cudaGetSymbolAddress((void**)&W1l, g_W1l);
    cudaGetSymbolAddress((void**)&W2h, g_W2h); cudaGetSymbolAddress((void**)&W2l, g_W2l);
    cudaGetSymbolAddress((void**)&W3h, g_W3h); cudaGetSymbolAddress((void**)&W3l, g_W3l);
    cudaGetSymbolAddress((void**)&W4h, g_W4h); cudaGetSymbolAddress((void**)&W4l, g_W4l);
    cudaGetSymbolAddress((void**)&W5h, g_W5h); cudaGetSymbolAddress((void**)&W5l, g_W5l);

    cudaFuncSetAttribute(mma_gemm<EP_X1, false, 2, 1>,    cudaFuncAttributeMaxDynamicSharedMemorySize, SMEM_GEMM);
    cudaFuncSetAttribute(mma_gemm<EP_BNR, false, 1, 2>,   cudaFuncAttributeMaxDynamicSharedMemorySize, SMEM_GEMM);
    cudaFuncSetAttribute(mma_gemm<EP_QK, false, 3, 1>,    cudaFuncAttributeMaxDynamicSharedMemorySize, SMEM_GEMM);
    cudaFuncSetAttribute(mma_gemm<EP_S, true, 2, 1>,      cudaFuncAttributeMaxDynamicSharedMemorySize, SMEM_GEMM);
    cudaFuncSetAttribute(mma_gemm<EP_SUBDIV, true, 1, 2>, cudaFuncAttributeMaxDynamicSharedMemorySize, SMEM_GEMM);
    cudaFuncSetAttribute(mma_gemm<EP_FINAL, false, 1, 2>, cudaFuncAttributeMaxDynamicSharedMemorySize, SMEM_GEMM);

    const size_t sX  = (size_t)CH * NPTS;
    const size_t sQT = (size_t)NPTS * CQK;
    const size_t sK  = (size_t)CQK * NPTS;
    const size_t sS  = (size_t)NPTS * NPTS;

    // 0) merged hi/lo split of x and all weights (1 launch)
    const int splitTotal = NX + 2 * NW + 2 * NQW + NW;
    split_all<<<splitTotal / 256, 256>>>(x, xh, xl, W1, W1h, W1l, W2, W2h, W2l,
                                         W3, W3h, W3l, W4, W4h, W4l, W5, W5h, W5l);
    // 1) x1 = relu(bn1(W1 @ x))           [2-term: W1h·(xh+xl)]
    mma_gemm<EP_X1, false, 2, 1><<<dim3(16, 8, 8), 256, SMEM_GEMM>>>(
        W1h, W1l, 0, xh, xl, sX, CH, CH,
        x1, x1h, x1l, g1, b1, m1, v1, nullptr, nullptr, NP8);
    // 2) v = relu(bn2(W2 @ x1))           [1-term, BK=64]
    mma_gemm<EP_BNR, false, 1, 2><<<dim3(16, 8, 8), 256, SMEM_GEMM>>>(
        W2h, W2l, 0, x1h, x1l, sX, CH, CH,
        nullptr, vh, nullptr, g2, b2, m2, v2, nullptr, nullptr, NP8);
    // 3+4) fused q (y=0, hi-only transposed) + k (y=1, hi+lo)  [3-term]
    mma_gemm<EP_QK, false, 3, 1><<<dim3(16, 2, 8), 256, SMEM_GEMM>>>(
        W3h, W3l, 0, x1h, x1l, sX, CQK, CH,
        nullptr, qh, nullptr, g3, b3, m3, v3, nullptr, nullptr,
        W4h, W4l, kh, kl, g4, b4, m4, v4);
    // 5) scores S[n][m]                   [2-term: qh·(kh+kl)]
    mma_gemm<EP_S, true, 2, 1><<<dim3(16, 16, 8), 256, SMEM_GEMM>>>(
        qh, qh, sQT, kh, kl, sK, NPTS, CQK,
        S, nullptr, nullptr, nullptr, nullptr, nullptr, nullptr,
        nullptr, nullptr, NP8);
    // 6) row softmax -> fp16 hi only
    softmax_kernel<<<BATCH * NPTS, 256>>>(S, Sh);
    // 7) renorm divisor from Sh (consistent with GEMM operand)
    colsum_kernel<<<(BATCH * NPTS) / 256, 256>>>(Sh, rd);
    // 8) t = x1 - (v @ S) * rdiv[col]     [1-term vh·Sh, BK=64]
    mma_gemm<EP_SUBDIV, true, 1, 2><<<dim3(16, 8, 8), 256, SMEM_GEMM>>>(
        vh, vh, sX, Sh, Sh, sS, CH, NPTS,
        nullptr, th, nullptr, nullptr, nullptr, nullptr, nullptr, x1, rd, NP8);
    // 9) out = x1 + relu(bn5(W5 @ t))     [1-term W5h·th, BK=64]
    mma_gemm<EP_FINAL, false, 1, 2><<<dim3(16, 8, 8), 256, SMEM_GEMM>>>(
        W5h, W5l, 0, th, th, sX, CH, CH,
        out, nullptr, nullptr, g5, b5, m5, v5, x1, nullptr, NP8);
}

// round 17
// speedup vs baseline: 2.2325x; 1.0316x over previous
#include <cuda_runtime.h>
#include <cuda_fp16.h>
#include <cstdint>

#define EPS_BN 1e-5f
#define EPS_RENORM 1e-9f

#define BATCH 8
#define CH    1024
#define NPTS  2048
#define CQK   128

typedef __half fp16;

// ---------------- scratch (no allocations allowed) ----------------
__device__ float g_x1[BATCH * CH * NPTS];
__device__ float g_S [(size_t)BATCH * NPTS * NPTS];
__device__ float g_rd[BATCH * NPTS];
__device__ fp16 g_xh [BATCH * CH * NPTS], g_xl [BATCH * CH * NPTS];
__device__ fp16 g_x1h[BATCH * CH * NPTS], g_x1l[BATCH * CH * NPTS];
__device__ fp16 g_vh [BATCH * CH * NPTS];
__device__ fp16 g_th [BATCH * CH * NPTS];
__device__ fp16 g_qh [BATCH * NPTS * CQK];
__device__ fp16 g_kh [BATCH * CQK * NPTS], g_kl[BATCH * CQK * NPTS];
__device__ fp16 g_Sh [(size_t)BATCH * NPTS * NPTS];
__device__ fp16 g_W1h[CH * CH],  g_W1l[CH * CH];
__device__ fp16 g_W2h[CH * CH],  g_W2l[CH * CH];
__device__ fp16 g_W5h[CH * CH],  g_W5l[CH * CH];
__device__ fp16 g_W3h[CQK * CH], g_W3l[CQK * CH];
__device__ fp16 g_W4h[CQK * CH], g_W4l[CQK * CH];

// ---------------- PTX helpers ----------------
__device__ __forceinline__ uint32_t s2u(const void* p) {
    uint32_t a;
    asm("{ .reg .u64 t; cvta.to.shared.u64 t, %1; cvt.u32.u64 %0, t; }"
        : "=r"(a) : "l"(p));
    return a;
}
__device__ __forceinline__ void cp16(uint32_t saddr, const void* g) {
    asm volatile("cp.async.cg.shared.global [%0], [%1], 16;"
                 :: "r"(saddr), "l"(g) : "memory");
}
#define CP_COMMIT() asm volatile("cp.async.commit_group;" ::: "memory")
#define CP_WAIT(n)  asm volatile("cp.async.wait_group %0;" :: "n"(n) : "memory")

__device__ __forceinline__ void ldsm4(uint32_t* r, uint32_t a) {
    asm volatile("ldmatrix.sync.aligned.m8n8.x4.shared.b16 {%0,%1,%2,%3}, [%4];"
                 : "=r"(r[0]), "=r"(r[1]), "=r"(r[2]), "=r"(r[3]) : "r"(a));
}
__device__ __forceinline__ void ldsm4t(uint32_t* r, uint32_t a) {
    asm volatile("ldmatrix.sync.aligned.m8n8.x4.trans.shared.b16 {%0,%1,%2,%3}, [%4];"
                 : "=r"(r[0]), "=r"(r[1]), "=r"(r[2]), "=r"(r[3]) : "r"(a));
}
__device__ __forceinline__ void mma16816(float* d, const uint32_t* a, const uint32_t* b) {
    asm volatile("mma.sync.aligned.m16n8k16.row.col.f32.f16.f16.f32 "
                 "{%0,%1,%2,%3}, {%4,%5,%6,%7}, {%8,%9}, {%0,%1,%2,%3};"
                 : "+f"(d[0]), "+f"(d[1]), "+f"(d[2]), "+f"(d[3])
                 : "r"(a[0]), "r"(a[1]), "r"(a[2]), "r"(a[3]), "r"(b[0]), "r"(b[1]));
}

// ---------------- split-fp16 MMA GEMM ----------------
// C[b] (M x N) = (Ah+Al)[b] @ (Bh+Bl)[b]
// NTERM 3: Ah·Bh + Ah·Bl + Al·Bh ; 2: Ah·Bh + Ah·Bl ; 1: Ah·Bh
// KPS: k32-tiles per pipeline stage (2 only allowed for NTERM==1).
// Stage sizes: NTERM==2 -> 24KB, 4 stages (depth-3 prefetch);
//              else 32KB, 3 stages (depth-2). Both = 96 KiB -> 2 CTAs/SM.
// A row-major [M][K], B row-major [K][N], N == NPTS.
// CTA 128x128, 8 warps (warp tile 32x64).
// EP_QK: fused q/k — blockIdx.y==0 -> q (A=W3, transposed coalesced store),
//        blockIdx.y==1 -> k (A=A2=W4, hi+lo store into C2).
#define SMEM_GEMM 98304

enum { EP_X1 = 0, EP_BNR = 1, EP_S = 3, EP_SUBDIV = 4, EP_FINAL = 5, EP_QK = 6 };

template<int EPI, bool ABATCH, int NTERM, int KPS>
__global__ void __launch_bounds__(256, 2)
mma_gemm(const fp16* __restrict__ Ahp, const fp16* __restrict__ Alp, size_t sA,
         const fp16* __restrict__ Bhp, const fp16* __restrict__ Blp, size_t sB,
         int M, int K,
         float* __restrict__ C32, fp16* __restrict__ Ch, fp16* __restrict__ Cl,
         const float* __restrict__ gg, const float* __restrict__ bb,
         const float* __restrict__ mm, const float* __restrict__ vv,
         const float* __restrict__ add, const float* __restrict__ rdiv,
         const fp16* __restrict__ A2h, const fp16* __restrict__ A2l,
         fp16* __restrict__ C2h, fp16* __restrict__ C2l,
         const float* __restrict__ gg2, const float* __restrict__ bb2,
         const float* __restrict__ mm2, const float* __restrict__ vv2)
{
    static_assert(KPS == 1 || NTERM == 1, "KPS=2 requires 1-term");
    constexpr int NSTGc = (NTERM == 2) ? 4 : 3;
    constexpr int STGc  = (NTERM == 2) ? 24576 : 32768;
    constexpr int DEPTH = NSTGc - 1;
    constexpr int BOFFc = (NTERM == 2) ? 8192 : 16384;

    extern __shared__ __align__(256) char smraw[];
    const uint32_t smb = s2u(smraw);
    const int tid  = threadIdx.x;
    const int lane = tid & 31;
    const int wid  = tid >> 5;
    const int m_w  = (wid & 3) * 32;     // warp M offset
    const int n_w  = (wid >> 2) * 64;    // warp N offset
    const int bz   = blockIdx.z;
    const int rowStart = blockIdx.y * 128;
    const int colStart = blockIdx.x * 128;
    const int N = NPTS;
    const bool isK2 = (EPI == EP_QK) && (blockIdx.y != 0);
    const int rowA = (EPI == EP_QK) ? 0 : rowStart;   // per-matrix local rows

    const fp16* Asel_h = isK2 ? A2h : Ahp;
    const fp16* Ah_ = Asel_h + (ABATCH ? (size_t)bz * sA : 0);
    const fp16* Al_ = Alp + (ABATCH ? (size_t)bz * sA : 0);   // only NTERM==3
    const fp16* Bh_ = Bhp + (size_t)bz * sB;
    const fp16* Bl_ = Blp + (size_t)bz * sB;

    float acc[2][8][4];
#pragma unroll
    for (int i = 0; i < 2; i++)
#pragma unroll
        for (int j = 0; j < 8; j++)
#pragma unroll
            for (int r = 0; r < 4; r++) acc[i][j][r] = 0.f;

    auto loadStage = [&](int t) {
        const int s = t % NSTGc;
        const uint32_t base = smb + (uint32_t)s * STGc;
        const int k0 = t * 32 * KPS;
#pragma unroll
        for (int sub = 0; sub < KPS; sub++) {
#pragma unroll
            for (int i = 0; i < 2; i++) {        // A: 128 rows x 4 chunks (16B)
                int idx = tid + i * 256;
                int row = idx >> 2, c = idx & 3;
                uint32_t off = (uint32_t)(row * 64 + ((c ^ ((row >> 1) & 3)) << 4));
                size_t go = (size_t)(rowA + row) * K + k0 + sub * 32 + c * 8;
                cp16(base + (uint32_t)sub * 8192 + off, Ah_ + go);
                if (NTERM >= 3) cp16(base + 8192 + off, Al_ + go);
            }
#pragma unroll
            for (int i = 0; i < 2; i++) {        // B: 32 rows x 16 chunks
                int idx = tid + i * 256;
                int k = idx >> 4, cn = idx & 15;
                uint32_t off = (uint32_t)(k * 256 + ((cn ^ (k & 7)) << 4));
                size_t go = (size_t)(k0 + sub * 32 + k) * N + colStart + cn * 8;
                cp16(base + BOFFc + (uint32_t)sub * 8192 + off, Bh_ + go);
                if (NTERM >= 2) cp16(base + BOFFc + 8192 + off, Bl_ + go);
            }
        }
        CP_COMMIT();
    };

    const int T = K / (32 * KPS);
    const int P = (T < DEPTH) ? T : DEPTH;
    for (int t = 0; t < P; t++) loadStage(t);

    for (int t = 0; t < T; t++) {
        const int rem = T - t;
        if (DEPTH == 3 && rem >= 3)      { CP_WAIT(2); }
        else if (rem >= 2)               { CP_WAIT(1); }
        else                             { CP_WAIT(0); }
        __syncthreads();
        // this barrier also protects the stage loadStage(t+DEPTH) overwrites
        // (== stage (t-1) % NSTGc, whose readers all passed the barrier).
        if (t + DEPTH < T) loadStage(t + DEPTH);

        const uint32_t Ab = smb + (uint32_t)(t % NSTGc) * STGc;
#pragma unroll
        for (int kk = 0; kk < 2 * KPS; kk++) {
            const int sub = kk >> 1;
            const int ks  = kk & 1;
            const uint32_t Asub = Ab + (uint32_t)sub * 8192;
            const uint32_t Bsub = Ab + BOFFc + (uint32_t)sub * 8192;
            uint32_t ah[2][4], al[2][4];
#pragma unroll
            for (int i = 0; i < 2; i++) {
                int row = m_w + i * 16 + (lane & 15);
                int c = ks * 2 + (lane >> 4);
                uint32_t off = (uint32_t)(row * 64 + ((c ^ ((row >> 1) & 3)) << 4));
                ldsm4(ah[i], Asub + off);
                if (NTERM >= 3) ldsm4(al[i], Asub + 8192 + off);
            }
#pragma unroll
            for (int p = 0; p < 4; p++) {
                int g = lane >> 3, j8 = lane & 7;
                int k = ks * 16 + (g & 1) * 8 + j8;
                int cn = (n_w >> 3) + p * 2 + (g >> 1);
                uint32_t off = (uint32_t)(k * 256 + ((cn ^ (k & 7)) << 4));
                uint32_t bh[4], bl[4];
                ldsm4t(bh, Bsub + off);
                if (NTERM >= 2) ldsm4t(bl, Bsub + 8192 + off);
                // term-major order: independent MMA groups
#pragma unroll
                for (int i = 0; i < 2; i++) {
                    mma16816(acc[i][2 * p],     ah[i], bh);
                    mma16816(acc[i][2 * p + 1], ah[i], bh + 2);
                }
                if (NTERM >= 2) {
#pragma unroll
                    for (int i = 0; i < 2; i++) {
                        mma16816(acc[i][2 * p],     ah[i], bl);
                        mma16816(acc[i][2 * p + 1], ah[i], bl + 2);
                    }
                }
                if (NTERM >= 3) {
#pragma unroll
                    for (int i = 0; i < 2; i++) {
                        mma16816(acc[i][2 * p],     al[i], bh);
                        mma16816(acc[i][2 * p + 1], al[i], bh + 2);
                    }
                }
            }
        }
    }

    // ---------------- epilogue ----------------
    __shared__ float s_scl[128], s_off[128];
    if (EPI == EP_X1 || EPI == EP_BNR || EPI == EP_QK || EPI == EP_FINAL) {
        __syncthreads();              // all warps out of mainloop smem
        if (tid < 128) {
            const float* G = (EPI == EP_QK && isK2) ? gg2 : gg;
            const float* B = (EPI == EP_QK && isK2) ? bb2 : bb;
            const float* Mn = (EPI == EP_QK && isK2) ? mm2 : mm;
            const float* V = (EPI == EP_QK && isK2) ? vv2 : vv;
            int rg = rowA + tid;   // local channel for EP_QK, global row else
            float inv = rsqrtf(V[rg] + EPS_BN);
            float sc = G[rg] * inv;
            s_scl[tid] = sc;
            s_off[tid] = B[rg] - Mn[rg] * sc;
        }
        __syncthreads();
    }

    if (EPI == EP_QK) {
        if (!isK2) {
            // q: stage BN+ReLU'd values transposed into padded smem, then
            // copy out fully coalesced (hi only — scores never reads q-lo).
            fp16* sq = reinterpret_cast<fp16*>(smraw);             // [128][136]
#pragma unroll
            for (int i = 0; i < 2; i++)
#pragma unroll
                for (int j = 0; j < 8; j++)
#pragma unroll
                    for (int hseg = 0; hseg < 2; hseg++) {
                        const int rl = m_w + i * 16 + (lane >> 2) + hseg * 8; // channel
                        const int cl = n_w + j * 8 + (lane & 3) * 2;          // point
                        const float sc = s_scl[rl], of = s_off[rl];
                        float z0 = fmaxf(acc[i][j][hseg * 2]     * sc + of, 0.f);
                        float z1 = fmaxf(acc[i][j][hseg * 2 + 1] * sc + of, 0.f);
                        sq[(cl + 0) * 136 + rl] = __float2half_rn(z0);
                        sq[(cl + 1) * 136 + rl] = __float2half_rn(z1);
                    }
            __syncthreads();
            const size_t baseq = (size_t)bz * ((size_t)NPTS * CQK)
                               + (size_t)colStart * CQK;
#pragma unroll
            for (int kx = 0; kx < 8; kx++) {
                int idx = tid + kx * 256;
                int pt = idx >> 4, c8 = idx & 15;
                uint4 v4 = *reinterpret_cast<const uint4*>(sq + pt * 136 + c8 * 8);
                *reinterpret_cast<uint4*>(Ch + baseq + (size_t)pt * CQK + c8 * 8) = v4;
            }
        } else {
            // k: [channel][point] half2 stores, hi + lo (scores reads both)
#pragma unroll
            for (int i = 0; i < 2; i++)
#pragma unroll
                for (int j = 0; j < 8; j++)
#pragma unroll
                    for (int hseg = 0; hseg < 2; hseg++) {
                        const int rl = m_w + i * 16 + (lane >> 2) + hseg * 8;
                        const int cl = n_w + j * 8 + (lane & 3) * 2;
                        const float sc = s_scl[rl], of = s_off[rl];
                        float z0 = fmaxf(acc[i][j][hseg * 2]     * sc + of, 0.f);
                        float z1 = fmaxf(acc[i][j][hseg * 2 + 1] * sc + of, 0.f);
                        fp16 h0 = __float2half_rn(z0), h1 = __float2half_rn(z1);
                        size_t ok = (size_t)bz * ((size_t)CQK * NPTS)
                                  + (size_t)rl * N + colStart + cl;
                        *(__half2*)(C2h + ok) = __halves2half2(h0, h1);
                        *(__half2*)(C2l + ok) = __halves2half2(
                            __float2half_rn(z0 - __half2float(h0)),
                            __float2half_rn(z1 - __half2float(h1)));
                    }
        }
        return;
    }

    const bool wantLo = (Cl != nullptr);
    const size_t sC = (size_t)M * N;
#pragma unroll
    for (int i = 0; i < 2; i++) {
#pragma unroll
        for (int j = 0; j < 8; j++) {
#pragma unroll
            for (int hseg = 0; hseg < 2; hseg++) {
                const int rl = m_w + i * 16 + (lane >> 2) + hseg * 8;
                const int cl = n_w + j * 8 + (lane & 3) * 2;
                const float y0 = acc[i][j][hseg * 2];
                const float y1 = acc[i][j][hseg * 2 + 1];
                const int rg = rowStart + rl;
                const int cg = colStart + cl;
                const size_t o = (size_t)bz * sC + (size_t)rg * N + cg;

                if (EPI == EP_S) {
                    float2 v2; v2.x = y0; v2.y = y1;
                    *(float2*)(C32 + o) = v2;
                } else if (EPI == EP_SUBDIV) {
                    float2 ad  = *(const float2*)(add + o);
                    float2 rdv = *(const float2*)(rdiv + (size_t)bz * N + cg);
                    float z0 = ad.x - y0 * rdv.x;
                    float z1 = ad.y - y1 * rdv.y;
                    fp16 h0 = __float2half_rn(z0), h1 = __float2half_rn(z1);
                    *(__half2*)(Ch + o) = __halves2half2(h0, h1);
                    if (wantLo)
                        *(__half2*)(Cl + o) = __halves2half2(
                            __float2half_rn(z0 - __half2float(h0)),
                            __float2half_rn(z1 - __half2float(h1)));
                } else {
                    const float sc = s_scl[rl], of = s_off[rl];
                    float z0 = fmaxf(y0 * sc + of, 0.f);
                    float z1 = fmaxf(y1 * sc + of, 0.f);
                    if (EPI == EP_FINAL) {
                        float2 ad = *(const float2*)(add + o);
                        float2 v2; v2.x = ad.x + z0; v2.y = ad.y + z1;
                        *(float2*)(C32 + o) = v2;
                    } else {
                        if (EPI == EP_X1) {
                            float2 v2; v2.x = z0; v2.y = z1;
                            *(float2*)(C32 + o) = v2;
                        }
                        fp16 h0 = __float2half_rn(z0), h1 = __float2half_rn(z1);
                        *(__half2*)(Ch + o) = __halves2half2(h0, h1);
                        if (wantLo)
                            *(__half2*)(Cl + o) = __halves2half2(
                                __float2half_rn(z0 - __half2float(h0)),
                                __float2half_rn(z1 - __half2float(h1)));
                    }
                }
            }
        }
    }
}

// ---------------- merged fp32 -> fp16 hi/lo split of all inputs ----------------
#define NX (BATCH * CH * NPTS)
#define NW (CH * CH)
#define NQW (CQK * CH)

__global__ void __launch_bounds__(256)
split_all(const float* __restrict__ x,  fp16* __restrict__ xh,  fp16* __restrict__ xl,
          const float* __restrict__ W1, fp16* __restrict__ W1h, fp16* __restrict__ W1l,
          const float* __restrict__ W2, fp16* __restrict__ W2h, fp16* __restrict__ W2l,
          const float* __restrict__ W3, fp16* __restrict__ W3h, fp16* __restrict__ W3l,
          const float* __restrict__ W4, fp16* __restrict__ W4h, fp16* __restrict__ W4l,
          const float* __restrict__ W5, fp16* __restrict__ W5h, fp16* __restrict__ W5l)
{
    size_t i = (size_t)blockIdx.x * 256 + threadIdx.x;
    const float* in; fp16 *oh, *ol; size_t li;
    if (i < NX)                       { in = x;  oh = xh;  ol = xl;  li = i; }
    else if (i < NX + NW)             { in = W1; oh = W1h; ol = W1l; li = i - NX; }
    else if (i < NX + 2 * NW)         { in = W2; oh = W2h; ol = W2l; li = i - NX - NW; }
    else if (i < NX + 2 * NW + NQW)   { in = W3; oh = W3h; ol = W3l; li = i - NX - 2 * NW; }
    else if (i < NX + 2 * NW + 2*NQW) { in = W4; oh = W4h; ol = W4l; li = i - NX - 2 * NW - NQW; }
    else                              { in = W5; oh = W5h; ol = W5l; li = i - NX - 2 * NW - 2 * NQW; }
    float v = in[li];
    fp16 h = __float2half_rn(v);
    oh[li] = h;
    ol[li] = __float2half_rn(v - __half2float(h));
}

// ---------------- row softmax: fp32 in, fp16 (hi only) out ----------------
__global__ void __launch_bounds__(256)
softmax_kernel(const float* __restrict__ S, fp16* __restrict__ Sh)
{
    __shared__ float buf[NPTS];
    __shared__ float red[8];
    const float* p = S + (size_t)blockIdx.x * NPTS;
    fp16* ph = Sh + (size_t)blockIdx.x * NPTS;
    int t = threadIdx.x;

    float mx = -3.402823466e38f;
    for (int i = t; i < NPTS; i += 256) { float v = p[i]; buf[i] = v; mx = fmaxf(mx, v); }
#pragma unroll
    for (int o = 16; o > 0; o >>= 1) mx = fmaxf(mx, __shfl_xor_sync(0xffffffffu, mx, o));
    if ((t & 31) == 0) red[t >> 5] = mx;
    __syncthreads();
    float bm = red[0];
#pragma unroll
    for (int i = 1; i < 8; i++) bm = fmaxf(bm, red[i]);
    __syncthreads();

    float sum = 0.f;
    for (int i = t; i < NPTS; i += 256) { float e = __expf(buf[i] - bm); buf[i] = e; sum += e; }
#pragma unroll
    for (int o = 16; o > 0; o >>= 1) sum += __shfl_xor_sync(0xffffffffu, sum, o);
    if ((t & 31) == 0) red[t >> 5] = sum;
    __syncthreads();
    float bs = 0.f;
#pragma unroll
    for (int i = 0; i < 8; i++) bs += red[i];
    float inv = 1.0f / bs;
    for (int i = t; i < NPTS; i += 256)
        ph[i] = __float2half_rn(buf[i] * inv);
}

// ---------------- column sums of Sh -> 1/(eps+colsum) ----------------
__global__ void __launch_bounds__(256)
colsum_kernel(const fp16* __restrict__ Sh, float* __restrict__ rdiv)
{
    int idx = blockIdx.x * 256 + threadIdx.x;
    int b = idx / NPTS, m = idx - b * NPTS;
    const fp16* ph = Sh + (size_t)b * NPTS * NPTS + m;
    float s[4] = {0.f, 0.f, 0.f, 0.f};
    for (int n = 0; n < NPTS; n += 4) {
#pragma unroll
        for (int u = 0; u < 4; u++)
            s[u] += __half2float(ph[(size_t)(n + u) * NPTS]);
    }
    rdiv[idx] = 1.0f / (EPS_RENORM + ((s[0] + s[1]) + (s[2] + s[3])));
}

// ---------------- launch ----------------
#define NP8 nullptr, nullptr, nullptr, nullptr, nullptr, nullptr, nullptr, nullptr

extern "C" void kernel_launch(void* const* d_in, const int* in_sizes, int n_in,
                              void* d_out, int out_size)
{
    (void)in_sizes; (void)n_in; (void)out_size;
    const float* x  = (const float*)d_in[0];
    const float *W1 = (const float*)d_in[1],  *g1 = (const float*)d_in[2],
                *b1 = (const float*)d_in[3],  *m1 = (const float*)d_in[4],
                *v1 = (const float*)d_in[5];
    const float *W2 = (const float*)d_in[6],  *g2 = (const float*)d_in[7],
                *b2 = (const float*)d_in[8],  *m2 = (const float*)d_in[9],
                *v2 = (const float*)d_in[10];
    const float *W3 = (const float*)d_in[11], *g3 = (const float*)d_in[12],
                *b3 = (const float*)d_in[13], *m3 = (const float*)d_in[14],
                *v3 = (const float*)d_in[15];
    const float *W4 = (const float*)d_in[16], *g4 = (const float*)d_in[17],
                *b4 = (const float*)d_in[18], *m4 = (const float*)d_in[19],
                *v4 = (const float*)d_in[20];
    const float *W5 = (const float*)d_in[21], *g5 = (const float*)d_in[22],
                *b5 = (const float*)d_in[23], *m5 = (const float*)d_in[24],
                *v5 = (const float*)d_in[25];
    float* out = (float*)d_out;

    float *x1, *S, *rd;
    fp16 *xh, *xl, *x1h, *x1l, *vh, *th, *qh, *kh, *kl, *Sh;
    fp16 *W1h, *W1l, *W2h, *W2l, *W3h, *W3l, *W4h, *W4l, *W5h, *W5l;
    cudaGetSymbolAddress((void**)&x1, g_x1);
    cudaGetSymbolAddress((void**)&S,  g_S);
    cudaGetSymbolAddress((void**)&rd, g_rd);
    cudaGetSymbolAddress((void**)&xh, g_xh);   cudaGetSymbolAddress((void**)&xl, g_xl);
    cudaGetSymbolAddress((void**)&x1h, g_x1h); cudaGetSymbolAddress((void**)&x1l, g_x1l);
    cudaGetSymbolAddress((void**)&vh, g_vh);
    cudaGetSymbolAddress((void**)&th, g_th);
    cudaGetSymbolAddress((void**)&qh, g_qh);
    cudaGetSymbolAddress((void**)&kh, g_kh);   cudaGetSymbolAddress((void**)&kl, g_kl);
    cudaGetSymbolAddress((void**)&Sh, g_Sh);
    cudaGetSymbolAddress((void**)&W1h, g_W1h); cudaGetSymbolAddress((void**)&W1l, g_W1l);
    cudaGetSymbolAddress((void**)&W2h, g_W2h); cudaGetSymbolAddress((void**)&W2l, g_W2l);
    cudaGetSymbolAddress((void**)&W3h, g_W3h); cudaGetSymbolAddress((void**)&W3l, g_W3l);
    cudaGetSymbolAddress((void**)&W4h, g_W4h); cudaGetSymbolAddress((void**)&W4l, g_W4l);
    cudaGetSymbolAddress((void**)&W5h, g_W5h); cudaGetSymbolAddress((void**)&W5l, g_W5l);

    cudaFuncSetAttribute(mma_gemm<EP_X1, false, 2, 1>,    cudaFuncAttributeMaxDynamicSharedMemorySize, SMEM_GEMM);
    cudaFuncSetAttribute(mma_gemm<EP_BNR, false, 1, 2>,   cudaFuncAttributeMaxDynamicSharedMemorySize, SMEM_GEMM);
    cudaFuncSetAttribute(mma_gemm<EP_QK, false, 2, 1>,    cudaFuncAttributeMaxDynamicSharedMemorySize, SMEM_GEMM);
    cudaFuncSetAttribute(mma_gemm<EP_S, true, 2, 1>,      cudaFuncAttributeMaxDynamicSharedMemorySize, SMEM_GEMM);
    cudaFuncSetAttribute(mma_gemm<EP_SUBDIV, true, 1, 2>, cudaFuncAttributeMaxDynamicSharedMemorySize, SMEM_GEMM);
    cudaFuncSetAttribute(mma_gemm<EP_FINAL, false, 1, 2>, cudaFuncAttributeMaxDynamicSharedMemorySize, SMEM_GEMM);

    const size_t sX  = (size_t)CH * NPTS;
    const size_t sQT = (size_t)NPTS * CQK;
    const size_t sK  = (size_t)CQK * NPTS;
    const size_t sS  = (size_t)NPTS * NPTS;

    // 0) merged hi/lo split of x and all weights (1 launch)
    const int splitTotal = NX + 2 * NW + 2 * NQW + NW;
    split_all<<<splitTotal / 256, 256>>>(x, xh, xl, W1, W1h, W1l, W2, W2h, W2l,
                                         W3, W3h, W3l, W4, W4h, W4l, W5, W5h, W5l);
    // 1) x1 = relu(bn1(W1 @ x))           [2-term: W1h·(xh+xl), 4-stage]
    mma_gemm<EP_X1, false, 2, 1><<<dim3(16, 8, 8), 256, SMEM_GEMM>>>(
        W1h, W1l, 0, xh, xl, sX, CH, CH,
        x1, x1h, x1l, g1, b1, m1, v1, nullptr, nullptr, NP8);
    // 2) v = relu(bn2(W2 @ x1))           [1-term, BK=64]
    mma_gemm<EP_BNR, false, 1, 2><<<dim3(16, 8, 8), 256, SMEM_GEMM>>>(
        W2h, W2l, 0, x1h, x1l, sX, CH, CH,
        nullptr, vh, nullptr, g2, b2, m2, v2, nullptr, nullptr, NP8);
    // 3+4) fused q (y=0) + k (y=1)        [2-term: Wh·(x1h+x1l), 4-stage]
    mma_gemm<EP_QK, false, 2, 1><<<dim3(16, 2, 8), 256, SMEM_GEMM>>>(
        W3h, W3l, 0, x1h, x1l, sX, CQK, CH,
        nullptr, qh, nullptr, g3, b3, m3, v3, nullptr, nullptr,
        W4h, W4l, kh, kl, g4, b4, m4, v4);
    // 5) scores S[n][m]                   [2-term: qh·(kh+kl), 4-stage]
    mma_gemm<EP_S, true, 2, 1><<<dim3(16, 16, 8), 256, SMEM_GEMM>>>(
        qh, qh, sQT, kh, kl, sK, NPTS, CQK,
        S, nullptr, nullptr, nullptr, nullptr, nullptr, nullptr,
        nullptr, nullptr, NP8);
    // 6) row softmax -> fp16 hi only
    softmax_kernel<<<BATCH * NPTS, 256>>>(S, Sh);
    // 7) renorm divisor from Sh (consistent with GEMM operand)
    colsum_kernel<<<(BATCH * NPTS) / 256, 256>>>(Sh, rd);
    // 8) t = x1 - (v @ S) * rdiv[col]     [1-term vh·Sh, BK=64]
    mma_gemm<EP_SUBDIV, true, 1, 2><<<dim3(16, 8, 8), 256, SMEM_GEMM>>>(
        vh, vh, sX, Sh, Sh, sS, CH, NPTS,
        nullptr, th, nullptr, nullptr, nullptr, nullptr, nullptr, x1, rd, NP8);
    // 9) out = x1 + relu(bn5(W5 @ t))     [1-term W5h·th, BK=64]
    mma_gemm<EP_FINAL, false, 1, 2><<<dim3(16, 8, 8), 256, SMEM_GEMM>>>(
        W5h, W5l, 0, th, th, sX, CH, CH,
        out, nullptr, nullptr, g5, b5, m5, v5, x1, nullptr, NP8);
}